// round 1
// baseline (speedup 1.0000x reference)
#include <cuda_runtime.h>
#include <math.h>

#define BATCH 32
#define T 4096
#define H 128
#define NS 128
#define DEPTH 2
#define TT (BATCH*T)
#define T2 2048
#define DOUT 64
#define FULL 0xFFFFFFFFu

// ---------------- scratch (device globals; no allocs allowed) ----------------
__device__ float g_x  [TT*H];        // running activation [B*T][H]   (64MB)
__device__ float g_xn [TT*H];        // LN1 output (needed for D-skip) (64MB)
__device__ float g_bur[BATCH*NS*T];  // Bu / xs real, layout [B][N][T] (64MB)
__device__ float g_bui[BATCH*NS*T];  // Bu / xs imag                   (64MB)
__device__ float g_y1 [BATCH*H*T2];  // conv1 output [B][C][2048]      (32MB)
__device__ float g_lbr[DEPTH*NS], g_lbi[DEPTH*NS];          // lambda_bar
__device__ float g_bbr[DEPTH*NS*H], g_bbi[DEPTH*NS*H];      // B_bar

// ---------------- param prep: lambda_bar, B_bar ----------------
__global__ void k_prep(const float* __restrict__ lre, const float* __restrict__ lim,
                       const float* __restrict__ Bre, const float* __restrict__ Bim,
                       const float* __restrict__ lstep)
{
    int idx = blockIdx.x;               // l*NS + n
    float lr = lre[idx], li = lim[idx];
    float dt = expf(lstep[idx]);
    float er = expf(lr*dt);
    float lbr = er * cosf(li*dt);
    float lbi = er * sinf(li*dt);
    if (threadIdx.x == 0){ g_lbr[idx]=lbr; g_lbi[idx]=lbi; }
    float den = lr*lr + li*li;
    float nr = lbr - 1.0f, ni = lbi;
    float fr = (nr*lr + ni*li)/den;
    float fi = (ni*lr - nr*li)/den;
    int h = threadIdx.x;
    float br = Bre[idx*H + h], bi = Bim[idx*H + h];
    g_bbr[idx*H + h] = fr*br - fi*bi;
    g_bbi[idx*H + h] = fr*bi + fi*br;
}

// ---------------- LN1 + Bu = xn @ B_bar^T (complex), write Bu transposed [B][N][T] ----
__global__ void k_ln_bu(const float* __restrict__ xin,
                        const float* __restrict__ g1, const float* __restrict__ b1v, int l)
{
    __shared__ float s_xn[16][128];
    __shared__ float s_br[32][129];
    __shared__ float s_bi[32][129];
    __shared__ float s_or[32][17];
    __shared__ float s_oi[32][17];

    const float* src = xin ? xin : g_x;
    int tid = threadIdx.x;
    int lane = tid & 31, warp = tid >> 5;
    int row0 = blockIdx.x * 16;

    // ---- LayerNorm: warp per row, 4 rows per warp ----
    for (int rr = 0; rr < 4; rr++){
        int r = warp*4 + rr;
        int base = (row0 + r) * H;
        float v0 = src[base + lane];
        float v1 = src[base + lane + 32];
        float v2 = src[base + lane + 64];
        float v3 = src[base + lane + 96];
        float s  = v0+v1+v2+v3;
        float sq = v0*v0+v1*v1+v2*v2+v3*v3;
        #pragma unroll
        for (int o=16;o>0;o>>=1){ s += __shfl_xor_sync(FULL,s,o); sq += __shfl_xor_sync(FULL,sq,o); }
        float mu = s * (1.0f/128.0f);
        float var = sq * (1.0f/128.0f) - mu*mu;
        float rstd = rsqrtf(var + 1e-5f);
        float vv[4] = {v0,v1,v2,v3};
        #pragma unroll
        for (int q=0;q<4;q++){
            int h = lane + 32*q;
            float xn = (vv[q] - mu)*rstd * g1[l*H+h] + b1v[l*H+h];
            s_xn[r][h] = xn;
            g_xn[base + h] = xn;
        }
    }
    __syncthreads();

    int b  = row0 >> 12;         // row0 / T
    int t0 = row0 & (T-1);
    int r4 = warp;               // 0..3
    int nn = tid & 31;

    for (int cb = 0; cb < 128; cb += 32){
        for (int e = tid; e < 32*128; e += 128){
            int np = e >> 7, h = e & 127;
            s_br[np][h] = g_bbr[(l*NS + cb + np)*H + h];
            s_bi[np][h] = g_bbi[(l*NS + cb + np)*H + h];
        }
        __syncthreads();
        float ar[4] = {0,0,0,0}, ai[4] = {0,0,0,0};
        for (int h = 0; h < 128; h++){
            float br = s_br[nn][h], bi = s_bi[nn][h];
            #pragma unroll
            for (int j=0;j<4;j++){
                float u = s_xn[r4*4+j][h];
                ar[j] += u*br; ai[j] += u*bi;
            }
        }
        #pragma unroll
        for (int j=0;j<4;j++){ s_or[nn][r4*4+j]=ar[j]; s_oi[nn][r4*4+j]=ai[j]; }
        __syncthreads();
        for (int e = tid; e < 512; e += 128){
            int np = e >> 4, jj = e & 15;
            int gi = (b*NS + cb + np)*T + t0 + jj;
            g_bur[gi] = s_or[np][jj];
            g_bui[gi] = s_oi[np][jj];
        }
        __syncthreads();
    }
}

// ---------------- in-place scan over T: x_t = lam_bar * x_{t-1} + Bu_t ----------------
__global__ void k_scan(int l)
{
    __shared__ float s_wr[8], s_wi[8], s_er[8], s_ei[8];
    int bid = blockIdx.x;        // b*NS + n
    int n = bid & (NS-1);
    int tid = threadIdx.x, lane = tid & 31, warp = tid >> 5;
    int base = bid * T + tid * 16;
    float lr = g_lbr[l*NS+n], li = g_lbi[l*NS+n];

    float vr[16], vi[16];
    float4* pr = (float4*)(g_bur + base);
    float4* pi = (float4*)(g_bui + base);
    #pragma unroll
    for (int q=0;q<4;q++){
        float4 a = pr[q]; vr[4*q]=a.x; vr[4*q+1]=a.y; vr[4*q+2]=a.z; vr[4*q+3]=a.w;
        float4 c = pi[q]; vi[4*q]=c.x; vi[4*q+1]=c.y; vi[4*q+2]=c.z; vi[4*q+3]=c.w;
    }

    // segment result from zero state
    float sr=0.f, si=0.f;
    #pragma unroll
    for (int i=0;i<16;i++){
        float tr = lr*sr - li*si + vr[i];
        float ti = lr*si + li*sr + vi[i];
        sr=tr; si=ti;
    }

    // powers: c = lam^16; cd[k] = c^(2^k), k=0..5
    float cdr[6], cdi[6];
    {
        float pr_=lr, pi_=li;
        #pragma unroll
        for (int q=0;q<4;q++){ float tr = pr_*pr_ - pi_*pi_; pi_ = 2.f*pr_*pi_; pr_ = tr; }
        cdr[0]=pr_; cdi[0]=pi_;
        #pragma unroll
        for (int q=1;q<6;q++){ float tr = cdr[q-1]*cdr[q-1]-cdi[q-1]*cdi[q-1];
                               cdi[q]=2.f*cdr[q-1]*cdi[q-1]; cdr[q]=tr; }
    }

    // warp Kogge-Stone on (geometric-weight) linear recurrence
    float xr=sr, xi=si;
    #pragma unroll
    for (int st=0; st<5; st++){
        int d = 1<<st;
        float or_ = __shfl_up_sync(FULL, xr, d);
        float oi_ = __shfl_up_sync(FULL, xi, d);
        if (lane >= d){
            float tr = cdr[st]*or_ - cdi[st]*oi_ + xr;
            xi = cdr[st]*oi_ + cdi[st]*or_ + xi;
            xr = tr;
        }
    }
    if (lane==31){ s_wr[warp]=xr; s_wi[warp]=xi; }
    __syncthreads();
    if (tid==0){
        float er=0.f, ei=0.f;
        #pragma unroll
        for (int w=0;w<8;w++){
            s_er[w]=er; s_ei[w]=ei;
            float tr = cdr[5]*er - cdi[5]*ei + s_wr[w];
            ei = cdr[5]*ei + cdi[5]*er + s_wi[w];
            er = tr;
        }
    }
    __syncthreads();
    float Er = s_er[warp], Ei = s_ei[warp];
    // c^lane
    float plr=1.f, pli=0.f;
    #pragma unroll
    for (int bt=0; bt<5; bt++){
        if (lane & (1<<bt)){
            float tr = plr*cdr[bt] - pli*cdi[bt];
            pli = plr*cdi[bt] + pli*cdr[bt];
            plr = tr;
        }
    }
    float car = plr*Er - pli*Ei;
    float cai = plr*Ei + pli*Er;
    float pvr = __shfl_up_sync(FULL, xr, 1);
    float pvi = __shfl_up_sync(FULL, xi, 1);
    if (lane > 0){ car += pvr; cai += pvi; }

    // replay with carry, store in-place
    sr = car; si = cai;
    #pragma unroll
    for (int i=0;i<16;i++){
        float tr = lr*sr - li*si + vr[i];
        float ti = lr*si + li*sr + vi[i];
        sr=tr; si=ti;
        vr[i]=sr; vi[i]=si;
    }
    #pragma unroll
    for (int q=0;q<4;q++){
        pr[q] = make_float4(vr[4*q],vr[4*q+1],vr[4*q+2],vr[4*q+3]);
        pi[q] = make_float4(vi[4*q],vi[4*q+1],vi[4*q+2],vi[4*q+3]);
    }
}

// ---------------- y = res + 2*Re(xs @ C^T) + xn*D_skip ----------------
__global__ void k_cmix(const float* __restrict__ xin,
                       const float* __restrict__ Cre, const float* __restrict__ Cim,
                       const float* __restrict__ Dsk, int l)
{
    __shared__ float s_xr[128][16], s_xi[128][16];
    __shared__ float s_cr[16][129], s_ci[16][129];
    const float* res = xin ? xin : g_x;
    int tid = threadIdx.x;
    int row0 = blockIdx.x * 16;
    int b = row0 >> 12, t0 = row0 & (T-1);

    for (int e=tid; e<2048; e+=128){
        int np = e>>4, j = e&15;
        int gi = (b*NS+np)*T + t0 + j;
        s_xr[np][j] = g_bur[gi];
        s_xi[np][j] = g_bui[gi];
    }
    float acc[16];
    #pragma unroll
    for (int r=0;r<16;r++) acc[r]=0.f;
    int h = tid;
    for (int n0=0;n0<128;n0+=16){
        __syncthreads();
        for (int e=tid; e<2048; e+=128){
            int hh=e>>4, np=e&15;
            s_cr[np][hh] = Cre[(l*H+hh)*NS + n0+np];
            s_ci[np][hh] = Cim[(l*H+hh)*NS + n0+np];
        }
        __syncthreads();
        #pragma unroll
        for (int np=0;np<16;np++){
            float cr = s_cr[np][h], ci = s_ci[np][h];
            #pragma unroll
            for (int r=0;r<16;r++){
                acc[r] += s_xr[n0+np][r]*cr;
                acc[r] -= s_xi[n0+np][r]*ci;
            }
        }
    }
    float dsk = Dsk[l*H+h];
    #pragma unroll
    for (int r=0;r<16;r++){
        int gi = (row0+r)*H + h;
        g_x[gi] = res[gi] + 2.0f*acc[r] + g_xn[gi]*dsk;
    }
}

// ---------------- LN2 + MLP(128->256 gelu ->128) + residual, in-place on g_x ----------
__global__ void k_mlp(const float* __restrict__ g2, const float* __restrict__ b2v,
                      const float* __restrict__ W1, const float* __restrict__ b1v,
                      const float* __restrict__ W2, const float* __restrict__ b2o, int l)
{
    __shared__ float s_xn[16][128];
    __shared__ float s_h[16][256];
    __shared__ float s_w[4096];
    int tid=threadIdx.x, lane=tid&31, warp=tid>>5;
    int row0 = blockIdx.x*16;

    for (int rr=0;rr<4;rr++){
        int r = warp*4+rr;
        int base = (row0+r)*H;
        float v0 = g_x[base + lane];
        float v1 = g_x[base + lane + 32];
        float v2 = g_x[base + lane + 64];
        float v3 = g_x[base + lane + 96];
        float s  = v0+v1+v2+v3;
        float sq = v0*v0+v1*v1+v2*v2+v3*v3;
        #pragma unroll
        for (int o=16;o>0;o>>=1){ s += __shfl_xor_sync(FULL,s,o); sq += __shfl_xor_sync(FULL,sq,o); }
        float mu = s * (1.0f/128.0f);
        float var = sq * (1.0f/128.0f) - mu*mu;
        float rstd = rsqrtf(var + 1e-5f);
        float vv[4] = {v0,v1,v2,v3};
        #pragma unroll
        for (int q=0;q<4;q++){
            int h = lane + 32*q;
            s_xn[r][h] = (vv[q] - mu)*rstd * g2[l*H+h] + b2v[l*H+h];
        }
    }
    __syncthreads();

    float a0[16], a1[16];
    #pragma unroll
    for (int r=0;r<16;r++){ a0[r]=0.f; a1[r]=0.f; }
    for (int kc=0;kc<8;kc++){
        int k0=kc*16;
        __syncthreads();
        for (int e=tid;e<4096;e+=128) s_w[e] = W1[(l*H + k0 + (e>>8))*256 + (e&255)];
        __syncthreads();
        #pragma unroll
        for (int kk=0;kk<16;kk++){
            float wa = s_w[kk*256+tid], wb = s_w[kk*256+tid+128];
            #pragma unroll
            for (int r=0;r<16;r++){
                float u = s_xn[r][k0+kk];
                a0[r] += u*wa; a1[r] += u*wb;
            }
        }
    }
    float bb0 = b1v[l*256+tid], bb1 = b1v[l*256+tid+128];
    #pragma unroll
    for (int r=0;r<16;r++){
        float x0 = a0[r]+bb0, x1 = a1[r]+bb1;
        s_h[r][tid]     = 0.5f*x0*(1.0f+erff(x0*0.70710678118f));
        s_h[r][tid+128] = 0.5f*x1*(1.0f+erff(x1*0.70710678118f));
    }
    #pragma unroll
    for (int r=0;r<16;r++) a0[r]=0.f;
    for (int fc=0;fc<16;fc++){
        int f0=fc*16;
        __syncthreads();
        for (int e=tid;e<2048;e+=128) s_w[e] = W2[(l*256 + f0 + (e>>7))*H + (e&127)];
        __syncthreads();
        #pragma unroll
        for (int ff=0;ff<16;ff++){
            float w = s_w[ff*128+tid];
            #pragma unroll
            for (int r=0;r<16;r++) a0[r] += s_h[r][f0+ff]*w;
        }
    }
    float bo = b2o[l*H+tid];
    #pragma unroll
    for (int r=0;r<16;r++){
        int gi = (row0+r)*H+tid;
        g_x[gi] = g_x[gi] + a0[r] + bo;
    }
}

// ---------------- conv1 (stride2,k5,pad2) + relu : g_x[B,T,H] -> g_y1[B,C,2048] -------
__global__ void k_conv1(const float* __restrict__ w1, const float* __restrict__ bc1)
{
    __shared__ float s_x[67][128];
    __shared__ __align__(16) float s_w[20][132];
    int tid=threadIdx.x;
    int b  = blockIdx.x >> 6;
    int i0 = (blockIdx.x & 63)*32;
    int t0 = 2*i0 - 2;

    for (int e=tid;e<67*128;e+=128){
        int tl=e>>7, ic=e&127;
        int tg = t0+tl;
        s_x[tl][ic] = (tg>=0 && tg<T) ? g_x[(b*T+tg)*H+ic] : 0.0f;
    }
    int c4 = tid & 31, ig = tid >> 5;
    float acc[4][8];
    #pragma unroll
    for (int j=0;j<4;j++)
        #pragma unroll
        for (int ii=0;ii<8;ii++) acc[j][ii]=0.f;

    for (int icc=0; icc<32; icc++){
        int ic0=icc*4;
        __syncthreads();
        {
            const float* srcw = w1 + (tid*H + ic0)*5;
            #pragma unroll
            for (int e=0;e<20;e++) s_w[e][tid] = srcw[e];
        }
        __syncthreads();
        #pragma unroll
        for (int ic=0; ic<4; ic++){
            #pragma unroll
            for (int k=0;k<5;k++){
                float4 w = *(const float4*)&s_w[ic*5+k][c4*4];
                #pragma unroll
                for (int ii=0; ii<8; ii++){
                    float xv = s_x[2*(ig*8+ii)+k][ic0+ic];
                    acc[0][ii] += xv*w.x;
                    acc[1][ii] += xv*w.y;
                    acc[2][ii] += xv*w.z;
                    acc[3][ii] += xv*w.w;
                }
            }
        }
    }
    float4 bias = *(const float4*)&bc1[c4*4];
    float bb[4] = {bias.x,bias.y,bias.z,bias.w};
    #pragma unroll
    for (int j=0;j<4;j++){
        int ci = c4*4 + j;
        #pragma unroll
        for (int ii=0;ii<8;ii++){
            int ip = i0 + ig*8 + ii;
            g_y1[(b*H + ci)*T2 + ip] = fmaxf(acc[j][ii] + bb[j], 0.0f);
        }
    }
}

// ---------------- conv2 + relu + adaptive avg pool -> out[B,H,64] ----------------
__global__ void k_conv2pool(const float* __restrict__ w2, const float* __restrict__ bc2,
                            float* __restrict__ out)
{
    __shared__ float s_y[128][36];
    __shared__ __align__(16) float s_w[40][132];
    __shared__ float s_p[4][128];
    int tid=threadIdx.x;
    int b = blockIdx.x >> 6;
    int d = blockIdx.x & 63;
    int ibase = 32*d - 2;

    for (int e=tid; e<128*35; e+=128){
        int ic = e/35, ii = e - ic*35;
        int ig = ibase + ii;
        s_y[ic][ii] = (ig>=0 && ig<T2) ? g_y1[(b*H+ic)*T2 + ig] : 0.0f;
    }
    int c4 = tid&31, jg = tid>>5;
    float acc[4][4];
    #pragma unroll
    for (int a=0;a<4;a++)
        #pragma unroll
        for (int jj=0;jj<4;jj++) acc[a][jj]=0.f;

    for (int icc=0; icc<16; icc++){
        int ic0 = icc*8;
        __syncthreads();
        {
            const float* srcw = w2 + (tid*H + ic0)*5;
            #pragma unroll
            for (int e=0;e<40;e++) s_w[e][tid] = srcw[e];
        }
        __syncthreads();
        #pragma unroll
        for (int ic=0; ic<8; ic++){
            #pragma unroll
            for (int k=0;k<5;k++){
                float4 w = *(const float4*)&s_w[ic*5+k][c4*4];
                #pragma unroll
                for (int jj=0;jj<4;jj++){
                    float xv = s_y[ic0+ic][2*(jg*4+jj)+k];
                    acc[0][jj]+=xv*w.x; acc[1][jj]+=xv*w.y;
                    acc[2][jj]+=xv*w.z; acc[3][jj]+=xv*w.w;
                }
            }
        }
    }
    float4 bias = *(const float4*)&bc2[c4*4];
    float bb[4]={bias.x,bias.y,bias.z,bias.w};
    #pragma unroll
    for (int cc=0;cc<4;cc++){
        float p = 0.f;
        #pragma unroll
        for (int jj=0;jj<4;jj++) p += fmaxf(acc[cc][jj] + bb[cc], 0.0f);
        s_p[jg][c4*4+cc] = p;
    }
    __syncthreads();
    {
        int c = tid;
        float v = (s_p[0][c]+s_p[1][c]+s_p[2][c]+s_p[3][c]) * (1.0f/16.0f);
        out[(b*H+c)*DOUT + d] = v;
    }
}

// ---------------- launch ----------------
extern "C" void kernel_launch(void* const* d_in, const int* in_sizes, int n_in,
                              void* d_out, int out_size)
{
    (void)in_sizes; (void)n_in; (void)out_size;
    const float* x    = (const float*)d_in[0];
    const float* ln1g = (const float*)d_in[1];
    const float* ln1b = (const float*)d_in[2];
    const float* ln2g = (const float*)d_in[3];
    const float* ln2b = (const float*)d_in[4];
    const float* lre  = (const float*)d_in[5];
    const float* lim  = (const float*)d_in[6];
    const float* Bre  = (const float*)d_in[7];
    const float* Bim  = (const float*)d_in[8];
    const float* Cre  = (const float*)d_in[9];
    const float* Cim  = (const float*)d_in[10];
    const float* Dsk  = (const float*)d_in[11];
    const float* lstep= (const float*)d_in[12];
    const float* W1   = (const float*)d_in[13];
    const float* b1   = (const float*)d_in[14];
    const float* W2   = (const float*)d_in[15];
    const float* b2   = (const float*)d_in[16];
    const float* c1w  = (const float*)d_in[17];
    const float* c1b  = (const float*)d_in[18];
    const float* c2w  = (const float*)d_in[19];
    const float* c2b  = (const float*)d_in[20];
    float* out = (float*)d_out;

    k_prep<<<DEPTH*NS, H>>>(lre, lim, Bre, Bim, lstep);
    for (int l=0;l<DEPTH;l++){
        const float* xin = (l==0) ? x : nullptr;   // nullptr -> read g_x inside
        k_ln_bu<<<TT/16, 128>>>(xin, ln1g, ln1b, l);
        k_scan<<<BATCH*NS, 256>>>(l);
        k_cmix<<<TT/16, 128>>>(xin, Cre, Cim, Dsk, l);
        k_mlp<<<TT/16, 128>>>(ln2g, ln2b, W1, b1, W2, b2, l);
    }
    k_conv1<<<BATCH*64, 128>>>(c1w, c1b);
    k_conv2pool<<<BATCH*64, 128>>>(c2w, c2b, out);
}

// round 3
// speedup vs baseline: 1.3627x; 1.3627x over previous
#include <cuda_runtime.h>
#include <math.h>
#include <stdint.h>

#define BATCH 32
#define T 4096
#define H 128
#define NS 128
#define DEPTH 2
#define TT (BATCH*T)
#define T2 2048
#define DOUT 64
#define FULL 0xFFFFFFFFu

// ---------------- scratch (device globals; no allocs allowed) ----------------
__device__ float g_x  [TT*H];        // running activation [B*T][H]
__device__ float g_xn [TT*H];        // LN1 output (needed for D-skip)
__device__ float g_bur[BATCH*NS*T];  // Bu / xs real, layout [B][N][T]
__device__ float g_bui[BATCH*NS*T];  // Bu / xs imag
__device__ float g_y1 [BATCH*H*T2];  // conv1 output [B][C][2048]
__device__ float g_lbr[DEPTH*NS], g_lbi[DEPTH*NS];           // lambda_bar
__device__ uint32_t g_Wbu[DEPTH*H*256];   // tf32 [l][k=h][n] n<128:re n>=128:im
__device__ uint32_t g_Wc [DEPTH*256*H];   // tf32 [l][k](k<128:2*Cre,k>=128:-2*Cim)[h]
__device__ uint32_t g_W1t[DEPTH*H*256];   // tf32 copy of W1
__device__ uint32_t g_W2t[DEPTH*256*H];   // tf32 copy of W2

// ---------------- helpers ----------------
__device__ __forceinline__ uint32_t f2tf(float x){
    uint32_t u; asm("cvt.rna.tf32.f32 %0, %1;" : "=r"(u) : "f"(x)); return u;
}
__device__ __forceinline__ void mma8(float* c, uint32_t a0,uint32_t a1,uint32_t a2,uint32_t a3,
                                     uint32_t b0,uint32_t b1){
    asm volatile("mma.sync.aligned.m16n8k8.row.col.f32.tf32.tf32.f32 "
        "{%0,%1,%2,%3},{%4,%5,%6,%7},{%8,%9},{%0,%1,%2,%3};"
        : "+f"(c[0]),"+f"(c[1]),"+f"(c[2]),"+f"(c[3])
        : "r"(a0),"r"(a1),"r"(a2),"r"(a3),"r"(b0),"r"(b1));
}

// ---------------- param prep: lambda_bar, W_bu (tf32, transposed, combined) --------
__global__ void k_prep(const float* __restrict__ lre, const float* __restrict__ lim,
                       const float* __restrict__ Bre, const float* __restrict__ Bim,
                       const float* __restrict__ lstep)
{
    int idx = blockIdx.x;               // l*NS + n
    int l = idx >> 7, n = idx & 127;
    float lr = lre[idx], li = lim[idx];
    float dt = expf(lstep[idx]);
    float er = expf(lr*dt);
    float lbr = er * cosf(li*dt);
    float lbi = er * sinf(li*dt);
    if (threadIdx.x == 0){ g_lbr[idx]=lbr; g_lbi[idx]=lbi; }
    float den = lr*lr + li*li;
    float nr = lbr - 1.0f, ni = lbi;
    float fr = (nr*lr + ni*li)/den;
    float fi = (ni*lr - nr*li)/den;
    int h = threadIdx.x;
    float br = Bre[idx*H + h], bi = Bim[idx*H + h];
    float wr = fr*br - fi*bi;
    float wi = fr*bi + fi*br;
    g_Wbu[(l*H + h)*256 + n]       = f2tf(wr);
    g_Wbu[(l*H + h)*256 + 128 + n] = f2tf(wi);
}

__global__ void k_prepW(const float* __restrict__ Cre, const float* __restrict__ Cim,
                        const float* __restrict__ W1, const float* __restrict__ W2)
{
    int i = blockIdx.x*256 + threadIdx.x;        // 65536 total, exactly each array size
    {   // Wc [l][k][h]
        int l = i>>15, k = (i>>7)&255, h = i&127;
        float v = (k<128) ? 2.0f*Cre[(l*H+h)*NS + k]
                          : -2.0f*Cim[(l*H+h)*NS + (k-128)];
        g_Wc[i] = f2tf(v);
    }
    g_W1t[i] = f2tf(W1[i]);
    g_W2t[i] = f2tf(W2[i]);
}

// ===================== LN1 + Bu GEMM (tf32 mma), write Bu [B][N][T] =================
// block: 64 rows, 256 threads, K=128, N=256
#define SM_LNBU (16896*4)
__global__ void k_ln_bu(const float* __restrict__ xin,
                        const float* __restrict__ g1, const float* __restrict__ b1v, int l)
{
    extern __shared__ uint32_t smem[];
    uint32_t* sa = smem;            // [64][132]
    uint32_t* sw = smem + 64*132;   // [32][264]
    const float* src = xin ? xin : g_x;
    int tid = threadIdx.x, lane = tid&31, warp = tid>>5;
    int gid = lane>>2, tig = lane&3;
    int row0 = blockIdx.x * 64;
    int b = row0 >> 12, t0 = row0 & (T-1);

    // ---- LayerNorm: warp per row, 8 rows per warp ----
    for (int rr = 0; rr < 8; rr++){
        int r = warp*8 + rr;
        int base = (row0 + r) * H;
        float v0 = src[base + lane];
        float v1 = src[base + lane + 32];
        float v2 = src[base + lane + 64];
        float v3 = src[base + lane + 96];
        float s  = v0+v1+v2+v3;
        float sq = v0*v0+v1*v1+v2*v2+v3*v3;
        #pragma unroll
        for (int o=16;o>0;o>>=1){ s += __shfl_xor_sync(FULL,s,o); sq += __shfl_xor_sync(FULL,sq,o); }
        float mu = s * (1.0f/128.0f);
        float var = sq * (1.0f/128.0f) - mu*mu;
        float rstd = rsqrtf(var + 1e-5f);
        float vv[4] = {v0,v1,v2,v3};
        #pragma unroll
        for (int q=0;q<4;q++){
            int h = lane + 32*q;
            float xn = (vv[q] - mu)*rstd * g1[l*H+h] + b1v[l*H+h];
            sa[r*132 + h] = f2tf(xn);
            g_xn[base + h] = xn;
        }
    }

    int wm = (warp>>1)*16, wn = (warp&1)*128;
    float acc[16][4];
    #pragma unroll
    for (int nt=0;nt<16;nt++){ acc[nt][0]=acc[nt][1]=acc[nt][2]=acc[nt][3]=0.f; }

    for (int kc=0; kc<4; kc++){
        __syncthreads();
        int kb = kc*32;
        for (int e=tid; e<8192; e+=256){
            int n = e&255, kk = e>>8;
            sw[kk*264+n] = g_Wbu[(l*H + kb + kk)*256 + n];
        }
        __syncthreads();
        #pragma unroll
        for (int ks=0; ks<4; ks++){
            int k0 = kb + ks*8, k0w = ks*8;
            uint32_t a0 = sa[(wm+gid)*132   + k0 + tig];
            uint32_t a1 = sa[(wm+gid+8)*132 + k0 + tig];
            uint32_t a2 = sa[(wm+gid)*132   + k0 + tig+4];
            uint32_t a3 = sa[(wm+gid+8)*132 + k0 + tig+4];
            #pragma unroll
            for (int nt=0; nt<16; nt++){
                uint32_t b0 = sw[(k0w+tig)*264   + wn + nt*8 + gid];
                uint32_t b1 = sw[(k0w+tig+4)*264 + wn + nt*8 + gid];
                mma8(acc[nt], a0,a1,a2,a3, b0,b1);
            }
        }
    }
    __syncthreads();
    // stage to smem (stride 257), then transposed coalesced writes
    float* so = (float*)smem;
    #pragma unroll
    for (int nt=0; nt<16; nt++){
        int n = wn + nt*8 + 2*tig;
        so[(wm+gid)*257 + n]     = acc[nt][0];
        so[(wm+gid)*257 + n+1]   = acc[nt][1];
        so[(wm+gid+8)*257 + n]   = acc[nt][2];
        so[(wm+gid+8)*257 + n+1] = acc[nt][3];
    }
    __syncthreads();
    for (int i=0; i<32; i++){
        int n = warp*32 + i;
        int np = n & 127;
        float* dst = ((n<128) ? g_bur : g_bui) + (b*NS + np)*T + t0;
        dst[lane]    = so[lane*257 + n];
        dst[lane+32] = so[(lane+32)*257 + n];
    }
}

// ---------------- in-place scan over T: x_t = lam_bar * x_{t-1} + Bu_t ----------------
__global__ void k_scan(int l)
{
    __shared__ float s_wr[8], s_wi[8], s_er[8], s_ei[8];
    int bid = blockIdx.x;        // b*NS + n
    int n = bid & (NS-1);
    int tid = threadIdx.x, lane = tid & 31, warp = tid >> 5;
    int base = bid * T + tid * 16;
    float lr = g_lbr[l*NS+n], li = g_lbi[l*NS+n];

    float vr[16], vi[16];
    float4* pr = (float4*)(g_bur + base);
    float4* pi = (float4*)(g_bui + base);
    #pragma unroll
    for (int q=0;q<4;q++){
        float4 a = pr[q]; vr[4*q]=a.x; vr[4*q+1]=a.y; vr[4*q+2]=a.z; vr[4*q+3]=a.w;
        float4 c = pi[q]; vi[4*q]=c.x; vi[4*q+1]=c.y; vi[4*q+2]=c.z; vi[4*q+3]=c.w;
    }
    float sr=0.f, si=0.f;
    #pragma unroll
    for (int i=0;i<16;i++){
        float tr = lr*sr - li*si + vr[i];
        float ti = lr*si + li*sr + vi[i];
        sr=tr; si=ti;
    }
    float cdr[6], cdi[6];
    {
        float pr_=lr, pi_=li;
        #pragma unroll
        for (int q=0;q<4;q++){ float tr = pr_*pr_ - pi_*pi_; pi_ = 2.f*pr_*pi_; pr_ = tr; }
        cdr[0]=pr_; cdi[0]=pi_;
        #pragma unroll
        for (int q=1;q<6;q++){ float tr = cdr[q-1]*cdr[q-1]-cdi[q-1]*cdi[q-1];
                               cdi[q]=2.f*cdr[q-1]*cdi[q-1]; cdr[q]=tr; }
    }
    float xr=sr, xi=si;
    #pragma unroll
    for (int st=0; st<5; st++){
        int d = 1<<st;
        float or_ = __shfl_up_sync(FULL, xr, d);
        float oi_ = __shfl_up_sync(FULL, xi, d);
        if (lane >= d){
            float tr = cdr[st]*or_ - cdi[st]*oi_ + xr;
            xi = cdr[st]*oi_ + cdi[st]*or_ + xi;
            xr = tr;
        }
    }
    if (lane==31){ s_wr[warp]=xr; s_wi[warp]=xi; }
    __syncthreads();
    if (tid==0){
        float er=0.f, ei=0.f;
        #pragma unroll
        for (int w=0;w<8;w++){
            s_er[w]=er; s_ei[w]=ei;
            float tr = cdr[5]*er - cdi[5]*ei + s_wr[w];
            ei = cdr[5]*ei + cdi[5]*er + s_wi[w];
            er = tr;
        }
    }
    __syncthreads();
    float Er = s_er[warp], Ei = s_ei[warp];
    float plr=1.f, pli=0.f;
    #pragma unroll
    for (int bt=0; bt<5; bt++){
        if (lane & (1<<bt)){
            float tr = plr*cdr[bt] - pli*cdi[bt];
            pli = plr*cdi[bt] + pli*cdr[bt];
            plr = tr;
        }
    }
    float car = plr*Er - pli*Ei;
    float cai = plr*Ei + pli*Er;
    float pvr = __shfl_up_sync(FULL, xr, 1);
    float pvi = __shfl_up_sync(FULL, xi, 1);
    if (lane > 0){ car += pvr; cai += pvi; }
    sr = car; si = cai;
    #pragma unroll
    for (int i=0;i<16;i++){
        float tr = lr*sr - li*si + vr[i];
        float ti = lr*si + li*sr + vi[i];
        sr=tr; si=ti;
        vr[i]=sr; vi[i]=si;
    }
    #pragma unroll
    for (int q=0;q<4;q++){
        pr[q] = make_float4(vr[4*q],vr[4*q+1],vr[4*q+2],vr[4*q+3]);
        pi[q] = make_float4(vi[4*q],vi[4*q+1],vi[4*q+2],vi[4*q+3]);
    }
}

// ===================== C-mix GEMM: y = res + [xr|xi]@Wc + xn*D (tf32 mma) ===========
// block: 64 rows, 256 threads, K=256, N=128
#define SM_CMIX (22784*4)
__global__ void k_cmix(const float* __restrict__ xin, const float* __restrict__ Dsk, int l)
{
    extern __shared__ uint32_t smem[];
    uint32_t* saT = smem;             // [256][72] (k-major)
    uint32_t* sw  = smem + 256*72;    // [32][136]
    int tid = threadIdx.x, lane = tid&31, warp = tid>>5;
    int gid = lane>>2, tig = lane&3;
    int row0 = blockIdx.x * 64;
    int b = row0 >> 12, t0 = row0 & (T-1);

    for (int e=tid; e<16384; e+=256){
        int r = e&63, k = e>>6;
        const float* srcp = (k<128) ? (g_bur + (b*NS+k)*T + t0)
                                    : (g_bui + (b*NS + (k-128))*T + t0);
        saT[k*72 + r] = f2tf(srcp[r]);
    }

    int wm = (warp>>1)*16, wn = (warp&1)*64;
    float acc[8][4];
    #pragma unroll
    for (int nt=0;nt<8;nt++){ acc[nt][0]=acc[nt][1]=acc[nt][2]=acc[nt][3]=0.f; }

    for (int kc=0; kc<8; kc++){
        __syncthreads();
        for (int e=tid; e<4096; e+=256){
            int n = e&127, kk = e>>7;
            sw[kk*136+n] = g_Wc[(l*256 + kc*32 + kk)*128 + n];
        }
        __syncthreads();
        #pragma unroll
        for (int ks=0; ks<4; ks++){
            int k0 = kc*32 + ks*8, k0w = ks*8;
            uint32_t a0 = saT[(k0+tig)*72   + wm+gid];
            uint32_t a1 = saT[(k0+tig)*72   + wm+gid+8];
            uint32_t a2 = saT[(k0+tig+4)*72 + wm+gid];
            uint32_t a3 = saT[(k0+tig+4)*72 + wm+gid+8];
            #pragma unroll
            for (int nt=0; nt<8; nt++){
                uint32_t b0 = sw[(k0w+tig)*136   + wn + nt*8 + gid];
                uint32_t b1 = sw[(k0w+tig+4)*136 + wn + nt*8 + gid];
                mma8(acc[nt], a0,a1,a2,a3, b0,b1);
            }
        }
    }
    __syncthreads();
    float* so = (float*)smem;   // [64][132]
    #pragma unroll
    for (int nt=0; nt<8; nt++){
        int n = wn + nt*8 + 2*tig;
        so[(wm+gid)*132 + n]     = acc[nt][0];
        so[(wm+gid)*132 + n+1]   = acc[nt][1];
        so[(wm+gid+8)*132 + n]   = acc[nt][2];
        so[(wm+gid+8)*132 + n+1] = acc[nt][3];
    }
    __syncthreads();
    const float* res = xin ? xin : g_x;
    for (int e=tid; e<8192; e+=256){
        int h = e&127, r = e>>7;
        int gi = (row0+r)*H + h;
        g_x[gi] = res[gi] + so[r*132+h] + g_xn[gi]*Dsk[l*H+h];
    }
}

// ===================== LN2 + MLP (tf32 mma), in-place on g_x ========================
// block: 32 rows, 256 threads
#define SM_MLP (20992*4)
__global__ void k_mlp(const float* __restrict__ g2, const float* __restrict__ b2v,
                      const float* __restrict__ b1v, const float* __restrict__ b2o, int l)
{
    extern __shared__ uint32_t smem[];
    uint32_t* sa = smem;                     // [32][132]
    uint32_t* sw = smem + 32*132;            // [32][264]  (also [32][136] for GEMM2)
    uint32_t* sh = smem + 32*132 + 32*264;   // [32][260]
    int tid = threadIdx.x, lane = tid&31, warp = tid>>5;
    int gid = lane>>2, tig = lane&3;
    int row0 = blockIdx.x * 32;

    // LN2: warp per row, 4 rows each
    for (int rr=0; rr<4; rr++){
        int r = warp*4 + rr;
        int base = (row0+r)*H;
        float v0 = g_x[base + lane];
        float v1 = g_x[base + lane + 32];
        float v2 = g_x[base + lane + 64];
        float v3 = g_x[base + lane + 96];
        float s  = v0+v1+v2+v3;
        float sq = v0*v0+v1*v1+v2*v2+v3*v3;
        #pragma unroll
        for (int o=16;o>0;o>>=1){ s += __shfl_xor_sync(FULL,s,o); sq += __shfl_xor_sync(FULL,sq,o); }
        float mu = s * (1.0f/128.0f);
        float var = sq * (1.0f/128.0f) - mu*mu;
        float rstd = rsqrtf(var + 1e-5f);
        float vv[4] = {v0,v1,v2,v3};
        #pragma unroll
        for (int q=0;q<4;q++){
            int h = lane + 32*q;
            sa[r*132 + h] = f2tf((vv[q] - mu)*rstd * g2[l*H+h] + b2v[l*H+h]);
        }
    }

    // ---- GEMM1: [32x128] @ [128x256] ----
    int wm = (warp>>2)*16, wn = (warp&3)*64;
    float acc[8][4];
    #pragma unroll
    for (int nt=0;nt<8;nt++){ acc[nt][0]=acc[nt][1]=acc[nt][2]=acc[nt][3]=0.f; }
    for (int kc=0; kc<4; kc++){
        __syncthreads();
        for (int e=tid; e<8192; e+=256){
            int n = e&255, kk = e>>8;
            sw[kk*264+n] = g_W1t[(l*H + kc*32 + kk)*256 + n];
        }
        __syncthreads();
        #pragma unroll
        for (int ks=0; ks<4; ks++){
            int k0 = kc*32 + ks*8, k0w = ks*8;
            uint32_t a0 = sa[(wm+gid)*132   + k0 + tig];
            uint32_t a1 = sa[(wm+gid+8)*132 + k0 + tig];
            uint32_t a2 = sa[(wm+gid)*132   + k0 + tig+4];
            uint32_t a3 = sa[(wm+gid+8)*132 + k0 + tig+4];
            #pragma unroll
            for (int nt=0; nt<8; nt++){
                uint32_t b0 = sw[(k0w+tig)*264   + wn + nt*8 + gid];
                uint32_t b1 = sw[(k0w+tig+4)*264 + wn + nt*8 + gid];
                mma8(acc[nt], a0,a1,a2,a3, b0,b1);
            }
        }
    }
    // bias + gelu -> sh (tf32)
    #pragma unroll
    for (int nt=0; nt<8; nt++){
        int n = wn + nt*8 + 2*tig;
        float bb0 = b1v[l*256 + n], bb1 = b1v[l*256 + n + 1];
        float x0 = acc[nt][0]+bb0, x1 = acc[nt][1]+bb1;
        float x2 = acc[nt][2]+bb0, x3 = acc[nt][3]+bb1;
        sh[(wm+gid)*260 + n]     = f2tf(0.5f*x0*(1.0f+erff(x0*0.70710678118f)));
        sh[(wm+gid)*260 + n+1]   = f2tf(0.5f*x1*(1.0f+erff(x1*0.70710678118f)));
        sh[(wm+gid+8)*260 + n]   = f2tf(0.5f*x2*(1.0f+erff(x2*0.70710678118f)));
        sh[(wm+gid+8)*260 + n+1] = f2tf(0.5f*x3*(1.0f+erff(x3*0.70710678118f)));
    }

    // ---- GEMM2: [32x256] @ [256x128] ----
    int wn2 = (warp&3)*32;
    float acc2[4][4];
    #pragma unroll
    for (int nt=0;nt<4;nt++){ acc2[nt][0]=acc2[nt][1]=acc2[nt][2]=acc2[nt][3]=0.f; }
    for (int kc=0; kc<8; kc++){
        __syncthreads();
        for (int e=tid; e<4096; e+=256){
            int n = e&127, kk = e>>7;
            sw[kk*136+n] = g_W2t[(l*256 + kc*32 + kk)*128 + n];
        }
        __syncthreads();
        #pragma unroll
        for (int ks=0; ks<4; ks++){
            int k0 = kc*32 + ks*8, k0w = ks*8;
            uint32_t a0 = sh[(wm+gid)*260   + k0 + tig];
            uint32_t a1 = sh[(wm+gid+8)*260 + k0 + tig];
            uint32_t a2 = sh[(wm+gid)*260   + k0 + tig+4];
            uint32_t a3 = sh[(wm+gid+8)*260 + k0 + tig+4];
            #pragma unroll
            for (int nt=0; nt<4; nt++){
                uint32_t b0 = sw[(k0w+tig)*136   + wn2 + nt*8 + gid];
                uint32_t b1 = sw[(k0w+tig+4)*136 + wn2 + nt*8 + gid];
                mma8(acc2[nt], a0,a1,a2,a3, b0,b1);
            }
        }
    }
    __syncthreads();
    float* so = (float*)sa;    // [32][132]
    #pragma unroll
    for (int nt=0; nt<4; nt++){
        int n = wn2 + nt*8 + 2*tig;
        so[(wm+gid)*132 + n]     = acc2[nt][0];
        so[(wm+gid)*132 + n+1]   = acc2[nt][1];
        so[(wm+gid+8)*132 + n]   = acc2[nt][2];
        so[(wm+gid+8)*132 + n+1] = acc2[nt][3];
    }
    __syncthreads();
    for (int e=tid; e<4096; e+=256){
        int h = e&127, r = e>>7;
        int gi = (row0+r)*H + h;
        g_x[gi] = g_x[gi] + so[r*132+h] + b2o[l*H+h];
    }
}

// ---------------- conv1 (stride2,k5,pad2) + relu : g_x[B,T,H] -> g_y1[B,C,2048] -------
__global__ void k_conv1(const float* __restrict__ w1, const float* __restrict__ bc1)
{
    __shared__ float s_x[67][128];
    __shared__ __align__(16) float s_w[20][132];
    int tid=threadIdx.x;
    int b  = blockIdx.x >> 6;
    int i0 = (blockIdx.x & 63)*32;
    int t0 = 2*i0 - 2;

    for (int e=tid;e<67*128;e+=128){
        int tl=e>>7, ic=e&127;
        int tg = t0+tl;
        s_x[tl][ic] = (tg>=0 && tg<T) ? g_x[(b*T+tg)*H+ic] : 0.0f;
    }
    int c4 = tid & 31, ig = tid >> 5;
    float acc[4][8];
    #pragma unroll
    for (int j=0;j<4;j++)
        #pragma unroll
        for (int ii=0;ii<8;ii++) acc[j][ii]=0.f;

    for (int icc=0; icc<32; icc++){
        int ic0=icc*4;
        __syncthreads();
        {
            const float* srcw = w1 + (tid*H + ic0)*5;
            #pragma unroll
            for (int e=0;e<20;e++) s_w[e][tid] = srcw[e];
        }
        __syncthreads();
        #pragma unroll
        for (int ic=0; ic<4; ic++){
            #pragma unroll
            for (int k=0;k<5;k++){
                float4 w = *(const float4*)&s_w[ic*5+k][c4*4];
                #pragma unroll
                for (int ii=0; ii<8; ii++){
                    float xv = s_x[2*(ig*8+ii)+k][ic0+ic];
                    acc[0][ii] += xv*w.x;
                    acc[1][ii] += xv*w.y;
                    acc[2][ii] += xv*w.z;
                    acc[3][ii] += xv*w.w;
                }
            }
        }
    }
    float4 bias = *(const float4*)&bc1[c4*4];
    float bb[4] = {bias.x,bias.y,bias.z,bias.w};
    #pragma unroll
    for (int j=0;j<4;j++){
        int ci = c4*4 + j;
        #pragma unroll
        for (int ii=0;ii<8;ii++){
            int ip = i0 + ig*8 + ii;
            g_y1[(b*H + ci)*T2 + ip] = fmaxf(acc[j][ii] + bb[j], 0.0f);
        }
    }
}

// ---------------- conv2 + relu + adaptive avg pool -> out[B,H,64] ----------------
__global__ void k_conv2pool(const float* __restrict__ w2, const float* __restrict__ bc2,
                            float* __restrict__ out)
{
    __shared__ float s_y[128][36];
    __shared__ __align__(16) float s_w[40][132];
    __shared__ float s_p[4][128];
    int tid=threadIdx.x;
    int b = blockIdx.x >> 6;
    int d = blockIdx.x & 63;
    int ibase = 32*d - 2;

    for (int e=tid; e<128*35; e+=128){
        int ic = e/35, ii = e - ic*35;
        int ig = ibase + ii;
        s_y[ic][ii] = (ig>=0 && ig<T2) ? g_y1[(b*H+ic)*T2 + ig] : 0.0f;
    }
    int c4 = tid&31, jg = tid>>5;
    float acc[4][4];
    #pragma unroll
    for (int a=0;a<4;a++)
        #pragma unroll
        for (int jj=0;jj<4;jj++) acc[a][jj]=0.f;

    for (int icc=0; icc<16; icc++){
        int ic0 = icc*8;
        __syncthreads();
        {
            const float* srcw = w2 + (tid*H + ic0)*5;
            #pragma unroll
            for (int e=0;e<40;e++) s_w[e][tid] = srcw[e];
        }
        __syncthreads();
        #pragma unroll
        for (int ic=0; ic<8; ic++){
            #pragma unroll
            for (int k=0;k<5;k++){
                float4 w = *(const float4*)&s_w[ic*5+k][c4*4];
                #pragma unroll
                for (int jj=0;jj<4;jj++){
                    float xv = s_y[ic0+ic][2*(jg*4+jj)+k];
                    acc[0][jj]+=xv*w.x; acc[1][jj]+=xv*w.y;
                    acc[2][jj]+=xv*w.z; acc[3][jj]+=xv*w.w;
                }
            }
        }
    }
    float4 bias = *(const float4*)&bc2[c4*4];
    float bb[4]={bias.x,bias.y,bias.z,bias.w};
    #pragma unroll
    for (int cc=0;cc<4;cc++){
        float p = 0.f;
        #pragma unroll
        for (int jj=0;jj<4;jj++) p += fmaxf(acc[cc][jj] + bb[cc], 0.0f);
        s_p[jg][c4*4+cc] = p;
    }
    __syncthreads();
    {
        int c = tid;
        float v = (s_p[0][c]+s_p[1][c]+s_p[2][c]+s_p[3][c]) * (1.0f/16.0f);
        out[(b*H+c)*DOUT + d] = v;
    }
}

// ---------------- launch ----------------
extern "C" void kernel_launch(void* const* d_in, const int* in_sizes, int n_in,
                              void* d_out, int out_size)
{
    (void)in_sizes; (void)n_in; (void)out_size;
    const float* x    = (const float*)d_in[0];
    const float* ln1g = (const float*)d_in[1];
    const float* ln1b = (const float*)d_in[2];
    const float* ln2g = (const float*)d_in[3];
    const float* ln2b = (const float*)d_in[4];
    const float* lre  = (const float*)d_in[5];
    const float* lim  = (const float*)d_in[6];
    const float* Bre  = (const float*)d_in[7];
    const float* Bim  = (const float*)d_in[8];
    const float* Cre  = (const float*)d_in[9];
    const float* Cim  = (const float*)d_in[10];
    const float* Dsk  = (const float*)d_in[11];
    const float* lstep= (const float*)d_in[12];
    const float* b1   = (const float*)d_in[14];
    const float* b2   = (const float*)d_in[16];
    const float* W1   = (const float*)d_in[13];
    const float* W2   = (const float*)d_in[15];
    const float* c1w  = (const float*)d_in[17];
    const float* c1b  = (const float*)d_in[18];
    const float* c2w  = (const float*)d_in[19];
    const float* c2b  = (const float*)d_in[20];
    float* out = (float*)d_out;

    cudaFuncSetAttribute(k_ln_bu, cudaFuncAttributeMaxDynamicSharedMemorySize, SM_LNBU);
    cudaFuncSetAttribute(k_cmix,  cudaFuncAttributeMaxDynamicSharedMemorySize, SM_CMIX);
    cudaFuncSetAttribute(k_mlp,   cudaFuncAttributeMaxDynamicSharedMemorySize, SM_MLP);

    k_prep<<<DEPTH*NS, H>>>(lre, lim, Bre, Bim, lstep);
    k_prepW<<<256, 256>>>(Cre, Cim, W1, W2);
    for (int l=0;l<DEPTH;l++){
        const float* xin = (l==0) ? x : nullptr;
        k_ln_bu<<<TT/64, 256, SM_LNBU>>>(xin, ln1g, ln1b, l);
        k_scan<<<BATCH*NS, 256>>>(l);
        k_cmix<<<TT/64, 256, SM_CMIX>>>(xin, Dsk, l);
        k_mlp<<<TT/32, 256, SM_MLP>>>(ln2g, ln2b, b1, b2, l);
    }
    k_conv1<<<BATCH*64, 128>>>(c1w, c1b);
    k_conv2pool<<<BATCH*64, 128>>>(c2w, c2b, out);
}

// round 4
// speedup vs baseline: 3.1487x; 2.3106x over previous
#include <cuda_runtime.h>
#include <math.h>
#include <stdint.h>

#define BATCH 32
#define T 4096
#define H 128
#define NS 128
#define DEPTH 2
#define TT (BATCH*T)
#define T2 2048
#define T4 1024
#define DOUT 64
#define FULL 0xFFFFFFFFu

// ---------------- scratch (device globals; no allocs allowed) ----------------
__device__ float g_x  [TT*H];        // running activation [B*T][H]
__device__ float g_xn [TT*H];        // LN1 output (needed for D-skip)
__device__ float g_bur[BATCH*NS*T];  // Bu / xs real, layout [B][N][T]
__device__ float g_bui[BATCH*NS*T];  // Bu / xs imag
__device__ float g_y1 [BATCH*T2*H];  // conv1 output [B][T2][C]
__device__ float g_lbr[DEPTH*NS], g_lbi[DEPTH*NS];
__device__ uint32_t g_Wbu[DEPTH*H*256];   // tf32 [l][k=h][n] n<128:re n>=128:im
__device__ uint32_t g_Wc [DEPTH*256*H];   // tf32 [l][k](k<128:2*Cre,k>=128:-2*Cim)[h]
__device__ uint32_t g_W1t[DEPTH*H*256];   // tf32 copy of W1
__device__ uint32_t g_W2t[DEPTH*256*H];   // tf32 copy of W2
__device__ uint32_t g_Wc1[640*128];       // conv1 w tf32 [kk=kv*128+ic][co]
__device__ uint32_t g_Wc2[640*128];       // conv2 w tf32

// ---------------- helpers ----------------
__device__ __forceinline__ uint32_t f2tf(float x){
    uint32_t u; asm("cvt.rna.tf32.f32 %0, %1;" : "=r"(u) : "f"(x)); return u;
}
__device__ __forceinline__ void mma8(float* c, uint32_t a0,uint32_t a1,uint32_t a2,uint32_t a3,
                                     uint32_t b0,uint32_t b1){
    asm volatile("mma.sync.aligned.m16n8k8.row.col.f32.tf32.tf32.f32 "
        "{%0,%1,%2,%3},{%4,%5,%6,%7},{%8,%9},{%0,%1,%2,%3};"
        : "+f"(c[0]),"+f"(c[1]),"+f"(c[2]),"+f"(c[3])
        : "r"(a0),"r"(a1),"r"(a2),"r"(a3),"r"(b0),"r"(b1));
}
__device__ __forceinline__ void cpa16(uint32_t s, const void* g){
    asm volatile("cp.async.cg.shared.global [%0], [%1], 16;" :: "r"(s), "l"(g));
}
__device__ __forceinline__ void cpcommit(){ asm volatile("cp.async.commit_group;" ::: "memory"); }
__device__ __forceinline__ void cpwait0(){ asm volatile("cp.async.wait_group 0;" ::: "memory"); }

// ---------------- param prep ----------------
__global__ void k_prep(const float* __restrict__ lre, const float* __restrict__ lim,
                       const float* __restrict__ Bre, const float* __restrict__ Bim,
                       const float* __restrict__ lstep)
{
    int idx = blockIdx.x;               // l*NS + n
    int l = idx >> 7, n = idx & 127;
    float lr = lre[idx], li = lim[idx];
    float dt = expf(lstep[idx]);
    float er = expf(lr*dt);
    float lbr = er * cosf(li*dt);
    float lbi = er * sinf(li*dt);
    if (threadIdx.x == 0){ g_lbr[idx]=lbr; g_lbi[idx]=lbi; }
    float den = lr*lr + li*li;
    float nr = lbr - 1.0f, ni = lbi;
    float fr = (nr*lr + ni*li)/den;
    float fi = (ni*lr - nr*li)/den;
    int h = threadIdx.x;
    float br = Bre[idx*H + h], bi = Bim[idx*H + h];
    float wr = fr*br - fi*bi;
    float wi = fr*bi + fi*br;
    g_Wbu[(l*H + h)*256 + n]       = f2tf(wr);
    g_Wbu[(l*H + h)*256 + 128 + n] = f2tf(wi);
}

__global__ void k_prepW(const float* __restrict__ Cre, const float* __restrict__ Cim,
                        const float* __restrict__ W1, const float* __restrict__ W2)
{
    int i = blockIdx.x*256 + threadIdx.x;        // 65536 total
    {
        int l = i>>15, k = (i>>7)&255, h = i&127;
        float v = (k<128) ? 2.0f*Cre[(l*H+h)*NS + k]
                          : -2.0f*Cim[(l*H+h)*NS + (k-128)];
        g_Wc[i] = f2tf(v);
    }
    g_W1t[i] = f2tf(W1[i]);
    g_W2t[i] = f2tf(W2[i]);
}

__global__ void k_prepConv(const float* __restrict__ w1, const float* __restrict__ w2)
{
    int i = blockIdx.x*256 + threadIdx.x;        // 81920 total
    int co = i & 127, r = i >> 7;                // r = kv*128+ic
    int kv = r >> 7, ic = r & 127;
    g_Wc1[i] = f2tf(w1[(co*H + ic)*5 + kv]);
    g_Wc2[i] = f2tf(w2[(co*H + ic)*5 + kv]);
}

// ===================== LN1 + Bu GEMM (tf32 mma, cp.async db), Bu -> [B][N][T] =======
// 64 rows, 256 threads. smem: sa[64][132] + 2x sw[32][264] = 25344 words
#define SM_LNBU (25344*4)
__global__ void __launch_bounds__(256,2) k_ln_bu(const float* __restrict__ xin,
                        const float* __restrict__ g1, const float* __restrict__ b1v, int l)
{
    extern __shared__ uint32_t smem[];
    uint32_t* sa = smem;            // [64][132]
    uint32_t  sb = (uint32_t)__cvta_generic_to_shared(smem);
    const float* src = xin ? xin : g_x;
    int tid = threadIdx.x, lane = tid&31, warp = tid>>5;
    int gid = lane>>2, tig = lane&3;
    int row0 = blockIdx.x * 64;
    int b = row0 >> 12, t0 = row0 & (T-1);

    // prefetch weight stage 0
    {
        const uint32_t* ws = g_Wbu + (l*H)*256;
        #pragma unroll
        for (int j=0;j<8;j++){
            int f = tid + j*256, row = f>>6, c4 = (f&63)*4;
            cpa16(sb + (8448 + row*264 + c4)*4, ws + row*256 + c4);
        }
        cpcommit();
    }

    // ---- LayerNorm: warp per row, 8 rows per warp ----
    for (int rr = 0; rr < 8; rr++){
        int r = warp*8 + rr;
        int base = (row0 + r) * H;
        float v0 = src[base + lane];
        float v1 = src[base + lane + 32];
        float v2 = src[base + lane + 64];
        float v3 = src[base + lane + 96];
        float s  = v0+v1+v2+v3;
        float sq = v0*v0+v1*v1+v2*v2+v3*v3;
        #pragma unroll
        for (int o=16;o>0;o>>=1){ s += __shfl_xor_sync(FULL,s,o); sq += __shfl_xor_sync(FULL,sq,o); }
        float mu = s * (1.0f/128.0f);
        float var = sq * (1.0f/128.0f) - mu*mu;
        float rstd = rsqrtf(var + 1e-5f);
        float vv[4] = {v0,v1,v2,v3};
        #pragma unroll
        for (int q=0;q<4;q++){
            int h = lane + 32*q;
            float xn = (vv[q] - mu)*rstd * g1[l*H+h] + b1v[l*H+h];
            sa[r*132 + h] = f2tf(xn);
            g_xn[base + h] = xn;
        }
    }

    int wm = (warp>>1)*16, wn = (warp&1)*128;
    float acc[16][4];
    #pragma unroll
    for (int nt=0;nt<16;nt++){ acc[nt][0]=acc[nt][1]=acc[nt][2]=acc[nt][3]=0.f; }

    for (int kc=0; kc<4; kc++){
        cpwait0();
        __syncthreads();
        if (kc < 3){
            const uint32_t* ws = g_Wbu + (l*H + (kc+1)*32)*256;
            uint32_t dst = sb + (8448 + ((kc+1)&1)*8448)*4;
            #pragma unroll
            for (int j=0;j<8;j++){
                int f = tid + j*256, row = f>>6, c4 = (f&63)*4;
                cpa16(dst + (row*264 + c4)*4, ws + row*256 + c4);
            }
            cpcommit();
        }
        uint32_t* sw = smem + 8448 + (kc&1)*8448;
        #pragma unroll
        for (int ks=0; ks<4; ks++){
            int k0 = kc*32 + ks*8, k0w = ks*8;
            uint32_t a0 = sa[(wm+gid)*132   + k0 + tig];
            uint32_t a1 = sa[(wm+gid+8)*132 + k0 + tig];
            uint32_t a2 = sa[(wm+gid)*132   + k0 + tig+4];
            uint32_t a3 = sa[(wm+gid+8)*132 + k0 + tig+4];
            #pragma unroll
            for (int nt=0; nt<16; nt++){
                uint32_t b0 = sw[(k0w+tig)*264   + wn + nt*8 + gid];
                uint32_t b1 = sw[(k0w+tig+4)*264 + wn + nt*8 + gid];
                mma8(acc[nt], a0,a1,a2,a3, b0,b1);
            }
        }
    }
    __syncthreads();
    float* so = (float*)smem;    // [64][257]
    #pragma unroll
    for (int nt=0; nt<16; nt++){
        int n = wn + nt*8 + 2*tig;
        so[(wm+gid)*257 + n]     = acc[nt][0];
        so[(wm+gid)*257 + n+1]   = acc[nt][1];
        so[(wm+gid+8)*257 + n]   = acc[nt][2];
        so[(wm+gid+8)*257 + n+1] = acc[nt][3];
    }
    __syncthreads();
    for (int i=0; i<32; i++){
        int n = warp*32 + i;
        int np = n & 127;
        float* dst = ((n<128) ? g_bur : g_bui) + (b*NS + np)*T + t0;
        dst[lane]    = so[lane*257 + n];
        dst[lane+32] = so[(lane+32)*257 + n];
    }
}

// ---------------- in-place scan over T ----------------
__global__ void k_scan(int l)
{
    __shared__ float s_wr[8], s_wi[8], s_er[8], s_ei[8];
    int bid = blockIdx.x;        // b*NS + n
    int n = bid & (NS-1);
    int tid = threadIdx.x, lane = tid & 31, warp = tid >> 5;
    int base = bid * T + tid * 16;
    float lr = g_lbr[l*NS+n], li = g_lbi[l*NS+n];

    float vr[16], vi[16];
    float4* pr = (float4*)(g_bur + base);
    float4* pi = (float4*)(g_bui + base);
    #pragma unroll
    for (int q=0;q<4;q++){
        float4 a = pr[q]; vr[4*q]=a.x; vr[4*q+1]=a.y; vr[4*q+2]=a.z; vr[4*q+3]=a.w;
        float4 c = pi[q]; vi[4*q]=c.x; vi[4*q+1]=c.y; vi[4*q+2]=c.z; vi[4*q+3]=c.w;
    }
    float sr=0.f, si=0.f;
    #pragma unroll
    for (int i=0;i<16;i++){
        float tr = lr*sr - li*si + vr[i];
        float ti = lr*si + li*sr + vi[i];
        sr=tr; si=ti;
    }
    float cdr[6], cdi[6];
    {
        float pr_=lr, pi_=li;
        #pragma unroll
        for (int q=0;q<4;q++){ float tr = pr_*pr_ - pi_*pi_; pi_ = 2.f*pr_*pi_; pr_ = tr; }
        cdr[0]=pr_; cdi[0]=pi_;
        #pragma unroll
        for (int q=1;q<6;q++){ float tr = cdr[q-1]*cdr[q-1]-cdi[q-1]*cdi[q-1];
                               cdi[q]=2.f*cdr[q-1]*cdi[q-1]; cdr[q]=tr; }
    }
    float xr=sr, xi=si;
    #pragma unroll
    for (int st=0; st<5; st++){
        int d = 1<<st;
        float or_ = __shfl_up_sync(FULL, xr, d);
        float oi_ = __shfl_up_sync(FULL, xi, d);
        if (lane >= d){
            float tr = cdr[st]*or_ - cdi[st]*oi_ + xr;
            xi = cdr[st]*oi_ + cdi[st]*or_ + xi;
            xr = tr;
        }
    }
    if (lane==31){ s_wr[warp]=xr; s_wi[warp]=xi; }
    __syncthreads();
    if (tid==0){
        float er=0.f, ei=0.f;
        #pragma unroll
        for (int w=0;w<8;w++){
            s_er[w]=er; s_ei[w]=ei;
            float tr = cdr[5]*er - cdi[5]*ei + s_wr[w];
            ei = cdr[5]*ei + cdi[5]*er + s_wi[w];
            er = tr;
        }
    }
    __syncthreads();
    float Er = s_er[warp], Ei = s_ei[warp];
    float plr=1.f, pli=0.f;
    #pragma unroll
    for (int bt=0; bt<5; bt++){
        if (lane & (1<<bt)){
            float tr = plr*cdr[bt] - pli*cdi[bt];
            pli = plr*cdi[bt] + pli*cdr[bt];
            plr = tr;
        }
    }
    float car = plr*Er - pli*Ei;
    float cai = plr*Ei + pli*Er;
    float pvr = __shfl_up_sync(FULL, xr, 1);
    float pvi = __shfl_up_sync(FULL, xi, 1);
    if (lane > 0){ car += pvr; cai += pvi; }
    sr = car; si = cai;
    #pragma unroll
    for (int i=0;i<16;i++){
        float tr = lr*sr - li*si + vr[i];
        float ti = lr*si + li*sr + vi[i];
        sr=tr; si=ti;
        vr[i]=sr; vi[i]=si;
    }
    #pragma unroll
    for (int q=0;q<4;q++){
        pr[q] = make_float4(vr[4*q],vr[4*q+1],vr[4*q+2],vr[4*q+3]);
        pi[q] = make_float4(vi[4*q],vi[4*q+1],vi[4*q+2],vi[4*q+3]);
    }
}

// ===================== C-mix GEMM (cp.async db) =====================================
// 64 rows, 256 threads. smem: saT[256][72] + 2x sw[32][136] = 27136 words
#define SM_CMIX (27136*4)
__global__ void __launch_bounds__(256,2) k_cmix(const float* __restrict__ xin,
                                                const float* __restrict__ Dsk, int l)
{
    extern __shared__ uint32_t smem[];
    uint32_t* saT = smem;             // [256][72]
    uint32_t  sb = (uint32_t)__cvta_generic_to_shared(smem);
    int tid = threadIdx.x, lane = tid&31, warp = tid>>5;
    int gid = lane>>2, tig = lane&3;
    int row0 = blockIdx.x * 64;
    int b = row0 >> 12, t0 = row0 & (T-1);

    {   // prefetch Wc stage 0
        const uint32_t* ws = g_Wc + (l*256)*128;
        #pragma unroll
        for (int j=0;j<4;j++){
            int f = tid + j*256, row = f>>5, c4 = (f&31)*4;
            cpa16(sb + (18432 + row*136 + c4)*4, ws + row*128 + c4);
        }
        cpcommit();
    }

    for (int e=tid; e<16384; e+=256){
        int r = e&63, k = e>>6;
        const float* srcp = (k<128) ? (g_bur + (b*NS+k)*T + t0)
                                    : (g_bui + (b*NS + (k-128))*T + t0);
        saT[k*72 + r] = f2tf(srcp[r]);
    }

    int wm = (warp>>1)*16, wn = (warp&1)*64;
    float acc[8][4];
    #pragma unroll
    for (int nt=0;nt<8;nt++){ acc[nt][0]=acc[nt][1]=acc[nt][2]=acc[nt][3]=0.f; }

    for (int kc=0; kc<8; kc++){
        cpwait0();
        __syncthreads();
        if (kc < 7){
            const uint32_t* ws = g_Wc + (l*256 + (kc+1)*32)*128;
            uint32_t dst = sb + (18432 + ((kc+1)&1)*4352)*4;
            #pragma unroll
            for (int j=0;j<4;j++){
                int f = tid + j*256, row = f>>5, c4 = (f&31)*4;
                cpa16(dst + (row*136 + c4)*4, ws + row*128 + c4);
            }
            cpcommit();
        }
        uint32_t* sw = smem + 18432 + (kc&1)*4352;
        #pragma unroll
        for (int ks=0; ks<4; ks++){
            int k0 = kc*32 + ks*8, k0w = ks*8;
            uint32_t a0 = saT[(k0+tig)*72   + wm+gid];
            uint32_t a1 = saT[(k0+tig)*72   + wm+gid+8];
            uint32_t a2 = saT[(k0+tig+4)*72 + wm+gid];
            uint32_t a3 = saT[(k0+tig+4)*72 + wm+gid+8];
            #pragma unroll
            for (int nt=0; nt<8; nt++){
                uint32_t b0 = sw[(k0w+tig)*136   + wn + nt*8 + gid];
                uint32_t b1 = sw[(k0w+tig+4)*136 + wn + nt*8 + gid];
                mma8(acc[nt], a0,a1,a2,a3, b0,b1);
            }
        }
    }
    __syncthreads();
    float* so = (float*)smem;   // [64][132]
    #pragma unroll
    for (int nt=0; nt<8; nt++){
        int n = wn + nt*8 + 2*tig;
        so[(wm+gid)*132 + n]     = acc[nt][0];
        so[(wm+gid)*132 + n+1]   = acc[nt][1];
        so[(wm+gid+8)*132 + n]   = acc[nt][2];
        so[(wm+gid+8)*132 + n+1] = acc[nt][3];
    }
    __syncthreads();
    const float* res = xin ? xin : g_x;
    for (int e=tid; e<8192; e+=256){
        int h = e&127, r = e>>7;
        int gi = (row0+r)*H + h;
        g_x[gi] = res[gi] + so[r*132+h] + g_xn[gi]*Dsk[l*H+h];
    }
}

// ===================== LN2 + MLP (cp.async db) ======================================
// 32 rows, 256 threads. smem: sa[32][132](4224) + wdb(8704) + sh[32][260](8320) = 21248
#define SM_MLP (21248*4)
__global__ void __launch_bounds__(256,2) k_mlp(const float* __restrict__ g2,
                      const float* __restrict__ b2v,
                      const float* __restrict__ b1v, const float* __restrict__ b2o, int l)
{
    extern __shared__ uint32_t smem[];
    uint32_t* sa = smem;                     // [32][132]
    uint32_t* sh = smem + 4224 + 8704;       // [32][260]
    uint32_t  sb = (uint32_t)__cvta_generic_to_shared(smem);
    uint32_t  wb = sb + 4224*4;
    int tid = threadIdx.x, lane = tid&31, warp = tid>>5;
    int gid = lane>>2, tig = lane&3;
    int row0 = blockIdx.x * 32;

    {   // prefetch W1 stage 0 (k-chunk 16)
        const uint32_t* ws = g_W1t + (l*H)*256;
        #pragma unroll
        for (int j=0;j<4;j++){
            int f = tid + j*256, row = f>>6, c4 = (f&63)*4;
            cpa16(wb + (row*264 + c4)*4, ws + row*256 + c4);
        }
        cpcommit();
    }

    // LN2: warp per row, 4 rows each
    for (int rr=0; rr<4; rr++){
        int r = warp*4 + rr;
        int base = (row0+r)*H;
        float v0 = g_x[base + lane];
        float v1 = g_x[base + lane + 32];
        float v2 = g_x[base + lane + 64];
        float v3 = g_x[base + lane + 96];
        float s  = v0+v1+v2+v3;
        float sq = v0*v0+v1*v1+v2*v2+v3*v3;
        #pragma unroll
        for (int o=16;o>0;o>>=1){ s += __shfl_xor_sync(FULL,s,o); sq += __shfl_xor_sync(FULL,sq,o); }
        float mu = s * (1.0f/128.0f);
        float var = sq * (1.0f/128.0f) - mu*mu;
        float rstd = rsqrtf(var + 1e-5f);
        float vv[4] = {v0,v1,v2,v3};
        #pragma unroll
        for (int q=0;q<4;q++){
            int h = lane + 32*q;
            sa[r*132 + h] = f2tf((vv[q] - mu)*rstd * g2[l*H+h] + b2v[l*H+h]);
        }
    }

    // ---- GEMM1: [32x128] @ [128x256], 8 stages of k16 ----
    int wm = (warp>>2)*16, wn = (warp&3)*64;
    float acc[8][4];
    #pragma unroll
    for (int nt=0;nt<8;nt++){ acc[nt][0]=acc[nt][1]=acc[nt][2]=acc[nt][3]=0.f; }
    for (int kc=0; kc<8; kc++){
        cpwait0();
        __syncthreads();
        if (kc < 7){
            const uint32_t* ws = g_W1t + (l*H + (kc+1)*16)*256;
            uint32_t dst = wb + (((kc+1)&1)*4224)*4;
            #pragma unroll
            for (int j=0;j<4;j++){
                int f = tid + j*256, row = f>>6, c4 = (f&63)*4;
                cpa16(dst + (row*264 + c4)*4, ws + row*256 + c4);
            }
            cpcommit();
        }
        uint32_t* sw = smem + 4224 + (kc&1)*4224;
        #pragma unroll
        for (int ks=0; ks<2; ks++){
            int k0 = kc*16 + ks*8, k0w = ks*8;
            uint32_t a0 = sa[(wm+gid)*132   + k0 + tig];
            uint32_t a1 = sa[(wm+gid+8)*132 + k0 + tig];
            uint32_t a2 = sa[(wm+gid)*132   + k0 + tig+4];
            uint32_t a3 = sa[(wm+gid+8)*132 + k0 + tig+4];
            #pragma unroll
            for (int nt=0; nt<8; nt++){
                uint32_t b0 = sw[(k0w+tig)*264   + wn + nt*8 + gid];
                uint32_t b1 = sw[(k0w+tig+4)*264 + wn + nt*8 + gid];
                mma8(acc[nt], a0,a1,a2,a3, b0,b1);
            }
        }
    }
    // prefetch W2 stage 0 (k-chunk 32) -- safe: writes buf0, last GEMM1 read was buf1
    {
        const uint32_t* ws = g_W2t + (l*256)*128;
        #pragma unroll
        for (int j=0;j<4;j++){
            int f = tid + j*256, row = f>>5, c4 = (f&31)*4;
            cpa16(wb + (row*136 + c4)*4, ws + row*128 + c4);
        }
        cpcommit();
    }
    // bias + gelu -> sh
    #pragma unroll
    for (int nt=0; nt<8; nt++){
        int n = wn + nt*8 + 2*tig;
        float bb0 = b1v[l*256 + n], bb1 = b1v[l*256 + n + 1];
        float x0 = acc[nt][0]+bb0, x1 = acc[nt][1]+bb1;
        float x2 = acc[nt][2]+bb0, x3 = acc[nt][3]+bb1;
        sh[(wm+gid)*260 + n]     = f2tf(0.5f*x0*(1.0f+erff(x0*0.70710678118f)));
        sh[(wm+gid)*260 + n+1]   = f2tf(0.5f*x1*(1.0f+erff(x1*0.70710678118f)));
        sh[(wm+gid+8)*260 + n]   = f2tf(0.5f*x2*(1.0f+erff(x2*0.70710678118f)));
        sh[(wm+gid+8)*260 + n+1] = f2tf(0.5f*x3*(1.0f+erff(x3*0.70710678118f)));
    }

    // ---- GEMM2: [32x256] @ [256x128], 8 stages of k32 ----
    int wn2 = (warp&3)*32;
    float acc2[4][4];
    #pragma unroll
    for (int nt=0;nt<4;nt++){ acc2[nt][0]=acc2[nt][1]=acc2[nt][2]=acc2[nt][3]=0.f; }
    for (int kc=0; kc<8; kc++){
        cpwait0();
        __syncthreads();
        if (kc < 7){
            const uint32_t* ws = g_W2t + (l*256 + (kc+1)*32)*128;
            uint32_t dst = wb + (((kc+1)&1)*4352)*4;
            #pragma unroll
            for (int j=0;j<4;j++){
                int f = tid + j*256, row = f>>5, c4 = (f&31)*4;
                cpa16(dst + (row*136 + c4)*4, ws + row*128 + c4);
            }
            cpcommit();
        }
        uint32_t* sw = smem + 4224 + (kc&1)*4352;
        #pragma unroll
        for (int ks=0; ks<4; ks++){
            int k0 = kc*32 + ks*8, k0w = ks*8;
            uint32_t a0 = sh[(wm+gid)*260   + k0 + tig];
            uint32_t a1 = sh[(wm+gid+8)*260 + k0 + tig];
            uint32_t a2 = sh[(wm+gid)*260   + k0 + tig+4];
            uint32_t a3 = sh[(wm+gid+8)*260 + k0 + tig+4];
            #pragma unroll
            for (int nt=0; nt<4; nt++){
                uint32_t b0 = sw[(k0w+tig)*136   + wn2 + nt*8 + gid];
                uint32_t b1 = sw[(k0w+tig+4)*136 + wn2 + nt*8 + gid];
                mma8(acc2[nt], a0,a1,a2,a3, b0,b1);
            }
        }
    }
    __syncthreads();
    float* so = (float*)sa;    // [32][132]
    #pragma unroll
    for (int nt=0; nt<4; nt++){
        int n = wn2 + nt*8 + 2*tig;
        so[(wm+gid)*132 + n]     = acc2[nt][0];
        so[(wm+gid)*132 + n+1]   = acc2[nt][1];
        so[(wm+gid+8)*132 + n]   = acc2[nt][2];
        so[(wm+gid+8)*132 + n+1] = acc2[nt][3];
    }
    __syncthreads();
    for (int e=tid; e<4096; e+=256){
        int h = e&127, r = e>>7;
        int gi = (row0+r)*H + h;
        g_x[gi] = g_x[gi] + so[r*132+h] + b2o[l*H+h];
    }
}

// ===================== conv1 as tf32 GEMM (K=640) ===================================
// 64 out positions x 128 co per block. smem: s_x[131][132](17292) + 2x[32][136](8704)
#define SM_CONV (25996*4)
__global__ void __launch_bounds__(256,2) k_conv1(const float* __restrict__ bc1)
{
    extern __shared__ uint32_t smem[];
    uint32_t* sx = smem;
    uint32_t  sb = (uint32_t)__cvta_generic_to_shared(smem);
    int tid = threadIdx.x, lane = tid&31, warp = tid>>5;
    int gid = lane>>2, tig = lane&3;
    int b = blockIdx.x >> 5;
    int ip0 = (blockIdx.x & 31) * 64;
    int t0 = 2*ip0 - 2;

    {   // prefetch chunk 0
        const uint32_t* ws = g_Wc1;
        #pragma unroll
        for (int j=0;j<4;j++){
            int f = tid + j*256, row = f>>5, c4 = (f&31)*4;
            cpa16(sb + (17292 + row*136 + c4)*4, ws + row*128 + c4);
        }
        cpcommit();
    }
    for (int e=tid; e<131*128; e+=256){
        int t = e>>7, ic = e&127;
        int tg = t0 + t;
        float v = (tg>=0 && tg<T) ? g_x[(b*T+tg)*H + ic] : 0.0f;
        sx[t*132 + ic] = f2tf(v);
    }

    int wm = (warp>>1)*16, wn = (warp&1)*64;
    float acc[8][4];
    #pragma unroll
    for (int nt=0;nt<8;nt++){ acc[nt][0]=acc[nt][1]=acc[nt][2]=acc[nt][3]=0.f; }

    for (int c=0; c<20; c++){
        cpwait0();
        __syncthreads();
        if (c < 19){
            const uint32_t* ws = g_Wc1 + (c+1)*32*128;
            uint32_t dst = sb + (17292 + ((c+1)&1)*4352)*4;
            #pragma unroll
            for (int j=0;j<4;j++){
                int f = tid + j*256, row = f>>5, c4 = (f&31)*4;
                cpa16(dst + (row*136 + c4)*4, ws + row*128 + c4);
            }
            cpcommit();
        }
        uint32_t* sw = smem + 17292 + (c&1)*4352;
        int kv = c>>2, icb = (c&3)*32;
        #pragma unroll
        for (int ks=0; ks<4; ks++){
            int ic0 = icb + ks*8, k0w = ks*8;
            uint32_t a0 = sx[(2*(wm+gid)+kv)*132   + ic0 + tig];
            uint32_t a1 = sx[(2*(wm+gid+8)+kv)*132 + ic0 + tig];
            uint32_t a2 = sx[(2*(wm+gid)+kv)*132   + ic0 + tig+4];
            uint32_t a3 = sx[(2*(wm+gid+8)+kv)*132 + ic0 + tig+4];
            #pragma unroll
            for (int nt=0; nt<8; nt++){
                uint32_t b0 = sw[(k0w+tig)*136   + wn + nt*8 + gid];
                uint32_t b1 = sw[(k0w+tig+4)*136 + wn + nt*8 + gid];
                mma8(acc[nt], a0,a1,a2,a3, b0,b1);
            }
        }
    }
    __syncthreads();
    float* so = (float*)smem;   // [64][132]
    #pragma unroll
    for (int nt=0; nt<8; nt++){
        int n = wn + nt*8 + 2*tig;
        so[(wm+gid)*132 + n]     = acc[nt][0];
        so[(wm+gid)*132 + n+1]   = acc[nt][1];
        so[(wm+gid+8)*132 + n]   = acc[nt][2];
        so[(wm+gid+8)*132 + n+1] = acc[nt][3];
    }
    __syncthreads();
    for (int e=tid; e<8192; e+=256){
        int r = e>>7, co = e&127;
        g_y1[(b*T2 + ip0 + r)*H + co] = fmaxf(so[r*132+co] + bc1[co], 0.0f);
    }
}

// ===================== conv2 as tf32 GEMM + fused pool ==============================
__global__ void __launch_bounds__(256,2) k_conv2pool(const float* __restrict__ bc2,
                                                     float* __restrict__ out)
{
    extern __shared__ uint32_t smem[];
    uint32_t* sx = smem;
    uint32_t  sb = (uint32_t)__cvta_generic_to_shared(smem);
    int tid = threadIdx.x, lane = tid&31, warp = tid>>5;
    int gid = lane>>2, tig = lane&3;
    int b = blockIdx.x >> 4;
    int tile = blockIdx.x & 15;
    int jp0 = tile * 64;
    int t0 = 2*jp0 - 2;

    {
        const uint32_t* ws = g_Wc2;
        #pragma unroll
        for (int j=0;j<4;j++){
            int f = tid + j*256, row = f>>5, c4 = (f&31)*4;
            cpa16(sb + (17292 + row*136 + c4)*4, ws + row*128 + c4);
        }
        cpcommit();
    }
    for (int e=tid; e<131*128; e+=256){
        int t = e>>7, ic = e&127;
        int tg = t0 + t;
        float v = (tg>=0 && tg<T2) ? g_y1[(b*T2+tg)*H + ic] : 0.0f;
        sx[t*132 + ic] = f2tf(v);
    }

    int wm = (warp>>1)*16, wn = (warp&1)*64;
    float acc[8][4];
    #pragma unroll
    for (int nt=0;nt<8;nt++){ acc[nt][0]=acc[nt][1]=acc[nt][2]=acc[nt][3]=0.f; }

    for (int c=0; c<20; c++){
        cpwait0();
        __syncthreads();
        if (c < 19){
            const uint32_t* ws = g_Wc2 + (c+1)*32*128;
            uint32_t dst = sb + (17292 + ((c+1)&1)*4352)*4;
            #pragma unroll
            for (int j=0;j<4;j++){
                int f = tid + j*256, row = f>>5, c4 = (f&31)*4;
                cpa16(dst + (row*136 + c4)*4, ws + row*128 + c4);
            }
            cpcommit();
        }
        uint32_t* sw = smem + 17292 + (c&1)*4352;
        int kv = c>>2, icb = (c&3)*32;
        #pragma unroll
        for (int ks=0; ks<4; ks++){
            int ic0 = icb + ks*8, k0w = ks*8;
            uint32_t a0 = sx[(2*(wm+gid)+kv)*132   + ic0 + tig];
            uint32_t a1 = sx[(2*(wm+gid+8)+kv)*132 + ic0 + tig];
            uint32_t a2 = sx[(2*(wm+gid)+kv)*132   + ic0 + tig+4];
            uint32_t a3 = sx[(2*(wm+gid+8)+kv)*132 + ic0 + tig+4];
            #pragma unroll
            for (int nt=0; nt<8; nt++){
                uint32_t b0 = sw[(k0w+tig)*136   + wn + nt*8 + gid];
                uint32_t b1 = sw[(k0w+tig+4)*136 + wn + nt*8 + gid];
                mma8(acc[nt], a0,a1,a2,a3, b0,b1);
            }
        }
    }
    __syncthreads();
    float* so = (float*)smem;   // [64][132]
    #pragma unroll
    for (int nt=0; nt<8; nt++){
        int n = wn + nt*8 + 2*tig;
        so[(wm+gid)*132 + n]     = acc[nt][0];
        so[(wm+gid)*132 + n+1]   = acc[nt][1];
        so[(wm+gid+8)*132 + n]   = acc[nt][2];
        so[(wm+gid+8)*132 + n+1] = acc[nt][3];
    }
    __syncthreads();
    {
        int co = tid & 127, half = tid >> 7;
        float bias = bc2[co];
        float s0 = 0.f, s1 = 0.f;
        #pragma unroll
        for (int i=0;i<16;i++) s0 += fmaxf(so[(half*32+i)*132+co] + bias, 0.0f);
        #pragma unroll
        for (int i=16;i<32;i++) s1 += fmaxf(so[(half*32+i)*132+co] + bias, 0.0f);
        int d = tile*4 + half*2;
        out[(b*H+co)*DOUT + d]     = s0 * (1.0f/16.0f);
        out[(b*H+co)*DOUT + d + 1] = s1 * (1.0f/16.0f);
    }
}

// ---------------- launch ----------------
extern "C" void kernel_launch(void* const* d_in, const int* in_sizes, int n_in,
                              void* d_out, int out_size)
{
    (void)in_sizes; (void)n_in; (void)out_size;
    const float* x    = (const float*)d_in[0];
    const float* ln1g = (const float*)d_in[1];
    const float* ln1b = (const float*)d_in[2];
    const float* ln2g = (const float*)d_in[3];
    const float* ln2b = (const float*)d_in[4];
    const float* lre  = (const float*)d_in[5];
    const float* lim  = (const float*)d_in[6];
    const float* Bre  = (const float*)d_in[7];
    const float* Bim  = (const float*)d_in[8];
    const float* Cre  = (const float*)d_in[9];
    const float* Cim  = (const float*)d_in[10];
    const float* Dsk  = (const float*)d_in[11];
    const float* lstep= (const float*)d_in[12];
    const float* W1   = (const float*)d_in[13];
    const float* b1   = (const float*)d_in[14];
    const float* W2   = (const float*)d_in[15];
    const float* b2   = (const float*)d_in[16];
    const float* c1w  = (const float*)d_in[17];
    const float* c1b  = (const float*)d_in[18];
    const float* c2w  = (const float*)d_in[19];
    const float* c2b  = (const float*)d_in[20];
    float* out = (float*)d_out;

    cudaFuncSetAttribute(k_ln_bu,     cudaFuncAttributeMaxDynamicSharedMemorySize, SM_LNBU);
    cudaFuncSetAttribute(k_cmix,      cudaFuncAttributeMaxDynamicSharedMemorySize, SM_CMIX);
    cudaFuncSetAttribute(k_mlp,       cudaFuncAttributeMaxDynamicSharedMemorySize, SM_MLP);
    cudaFuncSetAttribute(k_conv1,     cudaFuncAttributeMaxDynamicSharedMemorySize, SM_CONV);
    cudaFuncSetAttribute(k_conv2pool, cudaFuncAttributeMaxDynamicSharedMemorySize, SM_CONV);

    k_prep<<<DEPTH*NS, H>>>(lre, lim, Bre, Bim, lstep);
    k_prepW<<<256, 256>>>(Cre, Cim, W1, W2);
    k_prepConv<<<320, 256>>>(c1w, c2w);
    for (int l=0;l<DEPTH;l++){
        const float* xin = (l==0) ? x : nullptr;
        k_ln_bu<<<TT/64, 256, SM_LNBU>>>(xin, ln1g, ln1b, l);
        k_scan<<<BATCH*NS, 256>>>(l);
        k_cmix<<<TT/64, 256, SM_CMIX>>>(xin, Dsk, l);
        k_mlp<<<TT/32, 256, SM_MLP>>>(ln2g, ln2b, b1, b2, l);
    }
    k_conv1<<<BATCH*32, 256, SM_CONV>>>(c1b);
    k_conv2pool<<<BATCH*16, 256, SM_CONV>>>(c2b, out);
}

// round 9
// speedup vs baseline: 3.3367x; 1.0597x over previous
#include <cuda_runtime.h>
#include <math.h>
#include <stdint.h>

#define BATCH 32
#define T 4096
#define H 128
#define NS 128
#define DEPTH 2
#define TT (BATCH*T)
#define T2 2048
#define DOUT 64
#define FULL 0xFFFFFFFFu

// ---------------- scratch ----------------
__device__ float g_x  [TT*H];
__device__ float g_mu [TT];
__device__ float g_rs [TT];
__device__ float g_bur[BATCH*NS*T];
__device__ float g_bui[BATCH*NS*T];
__device__ float g_y1 [BATCH*T2*H];
__device__ float g_lbr[DEPTH*NS], g_lbi[DEPTH*NS];
// packed (mma-fragment order) tf32 weights
__device__ uint32_t g_WbuP[DEPTH*32768];  // K=128,N=256
__device__ uint32_t g_WcP [DEPTH*32768];  // K=256,N=128
__device__ uint32_t g_W1P [DEPTH*32768];  // K=128,N=256
__device__ uint32_t g_W2P [DEPTH*32768];  // K=256,N=128
__device__ uint32_t g_Wc1P[81920];        // K=640,N=128
__device__ uint32_t g_Wc2P[81920];

// ---------------- helpers ----------------
__device__ __forceinline__ uint32_t f2tf(float x){
    uint32_t u; asm("cvt.rna.tf32.f32 %0, %1;" : "=r"(u) : "f"(x)); return u;
}
__device__ __forceinline__ void mma8(float* c, uint32_t a0,uint32_t a1,uint32_t a2,uint32_t a3,
                                     uint32_t b0,uint32_t b1){
    asm volatile("mma.sync.aligned.m16n8k8.row.col.f32.tf32.tf32.f32 "
        "{%0,%1,%2,%3},{%4,%5,%6,%7},{%8,%9},{%0,%1,%2,%3};"
        : "+f"(c[0]),"+f"(c[1]),"+f"(c[2]),"+f"(c[3])
        : "r"(a0),"r"(a1),"r"(a2),"r"(a3),"r"(b0),"r"(b1));
}
__device__ __forceinline__ void cpa16(uint32_t s, const void* g){
    asm volatile("cp.async.cg.shared.global [%0], [%1], 16;" :: "r"(s), "l"(g));
}
__device__ __forceinline__ void cpcommit(){ asm volatile("cp.async.commit_group;" ::: "memory"); }
__device__ __forceinline__ void cpwait0(){ asm volatile("cp.async.wait_group 0;" ::: "memory"); }

// packed index: within [K][N] matrix, k-chunks of 32, NT = N/8
__device__ __forceinline__ int packIdx(int k, int n, int NT){
    int chunk = k>>5, r5 = k&31;
    int ks = r5>>3, tig = r5&3, p = (r5>>2)&1;
    int row = ks*32 + (n&7)*4 + tig;
    return chunk*(256*NT) + row*(2*NT) + (n>>3)*2 + p;
}

// ---------------- param prep ----------------
__global__ void k_prep(const float* __restrict__ lre, const float* __restrict__ lim,
                       const float* __restrict__ Bre, const float* __restrict__ Bim,
                       const float* __restrict__ lstep)
{
    int idx = blockIdx.x;               // l*NS + n
    int l = idx >> 7, n = idx & 127;
    float lr = lre[idx], li = lim[idx];
    float dt = expf(lstep[idx]);
    float er = expf(lr*dt);
    float lbr = er * cosf(li*dt);
    float lbi = er * sinf(li*dt);
    if (threadIdx.x == 0){ g_lbr[idx]=lbr; g_lbi[idx]=lbi; }
    float den = lr*lr + li*li;
    float nr = lbr - 1.0f, ni = lbi;
    float fr = (nr*lr + ni*li)/den;
    float fi = (ni*lr - nr*li)/den;
    int h = threadIdx.x;
    float br = Bre[idx*H + h], bi = Bim[idx*H + h];
    float wr = fr*br - fi*bi;
    float wi = fr*bi + fi*br;
    g_WbuP[l*32768 + packIdx(h, n,     32)] = f2tf(wr);
    g_WbuP[l*32768 + packIdx(h, n+128, 32)] = f2tf(wi);
}

__global__ void k_prepW(const float* __restrict__ Cre, const float* __restrict__ Cim,
                        const float* __restrict__ W1, const float* __restrict__ W2)
{
    int i = blockIdx.x*256 + threadIdx.x;        // 65536
    int l = i>>15, rem = i&32767;
    {   // Wc: [k(256)][h(128)]
        int k = rem>>7, h = rem&127;
        float v = (k<128) ? 2.0f*Cre[(l*H+h)*NS + k]
                          : -2.0f*Cim[(l*H+h)*NS + (k-128)];
        g_WcP[l*32768 + packIdx(k, h, 16)] = f2tf(v);
    }
    {   // W1: [k(128)][n(256)]
        int k = rem>>8, n = rem&255;
        g_W1P[l*32768 + packIdx(k, n, 32)] = f2tf(W1[i]);
    }
    {   // W2: [k(256)][n(128)]
        int k = rem>>7, n = rem&127;
        g_W2P[l*32768 + packIdx(k, n, 16)] = f2tf(W2[i]);
    }
}

__global__ void k_prepConv(const float* __restrict__ w1, const float* __restrict__ w2)
{
    int i = blockIdx.x*256 + threadIdx.x;        // 81920
    int co = i & 127, r = i >> 7;                // r = kv*128+ic
    int kv = r >> 7, ic = r & 127;
    int k = kv*128 + ic;
    int d = packIdx(k, co, 16);
    g_Wc1P[d] = f2tf(w1[(co*H + ic)*5 + kv]);
    g_Wc2P[d] = f2tf(w2[(co*H + ic)*5 + kv]);
}

// ===================== LN1 + Bu GEMM, Bu -> [B][N][T] ===============================
// 64 rows, 256 threads. smem: sa[64][132]=8448 + 2x wbuf[128][68]=17408 -> 25856 words
#define SM_LNBU (25856*4)
__global__ void __launch_bounds__(256,2) k_ln_bu(const float* __restrict__ xin,
                        const float* __restrict__ g1, const float* __restrict__ b1v, int l)
{
    extern __shared__ uint32_t smem[];
    uint32_t* sa = smem;            // [64][132]
    uint32_t  sb = (uint32_t)__cvta_generic_to_shared(smem);
    const float* src = xin ? xin : g_x;
    int tid = threadIdx.x, lane = tid&31, warp = tid>>5;
    int gid = lane>>2, tig = lane&3;
    int row0 = blockIdx.x * 64;
    int b = row0 >> 12, t0 = row0 & (T-1);

    {   // prefetch chunk 0
        const uint32_t* ws = g_WbuP + l*32768;
        #pragma unroll
        for (int j=0;j<8;j++){
            int f = tid + j*256, row = f>>4, g = (f&15)*4;
            cpa16(sb + (8448 + row*68 + g)*4, ws + row*64 + g);
        }
        cpcommit();
    }

    // ---- LayerNorm ----
    for (int rr = 0; rr < 8; rr++){
        int r = warp*8 + rr;
        int base = (row0 + r) * H;
        float v0 = src[base + lane];
        float v1 = src[base + lane + 32];
        float v2 = src[base + lane + 64];
        float v3 = src[base + lane + 96];
        float s  = v0+v1+v2+v3;
        float sq = v0*v0+v1*v1+v2*v2+v3*v3;
        #pragma unroll
        for (int o=16;o>0;o>>=1){ s += __shfl_xor_sync(FULL,s,o); sq += __shfl_xor_sync(FULL,sq,o); }
        float mu = s * (1.0f/128.0f);
        float var = sq * (1.0f/128.0f) - mu*mu;
        float rstd = rsqrtf(var + 1e-5f);
        if (lane == 0){ g_mu[row0+r] = mu; g_rs[row0+r] = rstd; }
        float vv[4] = {v0,v1,v2,v3};
        #pragma unroll
        for (int q=0;q<4;q++){
            int h = lane + 32*q;
            sa[r*132 + h] = f2tf((vv[q] - mu)*rstd * g1[l*H+h] + b1v[l*H+h]);
        }
    }

    int wm = (warp>>1)*16, wn = (warp&1)*128, wnb = (warp&1)*16;
    float acc[16][4];
    #pragma unroll
    for (int nt=0;nt<16;nt++){ acc[nt][0]=acc[nt][1]=acc[nt][2]=acc[nt][3]=0.f; }

    for (int kc=0; kc<4; kc++){
        cpwait0();
        __syncthreads();
        if (kc < 3){
            const uint32_t* ws = g_WbuP + l*32768 + (kc+1)*8192;
            uint32_t dst = sb + (8448 + ((kc+1)&1)*8704)*4;
            #pragma unroll
            for (int j=0;j<8;j++){
                int f = tid + j*256, row = f>>4, g = (f&15)*4;
                cpa16(dst + (row*68 + g)*4, ws + row*64 + g);
            }
            cpcommit();
        }
        uint32_t* sw = smem + 8448 + (kc&1)*8704;
        #pragma unroll
        for (int ks=0; ks<4; ks++){
            int k0 = kc*32 + ks*8;
            uint32_t a0 = sa[(wm+gid)*132   + k0 + tig];
            uint32_t a1 = sa[(wm+gid+8)*132 + k0 + tig];
            uint32_t a2 = sa[(wm+gid)*132   + k0 + tig+4];
            uint32_t a3 = sa[(wm+gid+8)*132 + k0 + tig+4];
            const uint32_t* bw = sw + (ks*32 + gid*4 + tig)*68 + wnb*2;
            #pragma unroll
            for (int nt0=0; nt0<16; nt0+=2){
                uint4 bv = *(const uint4*)(bw + nt0*2);
                mma8(acc[nt0],   a0,a1,a2,a3, bv.x, bv.y);
                mma8(acc[nt0+1], a0,a1,a2,a3, bv.z, bv.w);
            }
        }
    }
    __syncthreads();
    float* so = (float*)smem;    // [64][257]
    #pragma unroll
    for (int nt=0; nt<16; nt++){
        int n = wn + nt*8 + 2*tig;
        so[(wm+gid)*257 + n]     = acc[nt][0];
        so[(wm+gid)*257 + n+1]   = acc[nt][1];
        so[(wm+gid+8)*257 + n]   = acc[nt][2];
        so[(wm+gid+8)*257 + n+1] = acc[nt][3];
    }
    __syncthreads();
    for (int i=0; i<32; i++){
        int n = warp*32 + i;
        int np = n & 127;
        float* dst = ((n<128) ? g_bur : g_bui) + (b*NS + np)*T + t0;
        dst[lane]    = so[lane*257 + n];
        dst[lane+32] = so[(lane+32)*257 + n];
    }
}

// ---------------- in-place scan over T ----------------
__global__ void k_scan(int l)
{
    __shared__ float s_wr[8], s_wi[8], s_er[8], s_ei[8];
    int bid = blockIdx.x;
    int n = bid & (NS-1);
    int tid = threadIdx.x, lane = tid & 31, warp = tid >> 5;
    int base = bid * T + tid * 16;
    float lr = g_lbr[l*NS+n], li = g_lbi[l*NS+n];

    float vr[16], vi[16];
    float4* pr = (float4*)(g_bur + base);
    float4* pi = (float4*)(g_bui + base);
    #pragma unroll
    for (int q=0;q<4;q++){
        float4 a = pr[q]; vr[4*q]=a.x; vr[4*q+1]=a.y; vr[4*q+2]=a.z; vr[4*q+3]=a.w;
        float4 c = pi[q]; vi[4*q]=c.x; vi[4*q+1]=c.y; vi[4*q+2]=c.z; vi[4*q+3]=c.w;
    }
    float sr=0.f, si=0.f;
    #pragma unroll
    for (int i=0;i<16;i++){
        float tr = lr*sr - li*si + vr[i];
        float ti = lr*si + li*sr + vi[i];
        sr=tr; si=ti;
    }
    float cdr[6], cdi[6];
    {
        float pr_=lr, pi_=li;
        #pragma unroll
        for (int q=0;q<4;q++){ float tr = pr_*pr_ - pi_*pi_; pi_ = 2.f*pr_*pi_; pr_ = tr; }
        cdr[0]=pr_; cdi[0]=pi_;
        #pragma unroll
        for (int q=1;q<6;q++){ float tr = cdr[q-1]*cdr[q-1]-cdi[q-1]*cdi[q-1];
                               cdi[q]=2.f*cdr[q-1]*cdi[q-1]; cdr[q]=tr; }
    }
    float xr=sr, xi=si;
    #pragma unroll
    for (int st=0; st<5; st++){
        int d = 1<<st;
        float or_ = __shfl_up_sync(FULL, xr, d);
        float oi_ = __shfl_up_sync(FULL, xi, d);
        if (lane >= d){
            float tr = cdr[st]*or_ - cdi[st]*oi_ + xr;
            xi = cdr[st]*oi_ + cdi[st]*or_ + xi;
            xr = tr;
        }
    }
    if (lane==31){ s_wr[warp]=xr; s_wi[warp]=xi; }
    __syncthreads();
    if (tid==0){
        float er=0.f, ei=0.f;
        #pragma unroll
        for (int w=0;w<8;w++){
            s_er[w]=er; s_ei[w]=ei;
            float tr = cdr[5]*er - cdi[5]*ei + s_wr[w];
            ei = cdr[5]*ei + cdi[5]*er + s_wi[w];
            er = tr;
        }
    }
    __syncthreads();
    float Er = s_er[warp], Ei = s_ei[warp];
    float plr=1.f, pli=0.f;
    #pragma unroll
    for (int bt=0; bt<5; bt++){
        if (lane & (1<<bt)){
            float tr = plr*cdr[bt] - pli*cdi[bt];
            pli = plr*cdi[bt] + pli*cdr[bt];
            plr = tr;
        }
    }
    float car = plr*Er - pli*Ei;
    float cai = plr*Ei + pli*Er;
    float pvr = __shfl_up_sync(FULL, xr, 1);
    float pvi = __shfl_up_sync(FULL, xi, 1);
    if (lane > 0){ car += pvr; cai += pvi; }
    sr = car; si = cai;
    #pragma unroll
    for (int i=0;i<16;i++){
        float tr = lr*sr - li*si + vr[i];
        float ti = lr*si + li*sr + vi[i];
        sr=tr; si=ti;
        vr[i]=sr; vi[i]=si;
    }
    #pragma unroll
    for (int q=0;q<4;q++){
        pr[q] = make_float4(vr[4*q],vr[4*q+1],vr[4*q+2],vr[4*q+3]);
        pi[q] = make_float4(vi[4*q],vi[4*q+1],vi[4*q+2],vi[4*q+3]);
    }
}

// ===================== C-mix GEMM ===================================================
// 64 rows, 256 threads. smem: saT[256][72]=18432 + 2x[128][36]=9216 -> 27648 words
#define SM_CMIX (27648*4)
__global__ void __launch_bounds__(256,2) k_cmix(const float* __restrict__ xin,
                        const float* __restrict__ Dsk,
                        const float* __restrict__ g1, const float* __restrict__ b1v, int l)
{
    extern __shared__ uint32_t smem[];
    uint32_t* saT = smem;             // [256][72]
    uint32_t  sb = (uint32_t)__cvta_generic_to_shared(smem);
    int tid = threadIdx.x, lane = tid&31, warp = tid>>5;
    int gid = lane>>2, tig = lane&3;
    int row0 = blockIdx.x * 64;
    int b = row0 >> 12, t0 = row0 & (T-1);

    {   // prefetch Wc chunk 0
        const uint32_t* ws = g_WcP + l*32768;
        #pragma unroll
        for (int j=0;j<4;j++){
            int f = tid + j*256, row = f>>3, g = (f&7)*4;
            cpa16(sb + (18432 + row*36 + g)*4, ws + row*32 + g);
        }
        cpcommit();
    }

    for (int e=tid; e<16384; e+=256){
        int r = e&63, k = e>>6;
        const float* srcp = (k<128) ? (g_bur + (b*NS+k)*T + t0)
                                    : (g_bui + (b*NS + (k-128))*T + t0);
        saT[k*72 + r] = f2tf(srcp[r]);
    }

    int wm = (warp>>1)*16, wn = (warp&1)*64, wnb = (warp&1)*8;
    float acc[8][4];
    #pragma unroll
    for (int nt=0;nt<8;nt++){ acc[nt][0]=acc[nt][1]=acc[nt][2]=acc[nt][3]=0.f; }

    for (int kc=0; kc<8; kc++){
        cpwait0();
        __syncthreads();
        if (kc < 7){
            const uint32_t* ws = g_WcP + l*32768 + (kc+1)*4096;
            uint32_t dst = sb + (18432 + ((kc+1)&1)*4608)*4;
            #pragma unroll
            for (int j=0;j<4;j++){
                int f = tid + j*256, row = f>>3, g = (f&7)*4;
                cpa16(dst + (row*36 + g)*4, ws + row*32 + g);
            }
            cpcommit();
        }
        uint32_t* sw = smem + 18432 + (kc&1)*4608;
        #pragma unroll
        for (int ks=0; ks<4; ks++){
            int k0 = kc*32 + ks*8;
            uint32_t a0 = saT[(k0+tig)*72   + wm+gid];
            uint32_t a1 = saT[(k0+tig)*72   + wm+gid+8];
            uint32_t a2 = saT[(k0+tig+4)*72 + wm+gid];
            uint32_t a3 = saT[(k0+tig+4)*72 + wm+gid+8];
            const uint32_t* bw = sw + (ks*32 + gid*4 + tig)*36 + wnb*2;
            #pragma unroll
            for (int nt0=0; nt0<8; nt0+=2){
                uint4 bv = *(const uint4*)(bw + nt0*2);
                mma8(acc[nt0],   a0,a1,a2,a3, bv.x, bv.y);
                mma8(acc[nt0+1], a0,a1,a2,a3, bv.z, bv.w);
            }
        }
    }
    __syncthreads();
    float* so = (float*)smem;   // [64][132]
    #pragma unroll
    for (int nt=0; nt<8; nt++){
        int n = wn + nt*8 + 2*tig;
        so[(wm+gid)*132 + n]     = acc[nt][0];
        so[(wm+gid)*132 + n+1]   = acc[nt][1];
        so[(wm+gid+8)*132 + n]   = acc[nt][2];
        so[(wm+gid+8)*132 + n+1] = acc[nt][3];
    }
    __syncthreads();
    const float* res = xin ? xin : g_x;
    for (int e=tid; e<8192; e+=256){
        int h = e&127, r = e>>7;
        int gi = (row0+r)*H + h;
        float xv = res[gi];
        float xn = (xv - g_mu[row0+r])*g_rs[row0+r]*g1[l*H+h] + b1v[l*H+h];
        g_x[gi] = xv + so[r*132+h] + xn*Dsk[l*H+h];
    }
}

// ===================== LN2 + MLP, M=64, 512 threads =================================
// smem: sa[64][132]=8448 + sh[64][260]=16640 + 2x[128][68]=17408 -> 42496 words
#define SM_MLP (42496*4)
__global__ void __launch_bounds__(512,1) k_mlp(const float* __restrict__ g2,
                      const float* __restrict__ b2v,
                      const float* __restrict__ b1v, const float* __restrict__ b2o, int l)
{
    extern __shared__ uint32_t smem[];
    uint32_t* sa = smem;                     // [64][132]
    uint32_t* sh = smem + 8448;              // [64][260]
    uint32_t  sb = (uint32_t)__cvta_generic_to_shared(smem);
    uint32_t  wb = sb + 25088*4;
    int tid = threadIdx.x, lane = tid&31, warp = tid>>5;
    int gid = lane>>2, tig = lane&3;
    int row0 = blockIdx.x * 64;

    {   // prefetch W1 chunk 0
        const uint32_t* ws = g_W1P + l*32768;
        #pragma unroll
        for (int j=0;j<4;j++){
            int f = tid + j*512, row = f>>4, g = (f&15)*4;
            cpa16(wb + (row*68 + g)*4, ws + row*64 + g);
        }
        cpcommit();
    }

    // LN2: 16 warps x 4 rows
    for (int rr=0; rr<4; rr++){
        int r = warp*4 + rr;
        int base = (row0+r)*H;
        float v0 = g_x[base + lane];
        float v1 = g_x[base + lane + 32];
        float v2 = g_x[base + lane + 64];
        float v3 = g_x[base + lane + 96];
        float s  = v0+v1+v2+v3;
        float sq = v0*v0+v1*v1+v2*v2+v3*v3;
        #pragma unroll
        for (int o=16;o>0;o>>=1){ s += __shfl_xor_sync(FULL,s,o); sq += __shfl_xor_sync(FULL,sq,o); }
        float mu = s * (1.0f/128.0f);
        float var = sq * (1.0f/128.0f) - mu*mu;
        float rstd = rsqrtf(var + 1e-5f);
        float vv[4] = {v0,v1,v2,v3};
        #pragma unroll
        for (int q=0;q<4;q++){
            int h = lane + 32*q;
            sa[r*132 + h] = f2tf((vv[q] - mu)*rstd * g2[l*H+h] + b2v[l*H+h]);
        }
    }

    // ---- GEMM1: [64x128] @ [128x256] ----
    int wm = (warp>>2)*16, wn = (warp&3)*64, wnb = (warp&3)*8;
    float acc[8][4];
    #pragma unroll
    for (int nt=0;nt<8;nt++){ acc[nt][0]=acc[nt][1]=acc[nt][2]=acc[nt][3]=0.f; }
    for (int kc=0; kc<4; kc++){
        cpwait0();
        __syncthreads();
        if (kc < 3){
            const uint32_t* ws = g_W1P + l*32768 + (kc+1)*8192;
            uint32_t dst = wb + (((kc+1)&1)*8704)*4;
            #pragma unroll
            for (int j=0;j<4;j++){
                int f = tid + j*512, row = f>>4, g = (f&15)*4;
                cpa16(dst + (row*68 + g)*4, ws + row*64 + g);
            }
            cpcommit();
        }
        uint32_t* sw = smem + 25088 + (kc&1)*8704;
        #pragma unroll
        for (int ks=0; ks<4; ks++){
            int k0 = kc*32 + ks*8;
            uint32_t a0 = sa[(wm+gid)*132   + k0 + tig];
            uint32_t a1 = sa[(wm+gid+8)*132 + k0 + tig];
            uint32_t a2 = sa[(wm+gid)*132   + k0 + tig+4];
            uint32_t a3 = sa[(wm+gid+8)*132 + k0 + tig+4];
            const uint32_t* bw = sw + (ks*32 + gid*4 + tig)*68 + wnb*2;
            #pragma unroll
            for (int nt0=0; nt0<8; nt0+=2){
                uint4 bv = *(const uint4*)(bw + nt0*2);
                mma8(acc[nt0],   a0,a1,a2,a3, bv.x, bv.y);
                mma8(acc[nt0+1], a0,a1,a2,a3, bv.z, bv.w);
            }
        }
    }
    // prefetch W2 chunk 0 into buf0 (safe: buf0 dead since chunk-3 sync)
    {
        const uint32_t* ws = g_W2P + l*32768;
        #pragma unroll
        for (int j=0;j<2;j++){
            int f = tid + j*512, row = f>>3, g = (f&7)*4;
            cpa16(wb + (row*36 + g)*4, ws + row*32 + g);
        }
        cpcommit();
    }
    // bias + gelu -> sh
    #pragma unroll
    for (int nt=0; nt<8; nt++){
        int n = wn + nt*8 + 2*tig;
        float bb0 = b1v[l*256 + n], bb1 = b1v[l*256 + n + 1];
        float x0 = acc[nt][0]+bb0, x1 = acc[nt][1]+bb1;
        float x2 = acc[nt][2]+bb0, x3 = acc[nt][3]+bb1;
        sh[(wm+gid)*260 + n]     = f2tf(0.5f*x0*(1.0f+erff(x0*0.70710678118f)));
        sh[(wm+gid)*260 + n+1]   = f2tf(0.5f*x1*(1.0f+erff(x1*0.70710678118f)));
        sh[(wm+gid+8)*260 + n]   = f2tf(0.5f*x2*(1.0f+erff(x2*0.70710678118f)));
        sh[(wm+gid+8)*260 + n+1] = f2tf(0.5f*x3*(1.0f+erff(x3*0.70710678118f)));
    }

    // ---- GEMM2: [64x256] @ [256x128] ----
    int wn2 = (warp&3)*32, wnb2 = (warp&3)*4;
    float acc2[4][4];
    #pragma unroll
    for (int nt=0;nt<4;nt++){ acc2[nt][0]=acc2[nt][1]=acc2[nt][2]=acc2[nt][3]=0.f; }
    for (int kc=0; kc<8; kc++){
        cpwait0();
        __syncthreads();
        if (kc < 7){
            const uint32_t* ws = g_W2P + l*32768 + (kc+1)*4096;
            uint32_t dst = wb + (((kc+1)&1)*8704)*4;
            #pragma unroll
            for (int j=0;j<2;j++){
                int f = tid + j*512, row = f>>3, g = (f&7)*4;
                cpa16(dst + (row*36 + g)*4, ws + row*32 + g);
            }
            cpcommit();
        }
        uint32_t* sw = smem + 25088 + (kc&1)*8704;
        #pragma unroll
        for (int ks=0; ks<4; ks++){
            int k0 = kc*32 + ks*8;
            uint32_t a0 = sh[(wm+gid)*260   + k0 + tig];
            uint32_t a1 = sh[(wm+gid+8)*260 + k0 + tig];
            uint32_t a2 = sh[(wm+gid)*260   + k0 + tig+4];
            uint32_t a3 = sh[(wm+gid+8)*260 + k0 + tig+4];
            const uint32_t* bw = sw + (ks*32 + gid*4 + tig)*36 + wnb2*2;
            #pragma unroll
            for (int nt0=0; nt0<4; nt0+=2){
                uint4 bv = *(const uint4*)(bw + nt0*2);
                mma8(acc2[nt0],   a0,a1,a2,a3, bv.x, bv.y);
                mma8(acc2[nt0+1], a0,a1,a2,a3, bv.z, bv.w);
            }
        }
    }
    __syncthreads();
    float* so = (float*)sa;    // [64][132]
    #pragma unroll
    for (int nt=0; nt<4; nt++){
        int n = wn2 + nt*8 + 2*tig;
        so[(wm+gid)*132 + n]     = acc2[nt][0];
        so[(wm+gid)*132 + n+1]   = acc2[nt][1];
        so[(wm+gid+8)*132 + n]   = acc2[nt][2];
        so[(wm+gid+8)*132 + n+1] = acc2[nt][3];
    }
    __syncthreads();
    for (int e=tid; e<8192; e+=512){
        int h = e&127, r = e>>7;
        int gi = (row0+r)*H + h;
        g_x[gi] = g_x[gi] + so[r*132+h] + b2o[l*H+h];
    }
}

// ===================== conv1 as tf32 GEMM (K=640) ===================================
// smem: sx[131][132]=17292 + 2x[128][36]=9216 -> 26508 words
#define SM_CONV (26508*4)
__global__ void __launch_bounds__(256,2) k_conv1(const float* __restrict__ bc1)
{
    extern __shared__ uint32_t smem[];
    uint32_t* sx = smem;
    uint32_t  sb = (uint32_t)__cvta_generic_to_shared(smem);
    int tid = threadIdx.x, lane = tid&31, warp = tid>>5;
    int gid = lane>>2, tig = lane&3;
    int b = blockIdx.x >> 5;
    int ip0 = (blockIdx.x & 31) * 64;
    int t0 = 2*ip0 - 2;

    {
        const uint32_t* ws = g_Wc1P;
        #pragma unroll
        for (int j=0;j<4;j++){
            int f = tid + j*256, row = f>>3, g = (f&7)*4;
            cpa16(sb + (17292 + row*36 + g)*4, ws + row*32 + g);
        }
        cpcommit();
    }
    for (int e=tid; e<131*128; e+=256){
        int t = e>>7, ic = e&127;
        int tg = t0 + t;
        float v = (tg>=0 && tg<T) ? g_x[(b*T+tg)*H + ic] : 0.0f;
        sx[t*132 + ic] = f2tf(v);
    }

    int wm = (warp>>1)*16, wn = (warp&1)*64, wnb = (warp&1)*8;
    float acc[8][4];
    #pragma unroll
    for (int nt=0;nt<8;nt++){ acc[nt][0]=acc[nt][1]=acc[nt][2]=acc[nt][3]=0.f; }

    for (int c=0; c<20; c++){
        cpwait0();
        __syncthreads();
        if (c < 19){
            const uint32_t* ws = g_Wc1P + (c+1)*4096;
            uint32_t dst = sb + (17292 + ((c+1)&1)*4608)*4;
            #pragma unroll
            for (int j=0;j<4;j++){
                int f = tid + j*256, row = f>>3, g = (f&7)*4;
                cpa16(dst + (row*36 + g)*4, ws + row*32 + g);
            }
            cpcommit();
        }
        uint32_t* sw = smem + 17292 + (c&1)*4608;
        int kv = c>>2, icb = (c&3)*32;
        #pragma unroll
        for (int ks=0; ks<4; ks++){
            int ic0 = icb + ks*8;
            uint32_t a0 = sx[(2*(wm+gid)+kv)*132   + ic0 + tig];
            uint32_t a1 = sx[(2*(wm+gid+8)+kv)*132 + ic0 + tig];
            uint32_t a2 = sx[(2*(wm+gid)+kv)*132   + ic0 + tig+4];
            uint32_t a3 = sx[(2*(wm+gid+8)+kv)*132 + ic0 + tig+4];
            const uint32_t* bw = sw + (ks*32 + gid*4 + tig)*36 + wnb*2;
            #pragma unroll
            for (int nt0=0; nt0<8; nt0+=2){
                uint4 bv = *(const uint4*)(bw + nt0*2);
                mma8(acc[nt0],   a0,a1,a2,a3, bv.x, bv.y);
                mma8(acc[nt0+1], a0,a1,a2,a3, bv.z, bv.w);
            }
        }
    }
    __syncthreads();
    float* so = (float*)smem;   // [64][132]
    #pragma unroll
    for (int nt=0; nt<8; nt++){
        int n = wn + nt*8 + 2*tig;
        so[(wm+gid)*132 + n]     = acc[nt][0];
        so[(wm+gid)*132 + n+1]   = acc[nt][1];
        so[(wm+gid+8)*132 + n]   = acc[nt][2];
        so[(wm+gid+8)*132 + n+1] = acc[nt][3];
    }
    __syncthreads();
    for (int e=tid; e<8192; e+=256){
        int r = e>>7, co = e&127;
        g_y1[(b*T2 + ip0 + r)*H + co] = fmaxf(so[r*132+co] + bc1[co], 0.0f);
    }
}

// ===================== conv2 + fused pool ===========================================
__global__ void __launch_bounds__(256,2) k_conv2pool(const float* __restrict__ bc2,
                                                     float* __restrict__ out)
{
    extern __shared__ uint32_t smem[];
    uint32_t* sx = smem;
    uint32_t  sb = (uint32_t)__cvta_generic_to_shared(smem);
    int tid = threadIdx.x, lane = tid&31, warp = tid>>5;
    int gid = lane>>2, tig = lane&3;
    int b = blockIdx.x >> 4;
    int tile = blockIdx.x & 15;
    int jp0 = tile * 64;
    int t0 = 2*jp0 - 2;

    {
        const uint32_t* ws = g_Wc2P;
        #pragma unroll
        for (int j=0;j<4;j++){
            int f = tid + j*256, row = f>>3, g = (f&7)*4;
            cpa16(sb + (17292 + row*36 + g)*4, ws + row*32 + g);
        }
        cpcommit();
    }
    for (int e=tid; e<131*128; e+=256){
        int t = e>>7, ic = e&127;
        int tg = t0 + t;
        float v = (tg>=0 && tg<T2) ? g_y1[(b*T2+tg)*H + ic] : 0.0f;
        sx[t*132 + ic] = f2tf(v);
    }

    int wm = (warp>>1)*16, wn = (warp&1)*64, wnb = (warp&1)*8;
    float acc[8][4];
    #pragma unroll
    for (int nt=0;nt<8;nt++){ acc[nt][0]=acc[nt][1]=acc[nt][2]=acc[nt][3]=0.f; }

    for (int c=0; c<20; c++){
        cpwait0();
        __syncthreads();
        if (c < 19){
            const uint32_t* ws = g_Wc2P + (c+1)*4096;
            uint32_t dst = sb + (17292 + ((c+1)&1)*4608)*4;
            #pragma unroll
            for (int j=0;j<4;j++){
                int f = tid + j*256, row = f>>3, g = (f&7)*4;
                cpa16(dst + (row*36 + g)*4, ws + row*32 + g);
            }
            cpcommit();
        }
        uint32_t* sw = smem + 17292 + (c&1)*4608;
        int kv = c>>2, icb = (c&3)*32;
        #pragma unroll
        for (int ks=0; ks<4; ks++){
            int ic0 = icb + ks*8;
            uint32_t a0 = sx[(2*(wm+gid)+kv)*132   + ic0 + tig];
            uint32_t a1 = sx[(2*(wm+gid+8)+kv)*132 + ic0 + tig];
            uint32_t a2 = sx[(2*(wm+gid)+kv)*132   + ic0 + tig+4];
            uint32_t a3 = sx[(2*(wm+gid+8)+kv)*132 + ic0 + tig+4];
            const uint32_t* bw = sw + (ks*32 + gid*4 + tig)*36 + wnb*2;
            #pragma unroll
            for (int nt0=0; nt0<8; nt0+=2){
                uint4 bv = *(const uint4*)(bw + nt0*2);
                mma8(acc[nt0],   a0,a1,a2,a3, bv.x, bv.y);
                mma8(acc[nt0+1], a0,a1,a2,a3, bv.z, bv.w);
            }
        }
    }
    __syncthreads();
    float* so = (float*)smem;   // [64][132]
    #pragma unroll
    for (int nt=0; nt<8; nt++){
        int n = wn + nt*8 + 2*tig;
        so[(wm+gid)*132 + n]     = acc[nt][0];
        so[(wm+gid)*132 + n+1]   = acc[nt][1];
        so[(wm+gid+8)*132 + n]   = acc[nt][2];
        so[(wm+gid+8)*132 + n+1] = acc[nt][3];
    }
    __syncthreads();
    {
        int co = tid & 127, half = tid >> 7;
        float bias = bc2[co];
        float s0 = 0.f, s1 = 0.f;
        #pragma unroll
        for (int i=0;i<16;i++) s0 += fmaxf(so[(half*32+i)*132+co] + bias, 0.0f);
        #pragma unroll
        for (int i=16;i<32;i++) s1 += fmaxf(so[(half*32+i)*132+co] + bias, 0.0f);
        int d = tile*4 + half*2;
        out[(b*H+co)*DOUT + d]     = s0 * (1.0f/16.0f);
        out[(b*H+co)*DOUT + d + 1] = s1 * (1.0f/16.0f);
    }
}

// ---------------- launch ----------------
extern "C" void kernel_launch(void* const* d_in, const int* in_sizes, int n_in,
                              void* d_out, int out_size)
{
    (void)in_sizes; (void)n_in; (void)out_size;
    const float* x    = (const float*)d_in[0];
    const float* ln1g = (const float*)d_in[1];
    const float* ln1b = (const float*)d_in[2];
    const float* ln2g = (const float*)d_in[3];
    const float* ln2b = (const float*)d_in[4];
    const float* lre  = (const float*)d_in[5];
    const float* lim  = (const float*)d_in[6];
    const float* Bre  = (const float*)d_in[7];
    const float* Bim  = (const float*)d_in[8];
    const float* Cre  = (const float*)d_in[9];
    const float* Cim  = (const float*)d_in[10];
    const float* Dsk  = (const float*)d_in[11];
    const float* lstep= (const float*)d_in[12];
    const float* W1   = (const float*)d_in[13];
    const float* b1   = (const float*)d_in[14];
    const float* W2   = (const float*)d_in[15];
    const float* b2   = (const float*)d_in[16];
    const float* c1w  = (const float*)d_in[17];
    const float* c1b  = (const float*)d_in[18];
    const float* c2w  = (const float*)d_in[19];
    const float* c2b  = (const float*)d_in[20];
    float* out = (float*)d_out;

    cudaFuncSetAttribute(k_ln_bu,     cudaFuncAttributeMaxDynamicSharedMemorySize, SM_LNBU);
    cudaFuncSetAttribute(k_cmix,      cudaFuncAttributeMaxDynamicSharedMemorySize, SM_CMIX);
    cudaFuncSetAttribute(k_mlp,       cudaFuncAttributeMaxDynamicSharedMemorySize, SM_MLP);
    cudaFuncSetAttribute(k_conv1,     cudaFuncAttributeMaxDynamicSharedMemorySize, SM_CONV);
    cudaFuncSetAttribute(k_conv2pool, cudaFuncAttributeMaxDynamicSharedMemorySize, SM_CONV);

    k_prep<<<DEPTH*NS, H>>>(lre, lim, Bre, Bim, lstep);
    k_prepW<<<256, 256>>>(Cre, Cim, W1, W2);
    k_prepConv<<<320, 256>>>(c1w, c2w);
    for (int l=0;l<DEPTH;l++){
        const float* xin = (l==0) ? x : nullptr;
        k_ln_bu<<<TT/64, 256, SM_LNBU>>>(xin, ln1g, ln1b, l);
        k_scan<<<BATCH*NS, 256>>>(l);
        k_cmix<<<TT/64, 256, SM_CMIX>>>(xin, Dsk, ln1g, ln1b, l);
        k_mlp<<<TT/64, 512, SM_MLP>>>(ln2g, ln2b, b1, b2, l);
    }
    k_conv1<<<BATCH*32, 256, SM_CONV>>>(c1b);
    k_conv2pool<<<BATCH*16, 256, SM_CONV>>>(c2b, out);
}

// round 12
// speedup vs baseline: 3.4057x; 1.0207x over previous
#include <cuda_runtime.h>
#include <math.h>
#include <stdint.h>

#define BATCH 32
#define T 4096
#define H 128
#define NS 128
#define DEPTH 2
#define TT (BATCH*T)
#define T2 2048
#define DOUT 64
#define FULL 0xFFFFFFFFu

// ---------------- scratch ----------------
__device__ float g_x  [TT*H];
__device__ float g_mu [TT];
__device__ float g_rs [TT];
__device__ float g_bur[BATCH*NS*T];
__device__ float g_bui[BATCH*NS*T];
__device__ float g_y1 [BATCH*T2*H];
__device__ float g_lbr[DEPTH*NS], g_lbi[DEPTH*NS];
// packed (mma-fragment order) tf32 weights
__device__ uint32_t g_WbuP[DEPTH*32768];  // K=128,N=256
__device__ uint32_t g_WcP [DEPTH*32768];  // K=256,N=128
__device__ uint32_t g_W1P [DEPTH*32768];  // K=128,N=256
__device__ uint32_t g_W2P [DEPTH*32768];  // K=256,N=128
__device__ uint32_t g_Wc1P[81920];        // K=640,N=128
__device__ uint32_t g_Wc2P[81920];

// ---------------- helpers ----------------
__device__ __forceinline__ uint32_t f2tf(float x){
    uint32_t u; asm("cvt.rna.tf32.f32 %0, %1;" : "=r"(u) : "f"(x)); return u;
}
__device__ __forceinline__ void mma8(float* c, uint32_t a0,uint32_t a1,uint32_t a2,uint32_t a3,
                                     uint32_t b0,uint32_t b1){
    asm volatile("mma.sync.aligned.m16n8k8.row.col.f32.tf32.tf32.f32 "
        "{%0,%1,%2,%3},{%4,%5,%6,%7},{%8,%9},{%0,%1,%2,%3};"
        : "+f"(c[0]),"+f"(c[1]),"+f"(c[2]),"+f"(c[3])
        : "r"(a0),"r"(a1),"r"(a2),"r"(a3),"r"(b0),"r"(b1));
}
__device__ __forceinline__ void cpa16(uint32_t s, const void* g){
    asm volatile("cp.async.cg.shared.global [%0], [%1], 16;" :: "r"(s), "l"(g));
}
__device__ __forceinline__ void cpcommit(){ asm volatile("cp.async.commit_group;" ::: "memory"); }
__device__ __forceinline__ void cpwait0(){ asm volatile("cp.async.wait_group 0;" ::: "memory"); }

// packed index: within [K][N] matrix, k-chunks of 32, NT = N/8
__device__ __forceinline__ int packIdx(int k, int n, int NT){
    int chunk = k>>5, r5 = k&31;
    int ks = r5>>3, tig = r5&3;
    int row = ks*32 + (n&7)*4 + tig;
    int p = (r5>>2)&1;
    return chunk*(256*NT) + row*(2*NT) + (n>>3)*2 + p;
}

// ---------------- param prep ----------------
__global__ void k_prep(const float* __restrict__ lre, const float* __restrict__ lim,
                       const float* __restrict__ Bre, const float* __restrict__ Bim,
                       const float* __restrict__ lstep)
{
    int idx = blockIdx.x;               // l*NS + n
    int l = idx >> 7, n = idx & 127;
    float lr = lre[idx], li = lim[idx];
    float dt = expf(lstep[idx]);
    float er = expf(lr*dt);
    float lbr = er * cosf(li*dt);
    float lbi = er * sinf(li*dt);
    if (threadIdx.x == 0){ g_lbr[idx]=lbr; g_lbi[idx]=lbi; }
    float den = lr*lr + li*li;
    float nr = lbr - 1.0f, ni = lbi;
    float fr = (nr*lr + ni*li)/den;
    float fi = (ni*lr - nr*li)/den;
    int h = threadIdx.x;
    float br = Bre[idx*H + h], bi = Bim[idx*H + h];
    float wr = fr*br - fi*bi;
    float wi = fr*bi + fi*br;
    g_WbuP[l*32768 + packIdx(h, n,     32)] = f2tf(wr);
    g_WbuP[l*32768 + packIdx(h, n+128, 32)] = f2tf(wi);
}

__global__ void k_prepW(const float* __restrict__ Cre, const float* __restrict__ Cim,
                        const float* __restrict__ W1, const float* __restrict__ W2)
{
    int i = blockIdx.x*256 + threadIdx.x;        // 65536
    int l = i>>15, rem = i&32767;
    {   // Wc: [k(256)][h(128)]
        int k = rem>>7, h = rem&127;
        float v = (k<128) ? 2.0f*Cre[(l*H+h)*NS + k]
                          : -2.0f*Cim[(l*H+h)*NS + (k-128)];
        g_WcP[l*32768 + packIdx(k, h, 16)] = f2tf(v);
    }
    {   // W1: [k(128)][n(256)]
        int k = rem>>8, n = rem&255;
        g_W1P[l*32768 + packIdx(k, n, 32)] = f2tf(W1[i]);
    }
    {   // W2: [k(256)][n(128)]
        int k = rem>>7, n = rem&127;
        g_W2P[l*32768 + packIdx(k, n, 16)] = f2tf(W2[i]);
    }
}

__global__ void k_prepConv(const float* __restrict__ w1, const float* __restrict__ w2)
{
    int i = blockIdx.x*256 + threadIdx.x;        // 81920
    int co = i & 127, r = i >> 7;                // r = kv*128+ic
    int kv = r >> 7, ic = r & 127;
    int k = kv*128 + ic;
    int d = packIdx(k, co, 16);
    g_Wc1P[d] = f2tf(w1[(co*H + ic)*5 + kv]);
    g_Wc2P[d] = f2tf(w2[(co*H + ic)*5 + kv]);
}

// ===================== LN1 + Bu GEMM, Bu -> [B][N][T] ===============================
// 64 rows, 512 threads (16 warps, warp tile 16x64).
// smem: sa[64][132]=8448 + 2x wbuf[128][68]=17408 -> 25856 words
#define SM_LNBU (25856*4)
__global__ void __launch_bounds__(512,2) k_ln_bu(const float* __restrict__ xin,
                        const float* __restrict__ g1, const float* __restrict__ b1v, int l)
{
    extern __shared__ uint32_t smem[];
    uint32_t* sa = smem;            // [64][132]
    uint32_t  sb = (uint32_t)__cvta_generic_to_shared(smem);
    const float* src = xin ? xin : g_x;
    int tid = threadIdx.x, lane = tid&31, warp = tid>>5;
    int gid = lane>>2, tig = lane&3;
    int row0 = blockIdx.x * 64;
    int b = row0 >> 12, t0 = row0 & (T-1);

    {   // prefetch chunk 0 (8192 words)
        const uint32_t* ws = g_WbuP + l*32768;
        #pragma unroll
        for (int j=0;j<4;j++){
            int f = tid + j*512, row = f>>4, g = (f&15)*4;
            cpa16(sb + (8448 + row*68 + g)*4, ws + row*64 + g);
        }
        cpcommit();
    }

    // ---- LayerNorm: 16 warps x 4 rows ----
    for (int rr = 0; rr < 4; rr++){
        int r = warp*4 + rr;
        int base = (row0 + r) * H;
        float v0 = src[base + lane];
        float v1 = src[base + lane + 32];
        float v2 = src[base + lane + 64];
        float v3 = src[base + lane + 96];
        float s  = v0+v1+v2+v3;
        float sq = v0*v0+v1*v1+v2*v2+v3*v3;
        #pragma unroll
        for (int o=16;o>0;o>>=1){ s += __shfl_xor_sync(FULL,s,o); sq += __shfl_xor_sync(FULL,sq,o); }
        float mu = s * (1.0f/128.0f);
        float var = sq * (1.0f/128.0f) - mu*mu;
        float rstd = rsqrtf(var + 1e-5f);
        if (lane == 0){ g_mu[row0+r] = mu; g_rs[row0+r] = rstd; }
        float vv[4] = {v0,v1,v2,v3};
        #pragma unroll
        for (int q=0;q<4;q++){
            int h = lane + 32*q;
            sa[r*132 + h] = f2tf((vv[q] - mu)*rstd * g1[l*H+h] + b1v[l*H+h]);
        }
    }

    int wm = (warp>>2)*16, wn = (warp&3)*64, wnb = (warp&3)*8;
    float acc[8][4];
    #pragma unroll
    for (int nt=0;nt<8;nt++){ acc[nt][0]=acc[nt][1]=acc[nt][2]=acc[nt][3]=0.f; }

    for (int kc=0; kc<4; kc++){
        cpwait0();
        __syncthreads();
        if (kc < 3){
            const uint32_t* ws = g_WbuP + l*32768 + (kc+1)*8192;
            uint32_t dst = sb + (8448 + ((kc+1)&1)*8704)*4;
            #pragma unroll
            for (int j=0;j<4;j++){
                int f = tid + j*512, row = f>>4, g = (f&15)*4;
                cpa16(dst + (row*68 + g)*4, ws + row*64 + g);
            }
            cpcommit();
        }
        uint32_t* sw = smem + 8448 + (kc&1)*8704;
        #pragma unroll
        for (int ks=0; ks<4; ks++){
            int k0 = kc*32 + ks*8;
            uint32_t a0 = sa[(wm+gid)*132   + k0 + tig];
            uint32_t a1 = sa[(wm+gid+8)*132 + k0 + tig];
            uint32_t a2 = sa[(wm+gid)*132   + k0 + tig+4];
            uint32_t a3 = sa[(wm+gid+8)*132 + k0 + tig+4];
            const uint32_t* bw = sw + (ks*32 + gid*4 + tig)*68 + wnb*2;
            #pragma unroll
            for (int nt0=0; nt0<8; nt0+=2){
                uint4 bv = *(const uint4*)(bw + nt0*2);
                mma8(acc[nt0],   a0,a1,a2,a3, bv.x, bv.y);
                mma8(acc[nt0+1], a0,a1,a2,a3, bv.z, bv.w);
            }
        }
    }
    __syncthreads();
    float* so = (float*)smem;    // [64][257]
    #pragma unroll
    for (int nt=0; nt<8; nt++){
        int n = wn + nt*8 + 2*tig;
        so[(wm+gid)*257 + n]     = acc[nt][0];
        so[(wm+gid)*257 + n+1]   = acc[nt][1];
        so[(wm+gid+8)*257 + n]   = acc[nt][2];
        so[(wm+gid+8)*257 + n+1] = acc[nt][3];
    }
    __syncthreads();
    for (int i=0; i<16; i++){
        int n = warp*16 + i;
        int np = n & 127;
        float* dst = ((n<128) ? g_bur : g_bui) + (b*NS + np)*T + t0;
        dst[lane]    = so[lane*257 + n];
        dst[lane+32] = so[(lane+32)*257 + n];
    }
}

// ---------------- in-place scan over T ----------------
__global__ void k_scan(int l)
{
    __shared__ float s_wr[8], s_wi[8], s_er[8], s_ei[8];
    int bid = blockIdx.x;
    int n = bid & (NS-1);
    int tid = threadIdx.x, lane = tid & 31, warp = tid >> 5;
    int base = bid * T + tid * 16;
    float lr = g_lbr[l*NS+n], li = g_lbi[l*NS+n];

    float vr[16], vi[16];
    float4* pr = (float4*)(g_bur + base);
    float4* pi = (float4*)(g_bui + base);
    #pragma unroll
    for (int q=0;q<4;q++){
        float4 a = pr[q]; vr[4*q]=a.x; vr[4*q+1]=a.y; vr[4*q+2]=a.z; vr[4*q+3]=a.w;
        float4 c = pi[q]; vi[4*q]=c.x; vi[4*q+1]=c.y; vi[4*q+2]=c.z; vi[4*q+3]=c.w;
    }
    float sr=0.f, si=0.f;
    #pragma unroll
    for (int i=0;i<16;i++){
        float tr = lr*sr - li*si + vr[i];
        float ti = lr*si + li*sr + vi[i];
        sr=tr; si=ti;
    }
    float cdr[6], cdi[6];
    {
        float pr_=lr, pi_=li;
        #pragma unroll
        for (int q=0;q<4;q++){ float tr = pr_*pr_ - pi_*pi_; pi_ = 2.f*pr_*pi_; pr_ = tr; }
        cdr[0]=pr_; cdi[0]=pi_;
        #pragma unroll
        for (int q=1;q<6;q++){ float tr = cdr[q-1]*cdr[q-1]-cdi[q-1]*cdi[q-1];
                               cdi[q]=2.f*cdr[q-1]*cdi[q-1]; cdr[q]=tr; }
    }
    float xr=sr, xi=si;
    #pragma unroll
    for (int st=0; st<5; st++){
        int d = 1<<st;
        float or_ = __shfl_up_sync(FULL, xr, d);
        float oi_ = __shfl_up_sync(FULL, xi, d);
        if (lane >= d){
            float tr = cdr[st]*or_ - cdi[st]*oi_ + xr;
            xi = cdr[st]*oi_ + cdi[st]*or_ + xi;
            xr = tr;
        }
    }
    if (lane==31){ s_wr[warp]=xr; s_wi[warp]=xi; }
    __syncthreads();
    if (tid==0){
        float er=0.f, ei=0.f;
        #pragma unroll
        for (int w=0;w<8;w++){
            s_er[w]=er; s_ei[w]=ei;
            float tr = cdr[5]*er - cdi[5]*ei + s_wr[w];
            ei = cdr[5]*ei + cdi[5]*er + s_wi[w];
            er = tr;
        }
    }
    __syncthreads();
    float Er = s_er[warp], Ei = s_ei[warp];
    float plr=1.f, pli=0.f;
    #pragma unroll
    for (int bt=0; bt<5; bt++){
        if (lane & (1<<bt)){
            float tr = plr*cdr[bt] - pli*cdi[bt];
            pli = plr*cdi[bt] + pli*cdr[bt];
            plr = tr;
        }
    }
    float car = plr*Er - pli*Ei;
    float cai = plr*Ei + pli*Er;
    float pvr = __shfl_up_sync(FULL, xr, 1);
    float pvi = __shfl_up_sync(FULL, xi, 1);
    if (lane > 0){ car += pvr; cai += pvi; }
    sr = car; si = cai;
    #pragma unroll
    for (int i=0;i<16;i++){
        float tr = lr*sr - li*si + vr[i];
        float ti = lr*si + li*sr + vi[i];
        sr=tr; si=ti;
        vr[i]=sr; vi[i]=si;
    }
    #pragma unroll
    for (int q=0;q<4;q++){
        pr[q] = make_float4(vr[4*q],vr[4*q+1],vr[4*q+2],vr[4*q+3]);
        pi[q] = make_float4(vi[4*q],vi[4*q+1],vi[4*q+2],vi[4*q+3]);
    }
}

// ===================== C-mix GEMM ===================================================
// 64 rows, 256 threads. smem: saT[256][72]=18432 + 2x[128][36]=9216 -> 27648 words
#define SM_CMIX (27648*4)
__global__ void __launch_bounds__(256,2) k_cmix(const float* __restrict__ xin,
                        const float* __restrict__ Dsk,
                        const float* __restrict__ g1, const float* __restrict__ b1v, int l)
{
    extern __shared__ uint32_t smem[];
    uint32_t* saT = smem;             // [256][72]
    uint32_t  sb = (uint32_t)__cvta_generic_to_shared(smem);
    int tid = threadIdx.x, lane = tid&31, warp = tid>>5;
    int gid = lane>>2, tig = lane&3;
    int row0 = blockIdx.x * 64;
    int b = row0 >> 12, t0 = row0 & (T-1);

    {   // prefetch Wc chunk 0
        const uint32_t* ws = g_WcP + l*32768;
        #pragma unroll
        for (int j=0;j<4;j++){
            int f = tid + j*256, row = f>>3, g = (f&7)*4;
            cpa16(sb + (18432 + row*36 + g)*4, ws + row*32 + g);
        }
        cpcommit();
    }

    for (int e=tid; e<16384; e+=256){
        int r = e&63, k = e>>6;
        const float* srcp = (k<128) ? (g_bur + (b*NS+k)*T + t0)
                                    : (g_bui + (b*NS + (k-128))*T + t0);
        saT[k*72 + r] = f2tf(srcp[r]);
    }

    int wm = (warp>>1)*16, wn = (warp&1)*64, wnb = (warp&1)*8;
    float acc[8][4];
    #pragma unroll
    for (int nt=0;nt<8;nt++){ acc[nt][0]=acc[nt][1]=acc[nt][2]=acc[nt][3]=0.f; }

    for (int kc=0; kc<8; kc++){
        cpwait0();
        __syncthreads();
        if (kc < 7){
            const uint32_t* ws = g_WcP + l*32768 + (kc+1)*4096;
            uint32_t dst = sb + (18432 + ((kc+1)&1)*4608)*4;
            #pragma unroll
            for (int j=0;j<4;j++){
                int f = tid + j*256, row = f>>3, g = (f&7)*4;
                cpa16(dst + (row*36 + g)*4, ws + row*32 + g);
            }
            cpcommit();
        }
        uint32_t* sw = smem + 18432 + (kc&1)*4608;
        #pragma unroll
        for (int ks=0; ks<4; ks++){
            int k0 = kc*32 + ks*8;
            uint32_t a0 = saT[(k0+tig)*72   + wm+gid];
            uint32_t a1 = saT[(k0+tig)*72   + wm+gid+8];
            uint32_t a2 = saT[(k0+tig+4)*72 + wm+gid];
            uint32_t a3 = saT[(k0+tig+4)*72 + wm+gid+8];
            const uint32_t* bw = sw + (ks*32 + gid*4 + tig)*36 + wnb*2;
            #pragma unroll
            for (int nt0=0; nt0<8; nt0+=2){
                uint4 bv = *(const uint4*)(bw + nt0*2);
                mma8(acc[nt0],   a0,a1,a2,a3, bv.x, bv.y);
                mma8(acc[nt0+1], a0,a1,a2,a3, bv.z, bv.w);
            }
        }
    }
    __syncthreads();
    float* so = (float*)smem;   // [64][132]
    #pragma unroll
    for (int nt=0; nt<8; nt++){
        int n = wn + nt*8 + 2*tig;
        so[(wm+gid)*132 + n]     = acc[nt][0];
        so[(wm+gid)*132 + n+1]   = acc[nt][1];
        so[(wm+gid+8)*132 + n]   = acc[nt][2];
        so[(wm+gid+8)*132 + n+1] = acc[nt][3];
    }
    __syncthreads();
    const float* res = xin ? xin : g_x;
    for (int e=tid; e<8192; e+=256){
        int h = e&127, r = e>>7;
        int gi = (row0+r)*H + h;
        float xv = res[gi];
        float xn = (xv - g_mu[row0+r])*g_rs[row0+r]*g1[l*H+h] + b1v[l*H+h];
        g_x[gi] = xv + so[r*132+h] + xn*Dsk[l*H+h];
    }
}

// ===================== LN2 + MLP, M=64, 512 threads =================================
#define SM_MLP (42496*4)
__global__ void __launch_bounds__(512,1) k_mlp(const float* __restrict__ g2,
                      const float* __restrict__ b2v,
                      const float* __restrict__ b1v, const float* __restrict__ b2o, int l)
{
    extern __shared__ uint32_t smem[];
    uint32_t* sa = smem;                     // [64][132]
    uint32_t* sh = smem + 8448;              // [64][260]
    uint32_t  sb = (uint32_t)__cvta_generic_to_shared(smem);
    uint32_t  wb = sb + 25088*4;
    int tid = threadIdx.x, lane = tid&31, warp = tid>>5;
    int gid = lane>>2, tig = lane&3;
    int row0 = blockIdx.x * 64;

    {   // prefetch W1 chunk 0
        const uint32_t* ws = g_W1P + l*32768;
        #pragma unroll
        for (int j=0;j<4;j++){
            int f = tid + j*512, row = f>>4, g = (f&15)*4;
            cpa16(wb + (row*68 + g)*4, ws + row*64 + g);
        }
        cpcommit();
    }

    for (int rr=0; rr<4; rr++){
        int r = warp*4 + rr;
        int base = (row0+r)*H;
        float v0 = g_x[base + lane];
        float v1 = g_x[base + lane + 32];
        float v2 = g_x[base + lane + 64];
        float v3 = g_x[base + lane + 96];
        float s  = v0+v1+v2+v3;
        float sq = v0*v0+v1*v1+v2*v2+v3*v3;
        #pragma unroll
        for (int o=16;o>0;o>>=1){ s += __shfl_xor_sync(FULL,s,o); sq += __shfl_xor_sync(FULL,sq,o); }
        float mu = s * (1.0f/128.0f);
        float var = sq * (1.0f/128.0f) - mu*mu;
        float rstd = rsqrtf(var + 1e-5f);
        float vv[4] = {v0,v1,v2,v3};
        #pragma unroll
        for (int q=0;q<4;q++){
            int h = lane + 32*q;
            sa[r*132 + h] = f2tf((vv[q] - mu)*rstd * g2[l*H+h] + b2v[l*H+h]);
        }
    }

    int wm = (warp>>2)*16, wn = (warp&3)*64, wnb = (warp&3)*8;
    float acc[8][4];
    #pragma unroll
    for (int nt=0;nt<8;nt++){ acc[nt][0]=acc[nt][1]=acc[nt][2]=acc[nt][3]=0.f; }
    for (int kc=0; kc<4; kc++){
        cpwait0();
        __syncthreads();
        if (kc < 3){
            const uint32_t* ws = g_W1P + l*32768 + (kc+1)*8192;
            uint32_t dst = wb + (((kc+1)&1)*8704)*4;
            #pragma unroll
            for (int j=0;j<4;j++){
                int f = tid + j*512, row = f>>4, g = (f&15)*4;
                cpa16(dst + (row*68 + g)*4, ws + row*64 + g);
            }
            cpcommit();
        }
        uint32_t* sw = smem + 25088 + (kc&1)*8704;
        #pragma unroll
        for (int ks=0; ks<4; ks++){
            int k0 = kc*32 + ks*8;
            uint32_t a0 = sa[(wm+gid)*132   + k0 + tig];
            uint32_t a1 = sa[(wm+gid+8)*132 + k0 + tig];
            uint32_t a2 = sa[(wm+gid)*132   + k0 + tig+4];
            uint32_t a3 = sa[(wm+gid+8)*132 + k0 + tig+4];
            const uint32_t* bw = sw + (ks*32 + gid*4 + tig)*68 + wnb*2;
            #pragma unroll
            for (int nt0=0; nt0<8; nt0+=2){
                uint4 bv = *(const uint4*)(bw + nt0*2);
                mma8(acc[nt0],   a0,a1,a2,a3, bv.x, bv.y);
                mma8(acc[nt0+1], a0,a1,a2,a3, bv.z, bv.w);
            }
        }
    }
    {
        const uint32_t* ws = g_W2P + l*32768;
        #pragma unroll
        for (int j=0;j<2;j++){
            int f = tid + j*512, row = f>>3, g = (f&7)*4;
            cpa16(wb + (row*36 + g)*4, ws + row*32 + g);
        }
        cpcommit();
    }
    #pragma unroll
    for (int nt=0; nt<8; nt++){
        int n = wn + nt*8 + 2*tig;
        float bb0 = b1v[l*256 + n], bb1 = b1v[l*256 + n + 1];
        float x0 = acc[nt][0]+bb0, x1 = acc[nt][1]+bb1;
        float x2 = acc[nt][2]+bb0, x3 = acc[nt][3]+bb1;
        sh[(wm+gid)*260 + n]     = f2tf(0.5f*x0*(1.0f+erff(x0*0.70710678118f)));
        sh[(wm+gid)*260 + n+1]   = f2tf(0.5f*x1*(1.0f+erff(x1*0.70710678118f)));
        sh[(wm+gid+8)*260 + n]   = f2tf(0.5f*x2*(1.0f+erff(x2*0.70710678118f)));
        sh[(wm+gid+8)*260 + n+1] = f2tf(0.5f*x3*(1.0f+erff(x3*0.70710678118f)));
    }

    int wn2 = (warp&3)*32, wnb2 = (warp&3)*4;
    float acc2[4][4];
    #pragma unroll
    for (int nt=0;nt<4;nt++){ acc2[nt][0]=acc2[nt][1]=acc2[nt][2]=acc2[nt][3]=0.f; }
    for (int kc=0; kc<8; kc++){
        cpwait0();
        __syncthreads();
        if (kc < 7){
            const uint32_t* ws = g_W2P + l*32768 + (kc+1)*4096;
            uint32_t dst = wb + (((kc+1)&1)*8704)*4;
            #pragma unroll
            for (int j=0;j<2;j++){
                int f = tid + j*512, row = f>>3, g = (f&7)*4;
                cpa16(dst + (row*36 + g)*4, ws + row*32 + g);
            }
            cpcommit();
        }
        uint32_t* sw = smem + 25088 + (kc&1)*8704;
        #pragma unroll
        for (int ks=0; ks<4; ks++){
            int k0 = kc*32 + ks*8;
            uint32_t a0 = sh[(wm+gid)*260   + k0 + tig];
            uint32_t a1 = sh[(wm+gid+8)*260 + k0 + tig];
            uint32_t a2 = sh[(wm+gid)*260   + k0 + tig+4];
            uint32_t a3 = sh[(wm+gid+8)*260 + k0 + tig+4];
            const uint32_t* bw = sw + (ks*32 + gid*4 + tig)*36 + wnb2*2;
            #pragma unroll
            for (int nt0=0; nt0<4; nt0+=2){
                uint4 bv = *(const uint4*)(bw + nt0*2);
                mma8(acc2[nt0],   a0,a1,a2,a3, bv.x, bv.y);
                mma8(acc2[nt0+1], a0,a1,a2,a3, bv.z, bv.w);
            }
        }
    }
    __syncthreads();
    float* so = (float*)sa;    // [64][132]
    #pragma unroll
    for (int nt=0; nt<4; nt++){
        int n = wn2 + nt*8 + 2*tig;
        so[(wm+gid)*132 + n]     = acc2[nt][0];
        so[(wm+gid)*132 + n+1]   = acc2[nt][1];
        so[(wm+gid+8)*132 + n]   = acc2[nt][2];
        so[(wm+gid+8)*132 + n+1] = acc2[nt][3];
    }
    __syncthreads();
    for (int e=tid; e<8192; e+=512){
        int h = e&127, r = e>>7;
        int gi = (row0+r)*H + h;
        g_x[gi] = g_x[gi] + so[r*132+h] + b2o[l*H+h];
    }
}

// ===================== conv1 as tf32 GEMM (K=640) ===================================
#define SM_CONV (26508*4)
__global__ void __launch_bounds__(256,2) k_conv1(const float* __restrict__ bc1)
{
    extern __shared__ uint32_t smem[];
    uint32_t* sx = smem;
    uint32_t  sb = (uint32_t)__cvta_generic_to_shared(smem);
    int tid = threadIdx.x, lane = tid&31, warp = tid>>5;
    int gid = lane>>2, tig = lane&3;
    int b = blockIdx.x >> 5;
    int ip0 = (blockIdx.x & 31) * 64;
    int t0 = 2*ip0 - 2;

    {
        const uint32_t* ws = g_Wc1P;
        #pragma unroll
        for (int j=0;j<4;j++){
            int f = tid + j*256, row = f>>3, g = (f&7)*4;
            cpa16(sb + (17292 + row*36 + g)*4, ws + row*32 + g);
        }
        cpcommit();
    }
    for (int e=tid; e<131*128; e+=256){
        int t = e>>7, ic = e&127;
        int tg = t0 + t;
        float v = (tg>=0 && tg<T) ? g_x[(b*T+tg)*H + ic] : 0.0f;
        sx[t*132 + ic] = f2tf(v);
    }

    int wm = (warp>>1)*16, wn = (warp&1)*64, wnb = (warp&1)*8;
    float acc[8][4];
    #pragma unroll
    for (int nt=0;nt<8;nt++){ acc[nt][0]=acc[nt][1]=acc[nt][2]=acc[nt][3]=0.f; }

    for (int c=0; c<20; c++){
        cpwait0();
        __syncthreads();
        if (c < 19){
            const uint32_t* ws = g_Wc1P + (c+1)*4096;
            uint32_t dst = sb + (17292 + ((c+1)&1)*4608)*4;
            #pragma unroll
            for (int j=0;j<4;j++){
                int f = tid + j*256, row = f>>3, g = (f&7)*4;
                cpa16(dst + (row*36 + g)*4, ws + row*32 + g);
            }
            cpcommit();
        }
        uint32_t* sw = smem + 17292 + (c&1)*4608;
        int kv = c>>2, icb = (c&3)*32;
        #pragma unroll
        for (int ks=0; ks<4; ks++){
            int ic0 = icb + ks*8;
            uint32_t a0 = sx[(2*(wm+gid)+kv)*132   + ic0 + tig];
            uint32_t a1 = sx[(2*(wm+gid+8)+kv)*132 + ic0 + tig];
            uint32_t a2 = sx[(2*(wm+gid)+kv)*132   + ic0 + tig+4];
            uint32_t a3 = sx[(2*(wm+gid+8)+kv)*132 + ic0 + tig+4];
            const uint32_t* bw = sw + (ks*32 + gid*4 + tig)*36 + wnb*2;
            #pragma unroll
            for (int nt0=0; nt0<8; nt0+=2){
                uint4 bv = *(const uint4*)(bw + nt0*2);
                mma8(acc[nt0],   a0,a1,a2,a3, bv.x, bv.y);
                mma8(acc[nt0+1], a0,a1,a2,a3, bv.z, bv.w);
            }
        }
    }
    __syncthreads();
    float* so = (float*)smem;   // [64][132]
    #pragma unroll
    for (int nt=0; nt<8; nt++){
        int n = wn + nt*8 + 2*tig;
        so[(wm+gid)*132 + n]     = acc[nt][0];
        so[(wm+gid)*132 + n+1]   = acc[nt][1];
        so[(wm+gid+8)*132 + n]   = acc[nt][2];
        so[(wm+gid+8)*132 + n+1] = acc[nt][3];
    }
    __syncthreads();
    for (int e=tid; e<8192; e+=256){
        int r = e>>7, co = e&127;
        g_y1[(b*T2 + ip0 + r)*H + co] = fmaxf(so[r*132+co] + bc1[co], 0.0f);
    }
}

// ===================== conv2 + fused pool ===========================================
__global__ void __launch_bounds__(256,2) k_conv2pool(const float* __restrict__ bc2,
                                                     float* __restrict__ out)
{
    extern __shared__ uint32_t smem[];
    uint32_t* sx = smem;
    uint32_t  sb = (uint32_t)__cvta_generic_to_shared(smem);
    int tid = threadIdx.x, lane = tid&31, warp = tid>>5;
    int gid = lane>>2, tig = lane&3;
    int b = blockIdx.x >> 4;
    int tile = blockIdx.x & 15;
    int jp0 = tile * 64;
    int t0 = 2*jp0 - 2;

    {
        const uint32_t* ws = g_Wc2P;
        #pragma unroll
        for (int j=0;j<4;j++){
            int f = tid + j*256, row = f>>3, g = (f&7)*4;
            cpa16(sb + (17292 + row*36 + g)*4, ws + row*32 + g);
        }
        cpcommit();
    }
    for (int e=tid; e<131*128; e+=256){
        int t = e>>7, ic = e&127;
        int tg = t0 + t;
        float v = (tg>=0 && tg<T2) ? g_y1[(b*T2+tg)*H + ic] : 0.0f;
        sx[t*132 + ic] = f2tf(v);
    }

    int wm = (warp>>1)*16, wn = (warp&1)*64, wnb = (warp&1)*8;
    float acc[8][4];
    #pragma unroll
    for (int nt=0;nt<8;nt++){ acc[nt][0]=acc[nt][1]=acc[nt][2]=acc[nt][3]=0.f; }

    for (int c=0; c<20; c++){
        cpwait0();
        __syncthreads();
        if (c < 19){
            const uint32_t* ws = g_Wc2P + (c+1)*4096;
            uint32_t dst = sb + (17292 + ((c+1)&1)*4608)*4;
            #pragma unroll
            for (int j=0;j<4;j++){
                int f = tid + j*256, row = f>>3, g = (f&7)*4;
                cpa16(dst + (row*36 + g)*4, ws + row*32 + g);
            }
            cpcommit();
        }
        uint32_t* sw = smem + 17292 + (c&1)*4608;
        int kv = c>>2, icb = (c&3)*32;
        #pragma unroll
        for (int ks=0; ks<4; ks++){
            int ic0 = icb + ks*8;
            uint32_t a0 = sx[(2*(wm+gid)+kv)*132   + ic0 + tig];
            uint32_t a1 = sx[(2*(wm+gid+8)+kv)*132 + ic0 + tig];
            uint32_t a2 = sx[(2*(wm+gid)+kv)*132   + ic0 + tig+4];
            uint32_t a3 = sx[(2*(wm+gid+8)+kv)*132 + ic0 + tig+4];
            const uint32_t* bw = sw + (ks*32 + gid*4 + tig)*36 + wnb*2;
            #pragma unroll
            for (int nt0=0; nt0<8; nt0+=2){
                uint4 bv = *(const uint4*)(bw + nt0*2);
                mma8(acc[nt0],   a0,a1,a2,a3, bv.x, bv.y);
                mma8(acc[nt0+1], a0,a1,a2,a3, bv.z, bv.w);
            }
        }
    }
    __syncthreads();
    float* so = (float*)smem;   // [64][132]
    #pragma unroll
    for (int nt=0; nt<8; nt++){
        int n = wn + nt*8 + 2*tig;
        so[(wm+gid)*132 + n]     = acc[nt][0];
        so[(wm+gid)*132 + n+1]   = acc[nt][1];
        so[(wm+gid+8)*132 + n]   = acc[nt][2];
        so[(wm+gid+8)*132 + n+1] = acc[nt][3];
    }
    __syncthreads();
    {
        int co = tid & 127, half = tid >> 7;
        float bias = bc2[co];
        float s0 = 0.f, s1 = 0.f;
        #pragma unroll
        for (int i=0;i<16;i++) s0 += fmaxf(so[(half*32+i)*132+co] + bias, 0.0f);
        #pragma unroll
        for (int i=16;i<32;i++) s1 += fmaxf(so[(half*32+i)*132+co] + bias, 0.0f);
        int d = tile*4 + half*2;
        out[(b*H+co)*DOUT + d]     = s0 * (1.0f/16.0f);
        out[(b*H+co)*DOUT + d + 1] = s1 * (1.0f/16.0f);
    }
}

// ---------------- launch ----------------
extern "C" void kernel_launch(void* const* d_in, const int* in_sizes, int n_in,
                              void* d_out, int out_size)
{
    (void)in_sizes; (void)n_in; (void)out_size;
    const float* x    = (const float*)d_in[0];
    const float* ln1g = (const float*)d_in[1];
    const float* ln1b = (const float*)d_in[2];
    const float* ln2g = (const float*)d_in[3];
    const float* ln2b = (const float*)d_in[4];
    const float* lre  = (const float*)d_in[5];
    const float* lim  = (const float*)d_in[6];
    const float* Bre  = (const float*)d_in[7];
    const float* Bim  = (const float*)d_in[8];
    const float* Cre  = (const float*)d_in[9];
    const float* Cim  = (const float*)d_in[10];
    const float* Dsk  = (const float*)d_in[11];
    const float* lstep= (const float*)d_in[12];
    const float* W1   = (const float*)d_in[13];
    const float* b1   = (const float*)d_in[14];
    const float* W2   = (const float*)d_in[15];
    const float* b2   = (const float*)d_in[16];
    const float* c1w  = (const float*)d_in[17];
    const float* c1b  = (const float*)d_in[18];
    const float* c2w  = (const float*)d_in[19];
    const float* c2b  = (const float*)d_in[20];
    float* out = (float*)d_out;

    cudaFuncSetAttribute(k_ln_bu,     cudaFuncAttributeMaxDynamicSharedMemorySize, SM_LNBU);
    cudaFuncSetAttribute(k_cmix,      cudaFuncAttributeMaxDynamicSharedMemorySize, SM_CMIX);
    cudaFuncSetAttribute(k_mlp,       cudaFuncAttributeMaxDynamicSharedMemorySize, SM_MLP);
    cudaFuncSetAttribute(k_conv1,     cudaFuncAttributeMaxDynamicSharedMemorySize, SM_CONV);
    cudaFuncSetAttribute(k_conv2pool, cudaFuncAttributeMaxDynamicSharedMemorySize, SM_CONV);

    k_prep<<<DEPTH*NS, H>>>(lre, lim, Bre, Bim, lstep);
    k_prepW<<<256, 256>>>(Cre, Cim, W1, W2);
    k_prepConv<<<320, 256>>>(c1w, c2w);
    for (int l=0;l<DEPTH;l++){
        const float* xin = (l==0) ? x : nullptr;
        k_ln_bu<<<TT/64, 512, SM_LNBU>>>(xin, ln1g, ln1b, l);
        k_scan<<<BATCH*NS, 256>>>(l);
        k_cmix<<<TT/64, 256, SM_CMIX>>>(xin, Dsk, ln1g, ln1b, l);
        k_mlp<<<TT/64, 512, SM_MLP>>>(ln2g, ln2b, b1, b2, l);
    }
    k_conv1<<<BATCH*32, 256, SM_CONV>>>(c1b);
    k_conv2pool<<<BATCH*16, 256, SM_CONV>>>(c2b, out);
}

// round 13
// speedup vs baseline: 5.3865x; 1.5816x over previous
#include <cuda_runtime.h>
#include <cuda_fp16.h>
#include <math.h>
#include <stdint.h>

#define BATCH 32
#define T 4096
#define H 128
#define NS 128
#define DEPTH 2
#define TT (BATCH*T)
#define T2 2048
#define DOUT 64
#define FULL 0xFFFFFFFFu

// ---------------- scratch ----------------
__device__ float g_x  [TT*H];
__device__ float g_mu [TT];
__device__ float g_rs [TT];
__device__ float g_bur[BATCH*NS*T];
__device__ float g_bui[BATCH*NS*T];
__device__ float g_y1 [BATCH*T2*H];
__device__ float g_lbr[DEPTH*NS], g_lbi[DEPTH*NS];
// packed (m16n8k16 fragment order) fp16 weights
__device__ __half g_WbuH[DEPTH*32768];  // K=128,N=256
__device__ __half g_WcH [DEPTH*32768];  // K=256,N=128
__device__ __half g_W1H [DEPTH*32768];  // K=128,N=256
__device__ __half g_W2H [DEPTH*32768];  // K=256,N=128
__device__ __half g_Wc1H[81920];        // K=640,N=128
__device__ __half g_Wc2H[81920];

// ---------------- helpers ----------------
__device__ __forceinline__ uint32_t f2h2(float lo, float hi){
    __half2 h = __floats2half2_rn(lo, hi);
    return *(uint32_t*)&h;
}
__device__ __forceinline__ void mma16(float* c, uint32_t a0,uint32_t a1,uint32_t a2,uint32_t a3,
                                      uint32_t b0,uint32_t b1){
    asm volatile("mma.sync.aligned.m16n8k16.row.col.f32.f16.f16.f32 "
        "{%0,%1,%2,%3},{%4,%5,%6,%7},{%8,%9},{%0,%1,%2,%3};"
        : "+f"(c[0]),"+f"(c[1]),"+f"(c[2]),"+f"(c[3])
        : "r"(a0),"r"(a1),"r"(a2),"r"(a3),"r"(b0),"r"(b1));
}
__device__ __forceinline__ void cpa16(uint32_t s, const void* g){
    asm volatile("cp.async.cg.shared.global [%0], [%1], 16;" :: "r"(s), "l"(g));
}
__device__ __forceinline__ void cpcommit(){ asm volatile("cp.async.commit_group;" ::: "memory"); }
__device__ __forceinline__ void cpwait0(){ asm volatile("cp.async.wait_group 0;" ::: "memory"); }

// fp16 fragment-order packed half index, k chunks of 16, NT = N/8
__device__ __forceinline__ int packIdxH(int k, int n, int NT){
    int k16 = k>>4, r = k&15;
    int tig = (r>>1)&3, hi = (r>>3)&1, lo = r&1;
    int row = k16*32 + (n&7)*4 + tig;
    return ((row*(2*NT) + (n>>3)*2 + hi)<<1) | lo;
}

// ---------------- param prep ----------------
__global__ void k_prep(const float* __restrict__ lre, const float* __restrict__ lim,
                       const float* __restrict__ Bre, const float* __restrict__ Bim,
                       const float* __restrict__ lstep)
{
    int idx = blockIdx.x;               // l*NS + n
    int l = idx >> 7, n = idx & 127;
    float lr = lre[idx], li = lim[idx];
    float dt = expf(lstep[idx]);
    float er = expf(lr*dt);
    float lbr = er * cosf(li*dt);
    float lbi = er * sinf(li*dt);
    if (threadIdx.x == 0){ g_lbr[idx]=lbr; g_lbi[idx]=lbi; }
    float den = lr*lr + li*li;
    float nr = lbr - 1.0f, ni = lbi;
    float fr = (nr*lr + ni*li)/den;
    float fi = (ni*lr - nr*li)/den;
    int h = threadIdx.x;
    float br = Bre[idx*H + h], bi = Bim[idx*H + h];
    float wr = fr*br - fi*bi;
    float wi = fr*bi + fi*br;
    g_WbuH[l*32768 + packIdxH(h, n,     32)] = __float2half(wr);
    g_WbuH[l*32768 + packIdxH(h, n+128, 32)] = __float2half(wi);
}

__global__ void k_prepW(const float* __restrict__ Cre, const float* __restrict__ Cim,
                        const float* __restrict__ W1, const float* __restrict__ W2)
{
    int i = blockIdx.x*256 + threadIdx.x;        // 65536
    int l = i>>15, rem = i&32767;
    {   // Wc: [k(256)][h(128)]
        int k = rem>>7, h = rem&127;
        float v = (k<128) ? 2.0f*Cre[(l*H+h)*NS + k]
                          : -2.0f*Cim[(l*H+h)*NS + (k-128)];
        g_WcH[l*32768 + packIdxH(k, h, 16)] = __float2half(v);
    }
    {   // W1: [k(128)][n(256)]
        int k = rem>>8, n = rem&255;
        g_W1H[l*32768 + packIdxH(k, n, 32)] = __float2half(W1[i]);
    }
    {   // W2: [k(256)][n(128)]
        int k = rem>>7, n = rem&127;
        g_W2H[l*32768 + packIdxH(k, n, 16)] = __float2half(W2[i]);
    }
}

__global__ void k_prepConv(const float* __restrict__ w1, const float* __restrict__ w2)
{
    int i = blockIdx.x*256 + threadIdx.x;        // 81920
    int co = i & 127, r = i >> 7;                // r = kv*128+ic
    int kv = r >> 7, ic = r & 127;
    int k = kv*128 + ic;
    int d = packIdxH(k, co, 16);
    g_Wc1H[d] = __float2half(w1[(co*H + ic)*5 + kv]);
    g_Wc2H[d] = __float2half(w2[(co*H + ic)*5 + kv]);
}

// ===================== LN1 + Bu GEMM (fp16), Bu -> [B][N][T] ========================
// 64 rows, 512 threads (16 warps, warp tile 16x64).
// smem: sa[64][68]=4352 + 2x wbuf[64][68]=8704 ; epilogue so[64][257]=16448 words
#define SM_LNBU (16448*4)
__global__ void __launch_bounds__(512,2) k_ln_bu(const float* __restrict__ xin,
                        const float* __restrict__ g1, const float* __restrict__ b1v, int l)
{
    extern __shared__ uint32_t smem[];
    uint32_t* sa = smem;            // [64][68] half2
    uint32_t  sb = (uint32_t)__cvta_generic_to_shared(smem);
    const float* src = xin ? xin : g_x;
    int tid = threadIdx.x, lane = tid&31, warp = tid>>5;
    int gid = lane>>2, tig = lane&3;
    int row0 = blockIdx.x * 64;
    int b = row0 >> 12, t0 = row0 & (T-1);

    {   // prefetch chunk 0 (4096 words)
        const uint32_t* ws = (const uint32_t*)(g_WbuH + l*32768);
        #pragma unroll
        for (int j=0;j<2;j++){
            int f = tid + j*512, row = f>>4, g = (f&15)*4;
            cpa16(sb + (4352 + row*68 + g)*4, ws + row*64 + g);
        }
        cpcommit();
    }

    // ---- LayerNorm: 16 warps x 4 rows, write half2 pairs ----
    for (int rr = 0; rr < 4; rr++){
        int r = warp*4 + rr;
        int base = (row0 + r) * H;
        float2 p0 = *(const float2*)&src[base + 2*lane];
        float2 p1 = *(const float2*)&src[base + 64 + 2*lane];
        float s  = p0.x+p0.y+p1.x+p1.y;
        float sq = p0.x*p0.x+p0.y*p0.y+p1.x*p1.x+p1.y*p1.y;
        #pragma unroll
        for (int o=16;o>0;o>>=1){ s += __shfl_xor_sync(FULL,s,o); sq += __shfl_xor_sync(FULL,sq,o); }
        float mu = s * (1.0f/128.0f);
        float var = sq * (1.0f/128.0f) - mu*mu;
        float rstd = rsqrtf(var + 1e-5f);
        if (lane == 0){ g_mu[row0+r] = mu; g_rs[row0+r] = rstd; }
        float2 ga = *(const float2*)&g1[l*H + 2*lane];
        float2 ba = *(const float2*)&b1v[l*H + 2*lane];
        float2 gb = *(const float2*)&g1[l*H + 64 + 2*lane];
        float2 bb = *(const float2*)&b1v[l*H + 64 + 2*lane];
        sa[r*68 + lane]      = f2h2((p0.x-mu)*rstd*ga.x + ba.x, (p0.y-mu)*rstd*ga.y + ba.y);
        sa[r*68 + 32 + lane] = f2h2((p1.x-mu)*rstd*gb.x + bb.x, (p1.y-mu)*rstd*gb.y + bb.y);
    }

    int wm = (warp>>2)*16, wn = (warp&3)*64, wnb = (warp&3)*8;
    float acc[8][4];
    #pragma unroll
    for (int nt=0;nt<8;nt++){ acc[nt][0]=acc[nt][1]=acc[nt][2]=acc[nt][3]=0.f; }

    for (int kc=0; kc<4; kc++){
        cpwait0();
        __syncthreads();
        if (kc < 3){
            const uint32_t* ws = (const uint32_t*)(g_WbuH + l*32768) + (kc+1)*4096;
            uint32_t dst = sb + (4352 + ((kc+1)&1)*4352)*4;
            #pragma unroll
            for (int j=0;j<2;j++){
                int f = tid + j*512, row = f>>4, g = (f&15)*4;
                cpa16(dst + (row*68 + g)*4, ws + row*64 + g);
            }
            cpcommit();
        }
        uint32_t* sw = smem + 4352 + (kc&1)*4352;
        #pragma unroll
        for (int ks=0; ks<2; ks++){
            int kp0 = kc*16 + ks*8;
            uint32_t a0 = sa[(wm+gid)*68   + kp0 + tig];
            uint32_t a1 = sa[(wm+gid+8)*68 + kp0 + tig];
            uint32_t a2 = sa[(wm+gid)*68   + kp0 + tig+4];
            uint32_t a3 = sa[(wm+gid+8)*68 + kp0 + tig+4];
            const uint32_t* bw = sw + (ks*32 + gid*4 + tig)*68 + wnb*2;
            #pragma unroll
            for (int nt0=0; nt0<8; nt0+=2){
                uint4 bv = *(const uint4*)(bw + nt0*2);
                mma16(acc[nt0],   a0,a1,a2,a3, bv.x, bv.y);
                mma16(acc[nt0+1], a0,a1,a2,a3, bv.z, bv.w);
            }
        }
    }
    __syncthreads();
    float* so = (float*)smem;    // [64][257]
    #pragma unroll
    for (int nt=0; nt<8; nt++){
        int n = wn + nt*8 + 2*tig;
        so[(wm+gid)*257 + n]     = acc[nt][0];
        so[(wm+gid)*257 + n+1]   = acc[nt][1];
        so[(wm+gid+8)*257 + n]   = acc[nt][2];
        so[(wm+gid+8)*257 + n+1] = acc[nt][3];
    }
    __syncthreads();
    for (int i=0; i<16; i++){
        int n = warp*16 + i;
        int np = n & 127;
        float* dst = ((n<128) ? g_bur : g_bui) + (b*NS + np)*T + t0;
        dst[lane]    = so[lane*257 + n];
        dst[lane+32] = so[(lane+32)*257 + n];
    }
}

// ---------------- in-place scan over T ----------------
__global__ void k_scan(int l)
{
    __shared__ float s_wr[8], s_wi[8], s_er[8], s_ei[8];
    int bid = blockIdx.x;
    int n = bid & (NS-1);
    int tid = threadIdx.x, lane = tid & 31, warp = tid >> 5;
    int base = bid * T + tid * 16;
    float lr = g_lbr[l*NS+n], li = g_lbi[l*NS+n];

    float vr[16], vi[16];
    float4* pr = (float4*)(g_bur + base);
    float4* pi = (float4*)(g_bui + base);
    #pragma unroll
    for (int q=0;q<4;q++){
        float4 a = pr[q]; vr[4*q]=a.x; vr[4*q+1]=a.y; vr[4*q+2]=a.z; vr[4*q+3]=a.w;
        float4 c = pi[q]; vi[4*q]=c.x; vi[4*q+1]=c.y; vi[4*q+2]=c.z; vi[4*q+3]=c.w;
    }
    float sr=0.f, si=0.f;
    #pragma unroll
    for (int i=0;i<16;i++){
        float tr = lr*sr - li*si + vr[i];
        float ti = lr*si + li*sr + vi[i];
        sr=tr; si=ti;
    }
    float cdr[6], cdi[6];
    {
        float pr_=lr, pi_=li;
        #pragma unroll
        for (int q=0;q<4;q++){ float tr = pr_*pr_ - pi_*pi_; pi_ = 2.f*pr_*pi_; pr_ = tr; }
        cdr[0]=pr_; cdi[0]=pi_;
        #pragma unroll
        for (int q=1;q<6;q++){ float tr = cdr[q-1]*cdr[q-1]-cdi[q-1]*cdi[q-1];
                               cdi[q]=2.f*cdr[q-1]*cdi[q-1]; cdr[q]=tr; }
    }
    float xr=sr, xi=si;
    #pragma unroll
    for (int st=0; st<5; st++){
        int d = 1<<st;
        float or_ = __shfl_up_sync(FULL, xr, d);
        float oi_ = __shfl_up_sync(FULL, xi, d);
        if (lane >= d){
            float tr = cdr[st]*or_ - cdi[st]*oi_ + xr;
            xi = cdr[st]*oi_ + cdi[st]*or_ + xi;
            xr = tr;
        }
    }
    if (lane==31){ s_wr[warp]=xr; s_wi[warp]=xi; }
    __syncthreads();
    if (tid==0){
        float er=0.f, ei=0.f;
        #pragma unroll
        for (int w=0;w<8;w++){
            s_er[w]=er; s_ei[w]=ei;
            float tr = cdr[5]*er - cdi[5]*ei + s_wr[w];
            ei = cdr[5]*ei + cdi[5]*er + s_wi[w];
            er = tr;
        }
    }
    __syncthreads();
    float Er = s_er[warp], Ei = s_ei[warp];
    float plr=1.f, pli=0.f;
    #pragma unroll
    for (int bt=0; bt<5; bt++){
        if (lane & (1<<bt)){
            float tr = plr*cdr[bt] - pli*cdi[bt];
            pli = plr*cdi[bt] + pli*cdr[bt];
            plr = tr;
        }
    }
    float car = plr*Er - pli*Ei;
    float cai = plr*Ei + pli*Er;
    float pvr = __shfl_up_sync(FULL, xr, 1);
    float pvi = __shfl_up_sync(FULL, xi, 1);
    if (lane > 0){ car += pvr; cai += pvi; }
    sr = car; si = cai;
    #pragma unroll
    for (int i=0;i<16;i++){
        float tr = lr*sr - li*si + vr[i];
        float ti = lr*si + li*sr + vi[i];
        sr=tr; si=ti;
        vr[i]=sr; vi[i]=si;
    }
    #pragma unroll
    for (int q=0;q<4;q++){
        pr[q] = make_float4(vr[4*q],vr[4*q+1],vr[4*q+2],vr[4*q+3]);
        pi[q] = make_float4(vi[4*q],vi[4*q+1],vi[4*q+2],vi[4*q+3]);
    }
}

// ===================== C-mix GEMM (fp16) ============================================
// 64 rows, 256 threads. smem: saT[128][72]=9216 + 2x[64][36]=4608 -> 13824 words
#define SM_CMIX (13824*4)
__global__ void __launch_bounds__(256,2) k_cmix(const float* __restrict__ xin,
                        const float* __restrict__ Dsk,
                        const float* __restrict__ g1, const float* __restrict__ b1v, int l)
{
    extern __shared__ uint32_t smem[];
    uint32_t* saT = smem;             // [128 kp][72] half2 (k-pair major)
    uint32_t  sb = (uint32_t)__cvta_generic_to_shared(smem);
    int tid = threadIdx.x, lane = tid&31, warp = tid>>5;
    int gid = lane>>2, tig = lane&3;
    int row0 = blockIdx.x * 64;
    int b = row0 >> 12, t0 = row0 & (T-1);

    {   // prefetch Wc chunk 0 (2048 words)
        const uint32_t* ws = (const uint32_t*)(g_WcH + l*32768);
        #pragma unroll
        for (int j=0;j<2;j++){
            int f = tid + j*256, row = f>>3, g = (f&7)*4;
            cpa16(sb + (9216 + row*36 + g)*4, ws + row*32 + g);
        }
        cpcommit();
    }

    // stage xs (real|imag) as half2 k-pairs, k-major
    for (int e=tid; e<8192; e+=256){
        int kp = e>>6, r = e&63;
        int k2 = 2*kp;
        const float* sp = (k2<128) ? (g_bur + (b*NS+k2)*T + t0)
                                   : (g_bui + (b*NS + (k2-128))*T + t0);
        saT[kp*72 + r] = f2h2(sp[r], sp[T + r]);
    }

    int wm = (warp>>1)*16, wn = (warp&1)*64, wnb = (warp&1)*8;
    float acc[8][4];
    #pragma unroll
    for (int nt=0;nt<8;nt++){ acc[nt][0]=acc[nt][1]=acc[nt][2]=acc[nt][3]=0.f; }

    for (int kc=0; kc<8; kc++){
        cpwait0();
        __syncthreads();
        if (kc < 7){
            const uint32_t* ws = (const uint32_t*)(g_WcH + l*32768) + (kc+1)*2048;
            uint32_t dst = sb + (9216 + ((kc+1)&1)*2304)*4;
            #pragma unroll
            for (int j=0;j<2;j++){
                int f = tid + j*256, row = f>>3, g = (f&7)*4;
                cpa16(dst + (row*36 + g)*4, ws + row*32 + g);
            }
            cpcommit();
        }
        uint32_t* sw = smem + 9216 + (kc&1)*2304;
        #pragma unroll
        for (int ks=0; ks<2; ks++){
            int kp0 = kc*16 + ks*8;
            uint32_t a0 = saT[(kp0+tig)*72   + wm+gid];
            uint32_t a1 = saT[(kp0+tig)*72   + wm+gid+8];
            uint32_t a2 = saT[(kp0+tig+4)*72 + wm+gid];
            uint32_t a3 = saT[(kp0+tig+4)*72 + wm+gid+8];
            const uint32_t* bw = sw + (ks*32 + gid*4 + tig)*36 + wnb*2;
            #pragma unroll
            for (int nt0=0; nt0<8; nt0+=2){
                uint4 bv = *(const uint4*)(bw + nt0*2);
                mma16(acc[nt0],   a0,a1,a2,a3, bv.x, bv.y);
                mma16(acc[nt0+1], a0,a1,a2,a3, bv.z, bv.w);
            }
        }
    }
    __syncthreads();
    float* so = (float*)smem;   // [64][132]
    #pragma unroll
    for (int nt=0; nt<8; nt++){
        int n = wn + nt*8 + 2*tig;
        so[(wm+gid)*132 + n]     = acc[nt][0];
        so[(wm+gid)*132 + n+1]   = acc[nt][1];
        so[(wm+gid+8)*132 + n]   = acc[nt][2];
        so[(wm+gid+8)*132 + n+1] = acc[nt][3];
    }
    __syncthreads();
    const float* res = xin ? xin : g_x;
    for (int e=tid; e<8192; e+=256){
        int h = e&127, r = e>>7;
        int gi = (row0+r)*H + h;
        float xv = res[gi];
        float xn = (xv - g_mu[row0+r])*g_rs[row0+r]*g1[l*H+h] + b1v[l*H+h];
        g_x[gi] = xv + so[r*132+h] + xn*Dsk[l*H+h];
    }
}

// ===================== LN2 + MLP (fp16), M=64, 512 threads ==========================
// smem: sa[64][68]=4352 + sh[64][132]=8448 + 2x wbuf 4352 -> 21504 words
#define SM_MLP (21504*4)
__global__ void __launch_bounds__(512,2) k_mlp(const float* __restrict__ g2,
                      const float* __restrict__ b2v,
                      const float* __restrict__ b1v, const float* __restrict__ b2o, int l)
{
    extern __shared__ uint32_t smem[];
    uint32_t* sa = smem;                     // [64][68] half2
    uint32_t* sh = smem + 4352;              // [64][132] half2 (128 kp + pad)
    uint32_t  sb = (uint32_t)__cvta_generic_to_shared(smem);
    uint32_t  wb = sb + 12800*4;
    int tid = threadIdx.x, lane = tid&31, warp = tid>>5;
    int gid = lane>>2, tig = lane&3;
    int row0 = blockIdx.x * 64;

    {   // prefetch W1 chunk 0 (4096 words)
        const uint32_t* ws = (const uint32_t*)(g_W1H + l*32768);
        #pragma unroll
        for (int j=0;j<2;j++){
            int f = tid + j*512, row = f>>4, g = (f&15)*4;
            cpa16(wb + (row*68 + g)*4, ws + row*64 + g);
        }
        cpcommit();
    }

    // LN2: 16 warps x 4 rows
    for (int rr=0; rr<4; rr++){
        int r = warp*4 + rr;
        int base = (row0+r)*H;
        float2 p0 = *(const float2*)&g_x[base + 2*lane];
        float2 p1 = *(const float2*)&g_x[base + 64 + 2*lane];
        float s  = p0.x+p0.y+p1.x+p1.y;
        float sq = p0.x*p0.x+p0.y*p0.y+p1.x*p1.x+p1.y*p1.y;
        #pragma unroll
        for (int o=16;o>0;o>>=1){ s += __shfl_xor_sync(FULL,s,o); sq += __shfl_xor_sync(FULL,sq,o); }
        float mu = s * (1.0f/128.0f);
        float var = sq * (1.0f/128.0f) - mu*mu;
        float rstd = rsqrtf(var + 1e-5f);
        float2 ga = *(const float2*)&g2[l*H + 2*lane];
        float2 ba = *(const float2*)&b2v[l*H + 2*lane];
        float2 gb = *(const float2*)&g2[l*H + 64 + 2*lane];
        float2 bb = *(const float2*)&b2v[l*H + 64 + 2*lane];
        sa[r*68 + lane]      = f2h2((p0.x-mu)*rstd*ga.x + ba.x, (p0.y-mu)*rstd*ga.y + ba.y);
        sa[r*68 + 32 + lane] = f2h2((p1.x-mu)*rstd*gb.x + bb.x, (p1.y-mu)*rstd*gb.y + bb.y);
    }

    // ---- GEMM1: [64x128] @ [128x256] ----
    int wm = (warp>>2)*16, wn = (warp&3)*64, wnb = (warp&3)*8;
    float acc[8][4];
    #pragma unroll
    for (int nt=0;nt<8;nt++){ acc[nt][0]=acc[nt][1]=acc[nt][2]=acc[nt][3]=0.f; }
    for (int kc=0; kc<4; kc++){
        cpwait0();
        __syncthreads();
        if (kc < 3){
            const uint32_t* ws = (const uint32_t*)(g_W1H + l*32768) + (kc+1)*4096;
            uint32_t dst = wb + (((kc+1)&1)*4352)*4;
            #pragma unroll
            for (int j=0;j<2;j++){
                int f = tid + j*512, row = f>>4, g = (f&15)*4;
                cpa16(dst + (row*68 + g)*4, ws + row*64 + g);
            }
            cpcommit();
        }
        uint32_t* sw = smem + 12800 + (kc&1)*4352;
        #pragma unroll
        for (int ks=0; ks<2; ks++){
            int kp0 = kc*16 + ks*8;
            uint32_t a0 = sa[(wm+gid)*68   + kp0 + tig];
            uint32_t a1 = sa[(wm+gid+8)*68 + kp0 + tig];
            uint32_t a2 = sa[(wm+gid)*68   + kp0 + tig+4];
            uint32_t a3 = sa[(wm+gid+8)*68 + kp0 + tig+4];
            const uint32_t* bw = sw + (ks*32 + gid*4 + tig)*68 + wnb*2;
            #pragma unroll
            for (int nt0=0; nt0<8; nt0+=2){
                uint4 bv = *(const uint4*)(bw + nt0*2);
                mma16(acc[nt0],   a0,a1,a2,a3, bv.x, bv.y);
                mma16(acc[nt0+1], a0,a1,a2,a3, bv.z, bv.w);
            }
        }
    }
    // prefetch W2 chunk 0 into buf0 (safe: buf0 dead since kc=3 sync)
    {
        const uint32_t* ws = (const uint32_t*)(g_W2H + l*32768);
        {
            int f = tid, row = f>>3, g = (f&7)*4;   // 2048 words, 512 ops
            cpa16(wb + (row*36 + g)*4, ws + row*32 + g);
        }
        cpcommit();
    }
    // bias + gelu -> sh (half2)
    #pragma unroll
    for (int nt=0; nt<8; nt++){
        int n = wn + nt*8 + 2*tig;
        float bb0 = b1v[l*256 + n], bb1 = b1v[l*256 + n + 1];
        float x0 = acc[nt][0]+bb0, x1 = acc[nt][1]+bb1;
        float x2 = acc[nt][2]+bb0, x3 = acc[nt][3]+bb1;
        int c = n>>1;
        sh[(wm+gid)*132 + c]   = f2h2(0.5f*x0*(1.0f+erff(x0*0.70710678118f)),
                                      0.5f*x1*(1.0f+erff(x1*0.70710678118f)));
        sh[(wm+gid+8)*132 + c] = f2h2(0.5f*x2*(1.0f+erff(x2*0.70710678118f)),
                                      0.5f*x3*(1.0f+erff(x3*0.70710678118f)));
    }

    // ---- GEMM2: [64x256] @ [256x128] ----
    int wn2 = (warp&3)*32, wnb2 = (warp&3)*4;
    float acc2[4][4];
    #pragma unroll
    for (int nt=0;nt<4;nt++){ acc2[nt][0]=acc2[nt][1]=acc2[nt][2]=acc2[nt][3]=0.f; }
    for (int kc=0; kc<8; kc++){
        cpwait0();
        __syncthreads();
        if (kc < 7){
            const uint32_t* ws = (const uint32_t*)(g_W2H + l*32768) + (kc+1)*2048;
            uint32_t dst = wb + (((kc+1)&1)*4352)*4;
            {
                int f = tid, row = f>>3, g = (f&7)*4;
                cpa16(dst + (row*36 + g)*4, ws + row*32 + g);
            }
            cpcommit();
        }
        uint32_t* sw = smem + 12800 + (kc&1)*4352;
        #pragma unroll
        for (int ks=0; ks<2; ks++){
            int kp0 = kc*16 + ks*8;
            uint32_t a0 = sh[(wm+gid)*132   + kp0 + tig];
            uint32_t a1 = sh[(wm+gid+8)*132 + kp0 + tig];
            uint32_t a2 = sh[(wm+gid)*132   + kp0 + tig+4];
            uint32_t a3 = sh[(wm+gid+8)*132 + kp0 + tig+4];
            const uint32_t* bw = sw + (ks*32 + gid*4 + tig)*36 + wnb2*2;
            #pragma unroll
            for (int nt0=0; nt0<4; nt0+=2){
                uint4 bv = *(const uint4*)(bw + nt0*2);
                mma16(acc2[nt0],   a0,a1,a2,a3, bv.x, bv.y);
                mma16(acc2[nt0+1], a0,a1,a2,a3, bv.z, bv.w);
            }
        }
    }
    __syncthreads();
    float* so = (float*)smem;    // [64][132] floats (overlays sa+sh, both dead)
    #pragma unroll
    for (int nt=0; nt<4; nt++){
        int n = wn2 + nt*8 + 2*tig;
        so[(wm+gid)*132 + n]     = acc2[nt][0];
        so[(wm+gid)*132 + n+1]   = acc2[nt][1];
        so[(wm+gid+8)*132 + n]   = acc2[nt][2];
        so[(wm+gid+8)*132 + n+1] = acc2[nt][3];
    }
    __syncthreads();
    for (int e=tid; e<8192; e+=512){
        int h = e&127, r = e>>7;
        int gi = (row0+r)*H + h;
        g_x[gi] = g_x[gi] + so[r*132+h] + b2o[l*H+h];
    }
}

// ===================== conv1 as fp16 GEMM (K=640) ===================================
// smem: sx[131][70]=9170(+2 pad)=9172 + 2x[64][36]=4608 -> 13780 words
#define SM_CONV (13780*4)
__global__ void __launch_bounds__(256,2) k_conv1(const float* __restrict__ bc1)
{
    extern __shared__ uint32_t smem[];
    uint32_t* sx = smem;
    uint32_t  sb = (uint32_t)__cvta_generic_to_shared(smem);
    int tid = threadIdx.x, lane = tid&31, warp = tid>>5;
    int gid = lane>>2, tig = lane&3;
    int b = blockIdx.x >> 5;
    int ip0 = (blockIdx.x & 31) * 64;
    int t0 = 2*ip0 - 2;

    {
        const uint32_t* ws = (const uint32_t*)g_Wc1H;
        #pragma unroll
        for (int j=0;j<2;j++){
            int f = tid + j*256, row = f>>3, g = (f&7)*4;
            cpa16(sb + (9172 + row*36 + g)*4, ws + row*32 + g);
        }
        cpcommit();
    }
    for (int e=tid; e<131*64; e+=256){
        int t = e>>6, icp = e&63;
        int tg = t0 + t;
        float v0 = 0.f, v1 = 0.f;
        if (tg>=0 && tg<T){
            float2 p = *(const float2*)&g_x[(b*T+tg)*H + 2*icp];
            v0 = p.x; v1 = p.y;
        }
        sx[t*70 + icp] = f2h2(v0, v1);
    }

    int wm = (warp>>1)*16, wn = (warp&1)*64, wnb = (warp&1)*8;
    float acc[8][4];
    #pragma unroll
    for (int nt=0;nt<8;nt++){ acc[nt][0]=acc[nt][1]=acc[nt][2]=acc[nt][3]=0.f; }

    for (int c=0; c<20; c++){
        cpwait0();
        __syncthreads();
        if (c < 19){
            const uint32_t* ws = (const uint32_t*)g_Wc1H + (c+1)*2048;
            uint32_t dst = sb + (9172 + ((c+1)&1)*2304)*4;
            #pragma unroll
            for (int j=0;j<2;j++){
                int f = tid + j*256, row = f>>3, g = (f&7)*4;
                cpa16(dst + (row*36 + g)*4, ws + row*32 + g);
            }
            cpcommit();
        }
        uint32_t* sw = smem + 9172 + (c&1)*2304;
        int kv = c>>2, icpb = (c&3)*16;
        #pragma unroll
        for (int ks=0; ks<2; ks++){
            int icp0 = icpb + ks*8;
            uint32_t a0 = sx[(2*(wm+gid)+kv)*70   + icp0 + tig];
            uint32_t a1 = sx[(2*(wm+gid+8)+kv)*70 + icp0 + tig];
            uint32_t a2 = sx[(2*(wm+gid)+kv)*70   + icp0 + tig+4];
            uint32_t a3 = sx[(2*(wm+gid+8)+kv)*70 + icp0 + tig+4];
            const uint32_t* bw = sw + (ks*32 + gid*4 + tig)*36 + wnb*2;
            #pragma unroll
            for (int nt0=0; nt0<8; nt0+=2){
                uint4 bv = *(const uint4*)(bw + nt0*2);
                mma16(acc[nt0],   a0,a1,a2,a3, bv.x, bv.y);
                mma16(acc[nt0+1], a0,a1,a2,a3, bv.z, bv.w);
            }
        }
    }
    __syncthreads();
    float* so = (float*)smem;   // [64][132]
    #pragma unroll
    for (int nt=0; nt<8; nt++){
        int n = wn + nt*8 + 2*tig;
        so[(wm+gid)*132 + n]     = acc[nt][0];
        so[(wm+gid)*132 + n+1]   = acc[nt][1];
        so[(wm+gid+8)*132 + n]   = acc[nt][2];
        so[(wm+gid+8)*132 + n+1] = acc[nt][3];
    }
    __syncthreads();
    for (int e=tid; e<8192; e+=256){
        int r = e>>7, co = e&127;
        g_y1[(b*T2 + ip0 + r)*H + co] = fmaxf(so[r*132+co] + bc1[co], 0.0f);
    }
}

// ===================== conv2 + fused pool ===========================================
__global__ void __launch_bounds__(256,2) k_conv2pool(const float* __restrict__ bc2,
                                                     float* __restrict__ out)
{
    extern __shared__ uint32_t smem[];
    uint32_t* sx = smem;
    uint32_t  sb = (uint32_t)__cvta_generic_to_shared(smem);
    int tid = threadIdx.x, lane = tid&31, warp = tid>>5;
    int gid = lane>>2, tig = lane&3;
    int b = blockIdx.x >> 4;
    int tile = blockIdx.x & 15;
    int jp0 = tile * 64;
    int t0 = 2*jp0 - 2;

    {
        const uint32_t* ws = (const uint32_t*)g_Wc2H;
        #pragma unroll
        for (int j=0;j<2;j++){
            int f = tid + j*256, row = f>>3, g = (f&7)*4;
            cpa16(sb + (9172 + row*36 + g)*4, ws + row*32 + g);
        }
        cpcommit();
    }
    for (int e=tid; e<131*64; e+=256){
        int t = e>>6, icp = e&63;
        int tg = t0 + t;
        float v0 = 0.f, v1 = 0.f;
        if (tg>=0 && tg<T2){
            float2 p = *(const float2*)&g_y1[(b*T2+tg)*H + 2*icp];
            v0 = p.x; v1 = p.y;
        }
        sx[t*70 + icp] = f2h2(v0, v1);
    }

    int wm = (warp>>1)*16, wn = (warp&1)*64, wnb = (warp&1)*8;
    float acc[8][4];
    #pragma unroll
    for (int nt=0;nt<8;nt++){ acc[nt][0]=acc[nt][1]=acc[nt][2]=acc[nt][3]=0.f; }

    for (int c=0; c<20; c++){
        cpwait0();
        __syncthreads();
        if (c < 19){
            const uint32_t* ws = (const uint32_t*)g_Wc2H + (c+1)*2048;
            uint32_t dst = sb + (9172 + ((c+1)&1)*2304)*4;
            #pragma unroll
            for (int j=0;j<2;j++){
                int f = tid + j*256, row = f>>3, g = (f&7)*4;
                cpa16(dst + (row*36 + g)*4, ws + row*32 + g);
            }
            cpcommit();
        }
        uint32_t* sw = smem + 9172 + (c&1)*2304;
        int kv = c>>2, icpb = (c&3)*16;
        #pragma unroll
        for (int ks=0; ks<2; ks++){
            int icp0 = icpb + ks*8;
            uint32_t a0 = sx[(2*(wm+gid)+kv)*70   + icp0 + tig];
            uint32_t a1 = sx[(2*(wm+gid+8)+kv)*70 + icp0 + tig];
            uint32_t a2 = sx[(2*(wm+gid)+kv)*70   + icp0 + tig+4];
            uint32_t a3 = sx[(2*(wm+gid+8)+kv)*70 + icp0 + tig+4];
            const uint32_t* bw = sw + (ks*32 + gid*4 + tig)*36 + wnb*2;
            #pragma unroll
            for (int nt0=0; nt0<8; nt0+=2){
                uint4 bv = *(const uint4*)(bw + nt0*2);
                mma16(acc[nt0],   a0,a1,a2,a3, bv.x, bv.y);
                mma16(acc[nt0+1], a0,a1,a2,a3, bv.z, bv.w);
            }
        }
    }
    __syncthreads();
    float* so = (float*)smem;   // [64][132]
    #pragma unroll
    for (int nt=0; nt<8; nt++){
        int n = wn + nt*8 + 2*tig;
        so[(wm+gid)*132 + n]     = acc[nt][0];
        so[(wm+gid)*132 + n+1]   = acc[nt][1];
        so[(wm+gid+8)*132 + n]   = acc[nt][2];
        so[(wm+gid+8)*132 + n+1] = acc[nt][3];
    }
    __syncthreads();
    {
        int co = tid & 127, half = tid >> 7;
        float bias = bc2[co];
        float s0 = 0.f, s1 = 0.f;
        #pragma unroll
        for (int i=0;i<16;i++) s0 += fmaxf(so[(half*32+i)*132+co] + bias, 0.0f);
        #pragma unroll
        for (int i=16;i<32;i++) s1 += fmaxf(so[(half*32+i)*132+co] + bias, 0.0f);
        int d = tile*4 + half*2;
        out[(b*H+co)*DOUT + d]     = s0 * (1.0f/16.0f);
        out[(b*H+co)*DOUT + d + 1] = s1 * (1.0f/16.0f);
    }
}

// ---------------- launch ----------------
extern "C" void kernel_launch(void* const* d_in, const int* in_sizes, int n_in,
                              void* d_out, int out_size)
{
    (void)in_sizes; (void)n_in; (void)out_size;
    const float* x    = (const float*)d_in[0];
    const float* ln1g = (const float*)d_in[1];
    const float* ln1b = (const float*)d_in[2];
    const float* ln2g = (const float*)d_in[3];
    const float* ln2b = (const float*)d_in[4];
    const float* lre  = (const float*)d_in[5];
    const float* lim  = (const float*)d_in[6];
    const float* Bre  = (const float*)d_in[7];
    const float* Bim  = (const float*)d_in[8];
    const float* Cre  = (const float*)d_in[9];
    const float* Cim  = (const float*)d_in[10];
    const float* Dsk  = (const float*)d_in[11];
    const float* lstep= (const float*)d_in[12];
    const float* W1   = (const float*)d_in[13];
    const float* b1   = (const float*)d_in[14];
    const float* W2   = (const float*)d_in[15];
    const float* b2   = (const float*)d_in[16];
    const float* c1w  = (const float*)d_in[17];
    const float* c1b  = (const float*)d_in[18];
    const float* c2w  = (const float*)d_in[19];
    const float* c2b  = (const float*)d_in[20];
    float* out = (float*)d_out;

    cudaFuncSetAttribute(k_ln_bu,     cudaFuncAttributeMaxDynamicSharedMemorySize, SM_LNBU);
    cudaFuncSetAttribute(k_cmix,      cudaFuncAttributeMaxDynamicSharedMemorySize, SM_CMIX);
    cudaFuncSetAttribute(k_mlp,       cudaFuncAttributeMaxDynamicSharedMemorySize, SM_MLP);
    cudaFuncSetAttribute(k_conv1,     cudaFuncAttributeMaxDynamicSharedMemorySize, SM_CONV);
    cudaFuncSetAttribute(k_conv2pool, cudaFuncAttributeMaxDynamicSharedMemorySize, SM_CONV);

    k_prep<<<DEPTH*NS, H>>>(lre, lim, Bre, Bim, lstep);
    k_prepW<<<256, 256>>>(Cre, Cim, W1, W2);
    k_prepConv<<<320, 256>>>(c1w, c2w);
    for (int l=0;l<DEPTH;l++){
        const float* xin = (l==0) ? x : nullptr;
        k_ln_bu<<<TT/64, 512, SM_LNBU>>>(xin, ln1g, ln1b, l);
        k_scan<<<BATCH*NS, 256>>>(l);
        k_cmix<<<TT/64, 256, SM_CMIX>>>(xin, Dsk, ln1g, ln1b, l);
        k_mlp<<<TT/64, 512, SM_MLP>>>(ln2g, ln2b, b1, b2, l);
    }
    k_conv1<<<BATCH*32, 256, SM_CONV>>>(c1b);
    k_conv2pool<<<BATCH*16, 256, SM_CONV>>>(c2b, out);
}

// round 14
// speedup vs baseline: 6.4457x; 1.1966x over previous
#include <cuda_runtime.h>
#include <cuda_fp16.h>
#include <math.h>
#include <stdint.h>

#define BATCH 32
#define T 4096
#define H 128
#define NS 128
#define DEPTH 2
#define TT (BATCH*T)
#define T2 2048
#define DOUT 64
#define FULL 0xFFFFFFFFu

// ---------------- scratch ----------------
__device__ float g_x  [TT*H];
__device__ float g_mu [TT];
__device__ float g_rs [TT];
__device__ __half g_burH[BATCH*NS*T];
__device__ __half g_buiH[BATCH*NS*T];
__device__ __half g_y1H [BATCH*T2*H];
__device__ float g_lbr[DEPTH*NS], g_lbi[DEPTH*NS];
// packed (m16n8k16 fragment order) fp16 weights
__device__ __half g_WbuH[DEPTH*32768];  // K=128,N=256
__device__ __half g_WcH [DEPTH*32768];  // K=256,N=128
__device__ __half g_W1H [DEPTH*32768];  // K=128,N=256
__device__ __half g_W2H [DEPTH*32768];  // K=256,N=128
__device__ __half g_Wc1H[81920];        // K=640,N=128
__device__ __half g_Wc2H[81920];

// ---------------- helpers ----------------
__device__ __forceinline__ uint32_t f2h2(float lo, float hi){
    __half2 h = __floats2half2_rn(lo, hi);
    return *(uint32_t*)&h;
}
__device__ __forceinline__ void mma16(float* c, uint32_t a0,uint32_t a1,uint32_t a2,uint32_t a3,
                                      uint32_t b0,uint32_t b1){
    asm volatile("mma.sync.aligned.m16n8k16.row.col.f32.f16.f16.f32 "
        "{%0,%1,%2,%3},{%4,%5,%6,%7},{%8,%9},{%0,%1,%2,%3};"
        : "+f"(c[0]),"+f"(c[1]),"+f"(c[2]),"+f"(c[3])
        : "r"(a0),"r"(a1),"r"(a2),"r"(a3),"r"(b0),"r"(b1));
}
__device__ __forceinline__ void cpa16(uint32_t s, const void* g){
    asm volatile("cp.async.cg.shared.global [%0], [%1], 16;" :: "r"(s), "l"(g));
}
__device__ __forceinline__ void cpcommit(){ asm volatile("cp.async.commit_group;" ::: "memory"); }
__device__ __forceinline__ void cpwait0(){ asm volatile("cp.async.wait_group 0;" ::: "memory"); }

// fp16 fragment-order packed half index, k chunks of 16, NT = N/8
__device__ __forceinline__ int packIdxH(int k, int n, int NT){
    int k16 = k>>4, r = k&15;
    int tig = (r>>1)&3, hi = (r>>3)&1, lo = r&1;
    int row = k16*32 + (n&7)*4 + tig;
    return ((row*(2*NT) + (n>>3)*2 + hi)<<1) | lo;
}

// ---------------- param prep ----------------
__global__ void k_prep(const float* __restrict__ lre, const float* __restrict__ lim,
                       const float* __restrict__ Bre, const float* __restrict__ Bim,
                       const float* __restrict__ lstep)
{
    int idx = blockIdx.x;               // l*NS + n
    int l = idx >> 7, n = idx & 127;
    float lr = lre[idx], li = lim[idx];
    float dt = expf(lstep[idx]);
    float er = expf(lr*dt);
    float lbr = er * cosf(li*dt);
    float lbi = er * sinf(li*dt);
    if (threadIdx.x == 0){ g_lbr[idx]=lbr; g_lbi[idx]=lbi; }
    float den = lr*lr + li*li;
    float nr = lbr - 1.0f, ni = lbi;
    float fr = (nr*lr + ni*li)/den;
    float fi = (ni*lr - nr*li)/den;
    int h = threadIdx.x;
    float br = Bre[idx*H + h], bi = Bim[idx*H + h];
    float wr = fr*br - fi*bi;
    float wi = fr*bi + fi*br;
    g_WbuH[l*32768 + packIdxH(h, n,     32)] = __float2half(wr);
    g_WbuH[l*32768 + packIdxH(h, n+128, 32)] = __float2half(wi);
}

__global__ void k_prepW(const float* __restrict__ Cre, const float* __restrict__ Cim,
                        const float* __restrict__ W1, const float* __restrict__ W2)
{
    int i = blockIdx.x*256 + threadIdx.x;        // 65536
    int l = i>>15, rem = i&32767;
    {   // Wc: [k(256)][h(128)]
        int k = rem>>7, h = rem&127;
        float v = (k<128) ? 2.0f*Cre[(l*H+h)*NS + k]
                          : -2.0f*Cim[(l*H+h)*NS + (k-128)];
        g_WcH[l*32768 + packIdxH(k, h, 16)] = __float2half(v);
    }
    {   // W1: [k(128)][n(256)]
        int k = rem>>8, n = rem&255;
        g_W1H[l*32768 + packIdxH(k, n, 32)] = __float2half(W1[i]);
    }
    {   // W2: [k(256)][n(128)]
        int k = rem>>7, n = rem&127;
        g_W2H[l*32768 + packIdxH(k, n, 16)] = __float2half(W2[i]);
    }
}

__global__ void k_prepConv(const float* __restrict__ w1, const float* __restrict__ w2)
{
    int i = blockIdx.x*256 + threadIdx.x;        // 81920
    int co = i & 127, r = i >> 7;                // r = kv*128+ic
    int kv = r >> 7, ic = r & 127;
    int k = kv*128 + ic;
    int d = packIdxH(k, co, 16);
    g_Wc1H[d] = __float2half(w1[(co*H + ic)*5 + kv]);
    g_Wc2H[d] = __float2half(w2[(co*H + ic)*5 + kv]);
}

// ===================== LN1 + Bu GEMM (fp16), Bu -> [B][N][T] half ===================
// 64 rows, 512 threads (16 warps, warp tile 16x64).
#define SM_LNBU (16448*4)
__global__ void __launch_bounds__(512,2) k_ln_bu(const float* __restrict__ xin,
                        const float* __restrict__ g1, const float* __restrict__ b1v, int l)
{
    extern __shared__ uint32_t smem[];
    uint32_t* sa = smem;            // [64][68] half2
    uint32_t  sb = (uint32_t)__cvta_generic_to_shared(smem);
    const float* src = xin ? xin : g_x;
    int tid = threadIdx.x, lane = tid&31, warp = tid>>5;
    int gid = lane>>2, tig = lane&3;
    int row0 = blockIdx.x * 64;
    int b = row0 >> 12, t0 = row0 & (T-1);

    {   // prefetch chunk 0 (4096 words)
        const uint32_t* ws = (const uint32_t*)(g_WbuH + l*32768);
        #pragma unroll
        for (int j=0;j<2;j++){
            int f = tid + j*512, row = f>>4, g = (f&15)*4;
            cpa16(sb + (4352 + row*68 + g)*4, ws + row*64 + g);
        }
        cpcommit();
    }

    // ---- LayerNorm: 16 warps x 4 rows, write half2 pairs ----
    for (int rr = 0; rr < 4; rr++){
        int r = warp*4 + rr;
        int base = (row0 + r) * H;
        float2 p0 = *(const float2*)&src[base + 2*lane];
        float2 p1 = *(const float2*)&src[base + 64 + 2*lane];
        float s  = p0.x+p0.y+p1.x+p1.y;
        float sq = p0.x*p0.x+p0.y*p0.y+p1.x*p1.x+p1.y*p1.y;
        #pragma unroll
        for (int o=16;o>0;o>>=1){ s += __shfl_xor_sync(FULL,s,o); sq += __shfl_xor_sync(FULL,sq,o); }
        float mu = s * (1.0f/128.0f);
        float var = sq * (1.0f/128.0f) - mu*mu;
        float rstd = rsqrtf(var + 1e-5f);
        if (lane == 0){ g_mu[row0+r] = mu; g_rs[row0+r] = rstd; }
        float2 ga = *(const float2*)&g1[l*H + 2*lane];
        float2 ba = *(const float2*)&b1v[l*H + 2*lane];
        float2 gb = *(const float2*)&g1[l*H + 64 + 2*lane];
        float2 bb = *(const float2*)&b1v[l*H + 64 + 2*lane];
        sa[r*68 + lane]      = f2h2((p0.x-mu)*rstd*ga.x + ba.x, (p0.y-mu)*rstd*ga.y + ba.y);
        sa[r*68 + 32 + lane] = f2h2((p1.x-mu)*rstd*gb.x + bb.x, (p1.y-mu)*rstd*gb.y + bb.y);
    }

    int wm = (warp>>2)*16, wn = (warp&3)*64, wnb = (warp&3)*8;
    float acc[8][4];
    #pragma unroll
    for (int nt=0;nt<8;nt++){ acc[nt][0]=acc[nt][1]=acc[nt][2]=acc[nt][3]=0.f; }

    for (int kc=0; kc<4; kc++){
        cpwait0();
        __syncthreads();
        if (kc < 3){
            const uint32_t* ws = (const uint32_t*)(g_WbuH + l*32768) + (kc+1)*4096;
            uint32_t dst = sb + (4352 + ((kc+1)&1)*4352)*4;
            #pragma unroll
            for (int j=0;j<2;j++){
                int f = tid + j*512, row = f>>4, g = (f&15)*4;
                cpa16(dst + (row*68 + g)*4, ws + row*64 + g);
            }
            cpcommit();
        }
        uint32_t* sw = smem + 4352 + (kc&1)*4352;
        #pragma unroll
        for (int ks=0; ks<2; ks++){
            int kp0 = kc*16 + ks*8;
            uint32_t a0 = sa[(wm+gid)*68   + kp0 + tig];
            uint32_t a1 = sa[(wm+gid+8)*68 + kp0 + tig];
            uint32_t a2 = sa[(wm+gid)*68   + kp0 + tig+4];
            uint32_t a3 = sa[(wm+gid+8)*68 + kp0 + tig+4];
            const uint32_t* bw = sw + (ks*32 + gid*4 + tig)*68 + wnb*2;
            #pragma unroll
            for (int nt0=0; nt0<8; nt0+=2){
                uint4 bv = *(const uint4*)(bw + nt0*2);
                mma16(acc[nt0],   a0,a1,a2,a3, bv.x, bv.y);
                mma16(acc[nt0+1], a0,a1,a2,a3, bv.z, bv.w);
            }
        }
    }
    __syncthreads();
    float* so = (float*)smem;    // [64][257]
    #pragma unroll
    for (int nt=0; nt<8; nt++){
        int n = wn + nt*8 + 2*tig;
        so[(wm+gid)*257 + n]     = acc[nt][0];
        so[(wm+gid)*257 + n+1]   = acc[nt][1];
        so[(wm+gid+8)*257 + n]   = acc[nt][2];
        so[(wm+gid+8)*257 + n+1] = acc[nt][3];
    }
    __syncthreads();
    for (int i=0; i<16; i++){
        int n = warp*16 + i;
        int np = n & 127;
        __half* dst = ((n<128) ? g_burH : g_buiH) + (b*NS + np)*T + t0;
        dst[lane]    = __float2half(so[lane*257 + n]);
        dst[lane+32] = __float2half(so[(lane+32)*257 + n]);
    }
}

// ---------------- in-place scan over T (half I/O, fp32 compute) ----------------
__global__ void k_scan(int l)
{
    __shared__ float s_wr[8], s_wi[8], s_er[8], s_ei[8];
    int bid = blockIdx.x;
    int n = bid & (NS-1);
    int tid = threadIdx.x, lane = tid & 31, warp = tid >> 5;
    int base = bid * T + tid * 16;
    float lr = g_lbr[l*NS+n], li = g_lbi[l*NS+n];

    float vr[16], vi[16];
    uint4* pr = (uint4*)(g_burH + base);
    uint4* pi = (uint4*)(g_buiH + base);
    {
        uint4 u0 = pr[0], u1 = pr[1];
        const __half2* h0 = (const __half2*)&u0;
        const __half2* h1 = (const __half2*)&u1;
        #pragma unroll
        for (int q=0;q<4;q++){
            float2 f0 = __half22float2(h0[q]); vr[2*q]=f0.x; vr[2*q+1]=f0.y;
            float2 f1 = __half22float2(h1[q]); vr[8+2*q]=f1.x; vr[8+2*q+1]=f1.y;
        }
        uint4 w0 = pi[0], w1 = pi[1];
        const __half2* g0 = (const __half2*)&w0;
        const __half2* g1_ = (const __half2*)&w1;
        #pragma unroll
        for (int q=0;q<4;q++){
            float2 f0 = __half22float2(g0[q]); vi[2*q]=f0.x; vi[2*q+1]=f0.y;
            float2 f1 = __half22float2(g1_[q]); vi[8+2*q]=f1.x; vi[8+2*q+1]=f1.y;
        }
    }
    float sr=0.f, si=0.f;
    #pragma unroll
    for (int i=0;i<16;i++){
        float tr = lr*sr - li*si + vr[i];
        float ti = lr*si + li*sr + vi[i];
        sr=tr; si=ti;
    }
    float cdr[6], cdi[6];
    {
        float pr_=lr, pi_=li;
        #pragma unroll
        for (int q=0;q<4;q++){ float tr = pr_*pr_ - pi_*pi_; pi_ = 2.f*pr_*pi_; pr_ = tr; }
        cdr[0]=pr_; cdi[0]=pi_;
        #pragma unroll
        for (int q=1;q<6;q++){ float tr = cdr[q-1]*cdr[q-1]-cdi[q-1]*cdi[q-1];
                               cdi[q]=2.f*cdr[q-1]*cdi[q-1]; cdr[q]=tr; }
    }
    float xr=sr, xi=si;
    #pragma unroll
    for (int st=0; st<5; st++){
        int d = 1<<st;
        float or_ = __shfl_up_sync(FULL, xr, d);
        float oi_ = __shfl_up_sync(FULL, xi, d);
        if (lane >= d){
            float tr = cdr[st]*or_ - cdi[st]*oi_ + xr;
            xi = cdr[st]*oi_ + cdi[st]*or_ + xi;
            xr = tr;
        }
    }
    if (lane==31){ s_wr[warp]=xr; s_wi[warp]=xi; }
    __syncthreads();
    if (tid==0){
        float er=0.f, ei=0.f;
        #pragma unroll
        for (int w=0;w<8;w++){
            s_er[w]=er; s_ei[w]=ei;
            float tr = cdr[5]*er - cdi[5]*ei + s_wr[w];
            ei = cdr[5]*ei + cdi[5]*er + s_wi[w];
            er = tr;
        }
    }
    __syncthreads();
    float Er = s_er[warp], Ei = s_ei[warp];
    float plr=1.f, pli=0.f;
    #pragma unroll
    for (int bt=0; bt<5; bt++){
        if (lane & (1<<bt)){
            float tr = plr*cdr[bt] - pli*cdi[bt];
            pli = plr*cdi[bt] + pli*cdr[bt];
            plr = tr;
        }
    }
    float car = plr*Er - pli*Ei;
    float cai = plr*Ei + pli*Er;
    float pvr = __shfl_up_sync(FULL, xr, 1);
    float pvi = __shfl_up_sync(FULL, xi, 1);
    if (lane > 0){ car += pvr; cai += pvi; }
    sr = car; si = cai;
    #pragma unroll
    for (int i=0;i<16;i++){
        float tr = lr*sr - li*si + vr[i];
        float ti = lr*si + li*sr + vi[i];
        sr=tr; si=ti;
        vr[i]=sr; vi[i]=si;
    }
    {
        uint4 u0, u1;
        __half2* h0 = (__half2*)&u0;
        __half2* h1 = (__half2*)&u1;
        #pragma unroll
        for (int q=0;q<4;q++){
            h0[q] = __floats2half2_rn(vr[2*q], vr[2*q+1]);
            h1[q] = __floats2half2_rn(vr[8+2*q], vr[8+2*q+1]);
        }
        pr[0] = u0; pr[1] = u1;
        #pragma unroll
        for (int q=0;q<4;q++){
            h0[q] = __floats2half2_rn(vi[2*q], vi[2*q+1]);
            h1[q] = __floats2half2_rn(vi[8+2*q], vi[8+2*q+1]);
        }
        pi[0] = u0; pi[1] = u1;
    }
}

// ===================== C-mix GEMM (fp16) ============================================
#define SM_CMIX (13824*4)
__global__ void __launch_bounds__(256,3) k_cmix(const float* __restrict__ xin,
                        const float* __restrict__ Dsk,
                        const float* __restrict__ g1, const float* __restrict__ b1v, int l)
{
    extern __shared__ uint32_t smem[];
    uint32_t* saT = smem;             // [128 kp][72] half2 (k-pair major)
    uint32_t  sb = (uint32_t)__cvta_generic_to_shared(smem);
    int tid = threadIdx.x, lane = tid&31, warp = tid>>5;
    int gid = lane>>2, tig = lane&3;
    int row0 = blockIdx.x * 64;
    int b = row0 >> 12, t0 = row0 & (T-1);

    {   // prefetch Wc chunk 0 (2048 words)
        const uint32_t* ws = (const uint32_t*)(g_WcH + l*32768);
        #pragma unroll
        for (int j=0;j<2;j++){
            int f = tid + j*256, row = f>>3, g = (f&7)*4;
            cpa16(sb + (9216 + row*36 + g)*4, ws + row*32 + g);
        }
        cpcommit();
    }

    // stage xs (real|imag) as half2 k-pairs, k-major (direct half loads)
    for (int e=tid; e<8192; e+=256){
        int kp = e>>6, r = e&63;
        int k2 = 2*kp;
        const __half* sp = (k2<128) ? (g_burH + (b*NS+k2)*T + t0)
                                    : (g_buiH + (b*NS + (k2-128))*T + t0);
        __half2 h = __halves2half2(sp[r], sp[T + r]);
        saT[kp*72 + r] = *(uint32_t*)&h;
    }

    int wm = (warp>>1)*16, wn = (warp&1)*64, wnb = (warp&1)*8;
    float acc[8][4];
    #pragma unroll
    for (int nt=0;nt<8;nt++){ acc[nt][0]=acc[nt][1]=acc[nt][2]=acc[nt][3]=0.f; }

    for (int kc=0; kc<8; kc++){
        cpwait0();
        __syncthreads();
        if (kc < 7){
            const uint32_t* ws = (const uint32_t*)(g_WcH + l*32768) + (kc+1)*2048;
            uint32_t dst = sb + (9216 + ((kc+1)&1)*2304)*4;
            #pragma unroll
            for (int j=0;j<2;j++){
                int f = tid + j*256, row = f>>3, g = (f&7)*4;
                cpa16(dst + (row*36 + g)*4, ws + row*32 + g);
            }
            cpcommit();
        }
        uint32_t* sw = smem + 9216 + (kc&1)*2304;
        #pragma unroll
        for (int ks=0; ks<2; ks++){
            int kp0 = kc*16 + ks*8;
            uint32_t a0 = saT[(kp0+tig)*72   + wm+gid];
            uint32_t a1 = saT[(kp0+tig)*72   + wm+gid+8];
            uint32_t a2 = saT[(kp0+tig+4)*72 + wm+gid];
            uint32_t a3 = saT[(kp0+tig+4)*72 + wm+gid+8];
            const uint32_t* bw = sw + (ks*32 + gid*4 + tig)*36 + wnb*2;
            #pragma unroll
            for (int nt0=0; nt0<8; nt0+=2){
                uint4 bv = *(const uint4*)(bw + nt0*2);
                mma16(acc[nt0],   a0,a1,a2,a3, bv.x, bv.y);
                mma16(acc[nt0+1], a0,a1,a2,a3, bv.z, bv.w);
            }
        }
    }
    __syncthreads();
    float* so = (float*)smem;   // [64][132]
    #pragma unroll
    for (int nt=0; nt<8; nt++){
        int n = wn + nt*8 + 2*tig;
        so[(wm+gid)*132 + n]     = acc[nt][0];
        so[(wm+gid)*132 + n+1]   = acc[nt][1];
        so[(wm+gid+8)*132 + n]   = acc[nt][2];
        so[(wm+gid+8)*132 + n+1] = acc[nt][3];
    }
    __syncthreads();
    const float* res = xin ? xin : g_x;
    for (int e=tid; e<8192; e+=256){
        int h = e&127, r = e>>7;
        int gi = (row0+r)*H + h;
        float xv = res[gi];
        float xn = (xv - g_mu[row0+r])*g_rs[row0+r]*g1[l*H+h] + b1v[l*H+h];
        g_x[gi] = xv + so[r*132+h] + xn*Dsk[l*H+h];
    }
}

// ===================== LN2 + MLP (fp16), M=64, 512 threads ==========================
#define SM_MLP (21504*4)
__global__ void __launch_bounds__(512,2) k_mlp(const float* __restrict__ g2,
                      const float* __restrict__ b2v,
                      const float* __restrict__ b1v, const float* __restrict__ b2o, int l)
{
    extern __shared__ uint32_t smem[];
    uint32_t* sa = smem;                     // [64][68] half2
    uint32_t* sh = smem + 4352;              // [64][132] half2 (128 kp + pad)
    uint32_t  sb = (uint32_t)__cvta_generic_to_shared(smem);
    uint32_t  wb = sb + 12800*4;
    int tid = threadIdx.x, lane = tid&31, warp = tid>>5;
    int gid = lane>>2, tig = lane&3;
    int row0 = blockIdx.x * 64;

    {   // prefetch W1 chunk 0 (4096 words)
        const uint32_t* ws = (const uint32_t*)(g_W1H + l*32768);
        #pragma unroll
        for (int j=0;j<2;j++){
            int f = tid + j*512, row = f>>4, g = (f&15)*4;
            cpa16(wb + (row*68 + g)*4, ws + row*64 + g);
        }
        cpcommit();
    }

    // LN2: 16 warps x 4 rows
    for (int rr=0; rr<4; rr++){
        int r = warp*4 + rr;
        int base = (row0+r)*H;
        float2 p0 = *(const float2*)&g_x[base + 2*lane];
        float2 p1 = *(const float2*)&g_x[base + 64 + 2*lane];
        float s  = p0.x+p0.y+p1.x+p1.y;
        float sq = p0.x*p0.x+p0.y*p0.y+p1.x*p1.x+p1.y*p1.y;
        #pragma unroll
        for (int o=16;o>0;o>>=1){ s += __shfl_xor_sync(FULL,s,o); sq += __shfl_xor_sync(FULL,sq,o); }
        float mu = s * (1.0f/128.0f);
        float var = sq * (1.0f/128.0f) - mu*mu;
        float rstd = rsqrtf(var + 1e-5f);
        float2 ga = *(const float2*)&g2[l*H + 2*lane];
        float2 ba = *(const float2*)&b2v[l*H + 2*lane];
        float2 gb = *(const float2*)&g2[l*H + 64 + 2*lane];
        float2 bb = *(const float2*)&b2v[l*H + 64 + 2*lane];
        sa[r*68 + lane]      = f2h2((p0.x-mu)*rstd*ga.x + ba.x, (p0.y-mu)*rstd*ga.y + ba.y);
        sa[r*68 + 32 + lane] = f2h2((p1.x-mu)*rstd*gb.x + bb.x, (p1.y-mu)*rstd*gb.y + bb.y);
    }

    // ---- GEMM1: [64x128] @ [128x256] ----
    int wm = (warp>>2)*16, wn = (warp&3)*64, wnb = (warp&3)*8;
    float acc[8][4];
    #pragma unroll
    for (int nt=0;nt<8;nt++){ acc[nt][0]=acc[nt][1]=acc[nt][2]=acc[nt][3]=0.f; }
    for (int kc=0; kc<4; kc++){
        cpwait0();
        __syncthreads();
        if (kc < 3){
            const uint32_t* ws = (const uint32_t*)(g_W1H + l*32768) + (kc+1)*4096;
            uint32_t dst = wb + (((kc+1)&1)*4352)*4;
            #pragma unroll
            for (int j=0;j<2;j++){
                int f = tid + j*512, row = f>>4, g = (f&15)*4;
                cpa16(dst + (row*68 + g)*4, ws + row*64 + g);
            }
            cpcommit();
        }
        uint32_t* sw = smem + 12800 + (kc&1)*4352;
        #pragma unroll
        for (int ks=0; ks<2; ks++){
            int kp0 = kc*16 + ks*8;
            uint32_t a0 = sa[(wm+gid)*68   + kp0 + tig];
            uint32_t a1 = sa[(wm+gid+8)*68 + kp0 + tig];
            uint32_t a2 = sa[(wm+gid)*68   + kp0 + tig+4];
            uint32_t a3 = sa[(wm+gid+8)*68 + kp0 + tig+4];
            const uint32_t* bw = sw + (ks*32 + gid*4 + tig)*68 + wnb*2;
            #pragma unroll
            for (int nt0=0; nt0<8; nt0+=2){
                uint4 bv = *(const uint4*)(bw + nt0*2);
                mma16(acc[nt0],   a0,a1,a2,a3, bv.x, bv.y);
                mma16(acc[nt0+1], a0,a1,a2,a3, bv.z, bv.w);
            }
        }
    }
    // prefetch W2 chunk 0 into buf0 (safe: buf0 dead since kc=3 sync)
    {
        const uint32_t* ws = (const uint32_t*)(g_W2H + l*32768);
        {
            int f = tid, row = f>>3, g = (f&7)*4;   // 2048 words, 512 ops
            cpa16(wb + (row*36 + g)*4, ws + row*32 + g);
        }
        cpcommit();
    }
    // bias + gelu -> sh (half2)
    #pragma unroll
    for (int nt=0; nt<8; nt++){
        int n = wn + nt*8 + 2*tig;
        float bb0 = b1v[l*256 + n], bb1 = b1v[l*256 + n + 1];
        float x0 = acc[nt][0]+bb0, x1 = acc[nt][1]+bb1;
        float x2 = acc[nt][2]+bb0, x3 = acc[nt][3]+bb1;
        int c = n>>1;
        sh[(wm+gid)*132 + c]   = f2h2(0.5f*x0*(1.0f+erff(x0*0.70710678118f)),
                                      0.5f*x1*(1.0f+erff(x1*0.70710678118f)));
        sh[(wm+gid+8)*132 + c] = f2h2(0.5f*x2*(1.0f+erff(x2*0.70710678118f)),
                                      0.5f*x3*(1.0f+erff(x3*0.70710678118f)));
    }

    // ---- GEMM2: [64x256] @ [256x128] ----
    int wn2 = (warp&3)*32, wnb2 = (warp&3)*4;
    float acc2[4][4];
    #pragma unroll
    for (int nt=0;nt<4;nt++){ acc2[nt][0]=acc2[nt][1]=acc2[nt][2]=acc2[nt][3]=0.f; }
    for (int kc=0; kc<8; kc++){
        cpwait0();
        __syncthreads();
        if (kc < 7){
            const uint32_t* ws = (const uint32_t*)(g_W2H + l*32768) + (kc+1)*2048;
            uint32_t dst = wb + (((kc+1)&1)*4352)*4;
            {
                int f = tid, row = f>>3, g = (f&7)*4;
                cpa16(dst + (row*36 + g)*4, ws + row*32 + g);
            }
            cpcommit();
        }
        uint32_t* sw = smem + 12800 + (kc&1)*4352;
        #pragma unroll
        for (int ks=0; ks<2; ks++){
            int kp0 = kc*16 + ks*8;
            uint32_t a0 = sh[(wm+gid)*132   + kp0 + tig];
            uint32_t a1 = sh[(wm+gid+8)*132 + kp0 + tig];
            uint32_t a2 = sh[(wm+gid)*132   + kp0 + tig+4];
            uint32_t a3 = sh[(wm+gid+8)*132 + kp0 + tig+4];
            const uint32_t* bw = sw + (ks*32 + gid*4 + tig)*36 + wnb2*2;
            #pragma unroll
            for (int nt0=0; nt0<4; nt0+=2){
                uint4 bv = *(const uint4*)(bw + nt0*2);
                mma16(acc2[nt0],   a0,a1,a2,a3, bv.x, bv.y);
                mma16(acc2[nt0+1], a0,a1,a2,a3, bv.z, bv.w);
            }
        }
    }
    __syncthreads();
    float* so = (float*)smem;    // [64][132] floats (overlays sa+sh, both dead)
    #pragma unroll
    for (int nt=0; nt<4; nt++){
        int n = wn2 + nt*8 + 2*tig;
        so[(wm+gid)*132 + n]     = acc2[nt][0];
        so[(wm+gid)*132 + n+1]   = acc2[nt][1];
        so[(wm+gid+8)*132 + n]   = acc2[nt][2];
        so[(wm+gid+8)*132 + n+1] = acc2[nt][3];
    }
    __syncthreads();
    for (int e=tid; e<8192; e+=512){
        int h = e&127, r = e>>7;
        int gi = (row0+r)*H + h;
        g_x[gi] = g_x[gi] + so[r*132+h] + b2o[l*H+h];
    }
}

// ===================== conv1 as fp16 GEMM (K=640), output half ======================
#define SM_CONV (13780*4)
__global__ void __launch_bounds__(256,3) k_conv1(const float* __restrict__ bc1)
{
    extern __shared__ uint32_t smem[];
    uint32_t* sx = smem;
    uint32_t  sb = (uint32_t)__cvta_generic_to_shared(smem);
    int tid = threadIdx.x, lane = tid&31, warp = tid>>5;
    int gid = lane>>2, tig = lane&3;
    int b = blockIdx.x >> 5;
    int ip0 = (blockIdx.x & 31) * 64;
    int t0 = 2*ip0 - 2;

    {
        const uint32_t* ws = (const uint32_t*)g_Wc1H;
        #pragma unroll
        for (int j=0;j<2;j++){
            int f = tid + j*256, row = f>>3, g = (f&7)*4;
            cpa16(sb + (9172 + row*36 + g)*4, ws + row*32 + g);
        }
        cpcommit();
    }
    for (int e=tid; e<131*64; e+=256){
        int t = e>>6, icp = e&63;
        int tg = t0 + t;
        float v0 = 0.f, v1 = 0.f;
        if (tg>=0 && tg<T){
            float2 p = *(const float2*)&g_x[(b*T+tg)*H + 2*icp];
            v0 = p.x; v1 = p.y;
        }
        sx[t*70 + icp] = f2h2(v0, v1);
    }

    int wm = (warp>>1)*16, wn = (warp&1)*64, wnb = (warp&1)*8;
    float acc[8][4];
    #pragma unroll
    for (int nt=0;nt<8;nt++){ acc[nt][0]=acc[nt][1]=acc[nt][2]=acc[nt][3]=0.f; }

    for (int c=0; c<20; c++){
        cpwait0();
        __syncthreads();
        if (c < 19){
            const uint32_t* ws = (const uint32_t*)g_Wc1H + (c+1)*2048;
            uint32_t dst = sb + (9172 + ((c+1)&1)*2304)*4;
            #pragma unroll
            for (int j=0;j<2;j++){
                int f = tid + j*256, row = f>>3, g = (f&7)*4;
                cpa16(dst + (row*36 + g)*4, ws + row*32 + g);
            }
            cpcommit();
        }
        uint32_t* sw = smem + 9172 + (c&1)*2304;
        int kv = c>>2, icpb = (c&3)*16;
        #pragma unroll
        for (int ks=0; ks<2; ks++){
            int icp0 = icpb + ks*8;
            uint32_t a0 = sx[(2*(wm+gid)+kv)*70   + icp0 + tig];
            uint32_t a1 = sx[(2*(wm+gid+8)+kv)*70 + icp0 + tig];
            uint32_t a2 = sx[(2*(wm+gid)+kv)*70   + icp0 + tig+4];
            uint32_t a3 = sx[(2*(wm+gid+8)+kv)*70 + icp0 + tig+4];
            const uint32_t* bw = sw + (ks*32 + gid*4 + tig)*36 + wnb*2;
            #pragma unroll
            for (int nt0=0; nt0<8; nt0+=2){
                uint4 bv = *(const uint4*)(bw + nt0*2);
                mma16(acc[nt0],   a0,a1,a2,a3, bv.x, bv.y);
                mma16(acc[nt0+1], a0,a1,a2,a3, bv.z, bv.w);
            }
        }
    }
    __syncthreads();
    float* so = (float*)smem;   // [64][132]
    #pragma unroll
    for (int nt=0; nt<8; nt++){
        int n = wn + nt*8 + 2*tig;
        so[(wm+gid)*132 + n]     = acc[nt][0];
        so[(wm+gid)*132 + n+1]   = acc[nt][1];
        so[(wm+gid+8)*132 + n]   = acc[nt][2];
        so[(wm+gid+8)*132 + n+1] = acc[nt][3];
    }
    __syncthreads();
    for (int e=tid; e<8192; e+=256){
        int r = e>>7, co = e&127;
        g_y1H[(b*T2 + ip0 + r)*H + co] =
            __float2half(fmaxf(so[r*132+co] + bc1[co], 0.0f));
    }
}

// ===================== conv2 + fused pool ===========================================
__global__ void __launch_bounds__(256,3) k_conv2pool(const float* __restrict__ bc2,
                                                     float* __restrict__ out)
{
    extern __shared__ uint32_t smem[];
    uint32_t* sx = smem;
    uint32_t  sb = (uint32_t)__cvta_generic_to_shared(smem);
    int tid = threadIdx.x, lane = tid&31, warp = tid>>5;
    int gid = lane>>2, tig = lane&3;
    int b = blockIdx.x >> 4;
    int tile = blockIdx.x & 15;
    int jp0 = tile * 64;
    int t0 = 2*jp0 - 2;

    {
        const uint32_t* ws = (const uint32_t*)g_Wc2H;
        #pragma unroll
        for (int j=0;j<2;j++){
            int f = tid + j*256, row = f>>3, g = (f&7)*4;
            cpa16(sb + (9172 + row*36 + g)*4, ws + row*32 + g);
        }
        cpcommit();
    }
    for (int e=tid; e<131*64; e+=256){
        int t = e>>6, icp = e&63;
        int tg = t0 + t;
        uint32_t w = 0;
        if (tg>=0 && tg<T2) w = *(const uint32_t*)&g_y1H[(b*T2+tg)*H + 2*icp];
        sx[t*70 + icp] = w;
    }

    int wm = (warp>>1)*16, wn = (warp&1)*64, wnb = (warp&1)*8;
    float acc[8][4];
    #pragma unroll
    for (int nt=0;nt<8;nt++){ acc[nt][0]=acc[nt][1]=acc[nt][2]=acc[nt][3]=0.f; }

    for (int c=0; c<20; c++){
        cpwait0();
        __syncthreads();
        if (c < 19){
            const uint32_t* ws = (const uint32_t*)g_Wc2H + (c+1)*2048;
            uint32_t dst = sb + (9172 + ((c+1)&1)*2304)*4;
            #pragma unroll
            for (int j=0;j<2;j++){
                int f = tid + j*256, row = f>>3, g = (f&7)*4;
                cpa16(dst + (row*36 + g)*4, ws + row*32 + g);
            }
            cpcommit();
        }
        uint32_t* sw = smem + 9172 + (c&1)*2304;
        int kv = c>>2, icpb = (c&3)*16;
        #pragma unroll
        for (int ks=0; ks<2; ks++){
            int icp0 = icpb + ks*8;
            uint32_t a0 = sx[(2*(wm+gid)+kv)*70   + icp0 + tig];
            uint32_t a1 = sx[(2*(wm+gid+8)+kv)*70 + icp0 + tig];
            uint32_t a2 = sx[(2*(wm+gid)+kv)*70   + icp0 + tig+4];
            uint32_t a3 = sx[(2*(wm+gid+8)+kv)*70 + icp0 + tig+4];
            const uint32_t* bw = sw + (ks*32 + gid*4 + tig)*36 + wnb*2;
            #pragma unroll
            for (int nt0=0; nt0<8; nt0+=2){
                uint4 bv = *(const uint4*)(bw + nt0*2);
                mma16(acc[nt0],   a0,a1,a2,a3, bv.x, bv.y);
                mma16(acc[nt0+1], a0,a1,a2,a3, bv.z, bv.w);
            }
        }
    }
    __syncthreads();
    float* so = (float*)smem;   // [64][132]
    #pragma unroll
    for (int nt=0; nt<8; nt++){
        int n = wn + nt*8 + 2*tig;
        so[(wm+gid)*132 + n]     = acc[nt][0];
        so[(wm+gid)*132 + n+1]   = acc[nt][1];
        so[(wm+gid+8)*132 + n]   = acc[nt][2];
        so[(wm+gid+8)*132 + n+1] = acc[nt][3];
    }
    __syncthreads();
    {
        int co = tid & 127, half = tid >> 7;
        float bias = bc2[co];
        float s0 = 0.f, s1 = 0.f;
        #pragma unroll
        for (int i=0;i<16;i++) s0 += fmaxf(so[(half*32+i)*132+co] + bias, 0.0f);
        #pragma unroll
        for (int i=16;i<32;i++) s1 += fmaxf(so[(half*32+i)*132+co] + bias, 0.0f);
        int d = tile*4 + half*2;
        out[(b*H+co)*DOUT + d]     = s0 * (1.0f/16.0f);
        out[(b*H+co)*DOUT + d + 1] = s1 * (1.0f/16.0f);
    }
}

// ---------------- launch ----------------
extern "C" void kernel_launch(void* const* d_in, const int* in_sizes, int n_in,
                              void* d_out, int out_size)
{
    (void)in_sizes; (void)n_in; (void)out_size;
    const float* x    = (const float*)d_in[0];
    const float* ln1g = (const float*)d_in[1];
    const float* ln1b = (const float*)d_in[2];
    const float* ln2g = (const float*)d_in[3];
    const float* ln2b = (const float*)d_in[4];
    const float* lre  = (const float*)d_in[5];
    const float* lim  = (const float*)d_in[6];
    const float* Bre  = (const float*)d_in[7];
    const float* Bim  = (const float*)d_in[8];
    const float* Cre  = (const float*)d_in[9];
    const float* Cim  = (const float*)d_in[10];
    const float* Dsk  = (const float*)d_in[11];
    const float* lstep= (const float*)d_in[12];
    const float* W1   = (const float*)d_in[13];
    const float* b1   = (const float*)d_in[14];
    const float* W2   = (const float*)d_in[15];
    const float* b2   = (const float*)d_in[16];
    const float* c1w  = (const float*)d_in[17];
    const float* c1b  = (const float*)d_in[18];
    const float* c2w  = (const float*)d_in[19];
    const float* c2b  = (const float*)d_in[20];
    float* out = (float*)d_out;

    cudaFuncSetAttribute(k_ln_bu,     cudaFuncAttributeMaxDynamicSharedMemorySize, SM_LNBU);
    cudaFuncSetAttribute(k_cmix,      cudaFuncAttributeMaxDynamicSharedMemorySize, SM_CMIX);
    cudaFuncSetAttribute(k_mlp,       cudaFuncAttributeMaxDynamicSharedMemorySize, SM_MLP);
    cudaFuncSetAttribute(k_conv1,     cudaFuncAttributeMaxDynamicSharedMemorySize, SM_CONV);
    cudaFuncSetAttribute(k_conv2pool, cudaFuncAttributeMaxDynamicSharedMemorySize, SM_CONV);

    k_prep<<<DEPTH*NS, H>>>(lre, lim, Bre, Bim, lstep);
    k_prepW<<<256, 256>>>(Cre, Cim, W1, W2);
    k_prepConv<<<320, 256>>>(c1w, c2w);
    for (int l=0;l<DEPTH;l++){
        const float* xin = (l==0) ? x : nullptr;
        k_ln_bu<<<TT/64, 512, SM_LNBU>>>(xin, ln1g, ln1b, l);
        k_scan<<<BATCH*NS, 256>>>(l);
        k_cmix<<<TT/64, 256, SM_CMIX>>>(xin, Dsk, ln1g, ln1b, l);
        k_mlp<<<TT/64, 512, SM_MLP>>>(ln2g, ln2b, b1, b2, l);
    }
    k_conv1<<<BATCH*32, 256, SM_CONV>>>(c1b);
    k_conv2pool<<<BATCH*16, 256, SM_CONV>>>(c2b, out);
}

// round 15
// speedup vs baseline: 6.7980x; 1.0547x over previous
#include <cuda_runtime.h>
#include <cuda_fp16.h>
#include <math.h>
#include <stdint.h>

#define BATCH 32
#define T 4096
#define H 128
#define NS 128
#define DEPTH 2
#define TT (BATCH*T)
#define T2 2048
#define DOUT 64
#define FULL 0xFFFFFFFFu

// ---------------- scratch ----------------
__device__ float g_x  [TT*H];
__device__ float g_mu [TT];
__device__ float g_rs [TT];
__device__ __half g_burH[BATCH*NS*T];
__device__ __half g_buiH[BATCH*NS*T];
__device__ __half g_y1H [BATCH*T2*H];
__device__ float g_lbr[DEPTH*NS], g_lbi[DEPTH*NS];
// packed (m16n8k16 fragment order) fp16 weights
__device__ __half g_WbuH[DEPTH*32768];  // K=128,N=256
__device__ __half g_WcH [DEPTH*32768];  // K=256,N=128
__device__ __half g_W1H [DEPTH*32768];  // K=128,N=256
__device__ __half g_W2H [DEPTH*32768];  // K=256,N=128
__device__ __half g_Wc1H[81920];        // K=640,N=128
__device__ __half g_Wc2H[81920];

// ---------------- helpers ----------------
__device__ __forceinline__ uint32_t f2h2(float lo, float hi){
    __half2 h = __floats2half2_rn(lo, hi);
    return *(uint32_t*)&h;
}
__device__ __forceinline__ void mma16(float* c, uint32_t a0,uint32_t a1,uint32_t a2,uint32_t a3,
                                      uint32_t b0,uint32_t b1){
    asm volatile("mma.sync.aligned.m16n8k16.row.col.f32.f16.f16.f32 "
        "{%0,%1,%2,%3},{%4,%5,%6,%7},{%8,%9},{%0,%1,%2,%3};"
        : "+f"(c[0]),"+f"(c[1]),"+f"(c[2]),"+f"(c[3])
        : "r"(a0),"r"(a1),"r"(a2),"r"(a3),"r"(b0),"r"(b1));
}
__device__ __forceinline__ void cpa16(uint32_t s, const void* g){
    asm volatile("cp.async.cg.shared.global [%0], [%1], 16;" :: "r"(s), "l"(g));
}
__device__ __forceinline__ void cpcommit(){ asm volatile("cp.async.commit_group;" ::: "memory"); }
__device__ __forceinline__ void cpwait0(){ asm volatile("cp.async.wait_group 0;" ::: "memory"); }

// fp16 fragment-order packed half index, k chunks of 16, NT = N/8
__device__ __forceinline__ int packIdxH(int k, int n, int NT){
    int k16 = k>>4, r = k&15;
    int tig = (r>>1)&3, hi = (r>>3)&1, lo = r&1;
    int row = k16*32 + (n&7)*4 + tig;
    return ((row*(2*NT) + (n>>3)*2 + hi)<<1) | lo;
}

// ---------------- param prep ----------------
__global__ void k_prep(const float* __restrict__ lre, const float* __restrict__ lim,
                       const float* __restrict__ Bre, const float* __restrict__ Bim,
                       const float* __restrict__ lstep)
{
    int idx = blockIdx.x;               // l*NS + n
    int l = idx >> 7, n = idx & 127;
    float lr = lre[idx], li = lim[idx];
    float dt = expf(lstep[idx]);
    float er = expf(lr*dt);
    float lbr = er * cosf(li*dt);
    float lbi = er * sinf(li*dt);
    if (threadIdx.x == 0){ g_lbr[idx]=lbr; g_lbi[idx]=lbi; }
    float den = lr*lr + li*li;
    float nr = lbr - 1.0f, ni = lbi;
    float fr = (nr*lr + ni*li)/den;
    float fi = (ni*lr - nr*li)/den;
    int h = threadIdx.x;
    float br = Bre[idx*H + h], bi = Bim[idx*H + h];
    float wr = fr*br - fi*bi;
    float wi = fr*bi + fi*br;
    g_WbuH[l*32768 + packIdxH(h, n,     32)] = __float2half(wr);
    g_WbuH[l*32768 + packIdxH(h, n+128, 32)] = __float2half(wi);
}

__global__ void k_prepW(const float* __restrict__ Cre, const float* __restrict__ Cim,
                        const float* __restrict__ W1, const float* __restrict__ W2)
{
    int i = blockIdx.x*256 + threadIdx.x;        // 65536
    int l = i>>15, rem = i&32767;
    {   // Wc: [k(256)][h(128)]
        int k = rem>>7, h = rem&127;
        float v = (k<128) ? 2.0f*Cre[(l*H+h)*NS + k]
                          : -2.0f*Cim[(l*H+h)*NS + (k-128)];
        g_WcH[l*32768 + packIdxH(k, h, 16)] = __float2half(v);
    }
    {   // W1: [k(128)][n(256)]
        int k = rem>>8, n = rem&255;
        g_W1H[l*32768 + packIdxH(k, n, 32)] = __float2half(W1[i]);
    }
    {   // W2: [k(256)][n(128)]
        int k = rem>>7, n = rem&127;
        g_W2H[l*32768 + packIdxH(k, n, 16)] = __float2half(W2[i]);
    }
}

__global__ void k_prepConv(const float* __restrict__ w1, const float* __restrict__ w2)
{
    int i = blockIdx.x*256 + threadIdx.x;        // 81920
    int co = i & 127, r = i >> 7;                // r = kv*128+ic
    int kv = r >> 7, ic = r & 127;
    int k = kv*128 + ic;
    int d = packIdxH(k, co, 16);
    g_Wc1H[d] = __float2half(w1[(co*H + ic)*5 + kv]);
    g_Wc2H[d] = __float2half(w2[(co*H + ic)*5 + kv]);
}

// ===================== LN1 + Bu GEMM (fp16), Bu -> [B][N][T] half ===================
// 64 rows, 512 threads (16 warps, warp tile 16x64).
#define SM_LNBU (16448*4)
__global__ void __launch_bounds__(512,2) k_ln_bu(const float* __restrict__ xin,
                        const float* __restrict__ g1, const float* __restrict__ b1v, int l)
{
    extern __shared__ uint32_t smem[];
    uint32_t* sa = smem;            // [64][68] half2
    uint32_t  sb = (uint32_t)__cvta_generic_to_shared(smem);
    const float* src = xin ? xin : g_x;
    int tid = threadIdx.x, lane = tid&31, warp = tid>>5;
    int gid = lane>>2, tig = lane&3;
    int row0 = blockIdx.x * 64;
    int b = row0 >> 12, t0 = row0 & (T-1);

    {   // prefetch chunk 0 (4096 words)
        const uint32_t* ws = (const uint32_t*)(g_WbuH + l*32768);
        #pragma unroll
        for (int j=0;j<2;j++){
            int f = tid + j*512, row = f>>4, g = (f&15)*4;
            cpa16(sb + (4352 + row*68 + g)*4, ws + row*64 + g);
        }
        cpcommit();
    }

    // ---- LayerNorm: 16 warps x 4 rows, write half2 pairs ----
    for (int rr = 0; rr < 4; rr++){
        int r = warp*4 + rr;
        int base = (row0 + r) * H;
        float2 p0 = *(const float2*)&src[base + 2*lane];
        float2 p1 = *(const float2*)&src[base + 64 + 2*lane];
        float s  = p0.x+p0.y+p1.x+p1.y;
        float sq = p0.x*p0.x+p0.y*p0.y+p1.x*p1.x+p1.y*p1.y;
        #pragma unroll
        for (int o=16;o>0;o>>=1){ s += __shfl_xor_sync(FULL,s,o); sq += __shfl_xor_sync(FULL,sq,o); }
        float mu = s * (1.0f/128.0f);
        float var = sq * (1.0f/128.0f) - mu*mu;
        float rstd = rsqrtf(var + 1e-5f);
        if (lane == 0){ g_mu[row0+r] = mu; g_rs[row0+r] = rstd; }
        float2 ga = *(const float2*)&g1[l*H + 2*lane];
        float2 ba = *(const float2*)&b1v[l*H + 2*lane];
        float2 gb = *(const float2*)&g1[l*H + 64 + 2*lane];
        float2 bb = *(const float2*)&b1v[l*H + 64 + 2*lane];
        sa[r*68 + lane]      = f2h2((p0.x-mu)*rstd*ga.x + ba.x, (p0.y-mu)*rstd*ga.y + ba.y);
        sa[r*68 + 32 + lane] = f2h2((p1.x-mu)*rstd*gb.x + bb.x, (p1.y-mu)*rstd*gb.y + bb.y);
    }

    int wm = (warp>>2)*16, wn = (warp&3)*64, wnb = (warp&3)*8;
    float acc[8][4];
    #pragma unroll
    for (int nt=0;nt<8;nt++){ acc[nt][0]=acc[nt][1]=acc[nt][2]=acc[nt][3]=0.f; }

    for (int kc=0; kc<4; kc++){
        cpwait0();
        __syncthreads();
        if (kc < 3){
            const uint32_t* ws = (const uint32_t*)(g_WbuH + l*32768) + (kc+1)*4096;
            uint32_t dst = sb + (4352 + ((kc+1)&1)*4352)*4;
            #pragma unroll
            for (int j=0;j<2;j++){
                int f = tid + j*512, row = f>>4, g = (f&15)*4;
                cpa16(dst + (row*68 + g)*4, ws + row*64 + g);
            }
            cpcommit();
        }
        uint32_t* sw = smem + 4352 + (kc&1)*4352;
        #pragma unroll
        for (int ks=0; ks<2; ks++){
            int kp0 = kc*16 + ks*8;
            uint32_t a0 = sa[(wm+gid)*68   + kp0 + tig];
            uint32_t a1 = sa[(wm+gid+8)*68 + kp0 + tig];
            uint32_t a2 = sa[(wm+gid)*68   + kp0 + tig+4];
            uint32_t a3 = sa[(wm+gid+8)*68 + kp0 + tig+4];
            const uint32_t* bw = sw + (ks*32 + gid*4 + tig)*68 + wnb*2;
            #pragma unroll
            for (int nt0=0; nt0<8; nt0+=2){
                uint4 bv = *(const uint4*)(bw + nt0*2);
                mma16(acc[nt0],   a0,a1,a2,a3, bv.x, bv.y);
                mma16(acc[nt0+1], a0,a1,a2,a3, bv.z, bv.w);
            }
        }
    }
    __syncthreads();
    float* so = (float*)smem;    // [64][257]
    #pragma unroll
    for (int nt=0; nt<8; nt++){
        int n = wn + nt*8 + 2*tig;
        so[(wm+gid)*257 + n]     = acc[nt][0];
        so[(wm+gid)*257 + n+1]   = acc[nt][1];
        so[(wm+gid+8)*257 + n]   = acc[nt][2];
        so[(wm+gid+8)*257 + n+1] = acc[nt][3];
    }
    __syncthreads();
    // vectorized transpose-store: each lane packs t-pair (2*lane, 2*lane+1) -> STG.32
    for (int i=0; i<16; i++){
        int n = warp*16 + i;
        int np = n & 127;
        __half* dst = ((n<128) ? g_burH : g_buiH) + (b*NS + np)*T + t0;
        float v0 = so[(2*lane)*257 + n];
        float v1 = so[(2*lane+1)*257 + n];
        *(uint32_t*)&dst[2*lane] = f2h2(v0, v1);
    }
}

// ---------------- in-place scan over T (half I/O, fp32 compute) ----------------
__global__ void k_scan(int l)
{
    __shared__ float s_wr[8], s_wi[8], s_er[8], s_ei[8];
    int bid = blockIdx.x;
    int n = bid & (NS-1);
    int tid = threadIdx.x, lane = tid & 31, warp = tid >> 5;
    int base = bid * T + tid * 16;
    float lr = g_lbr[l*NS+n], li = g_lbi[l*NS+n];

    float vr[16], vi[16];
    uint4* pr = (uint4*)(g_burH + base);
    uint4* pi = (uint4*)(g_buiH + base);
    {
        uint4 u0 = pr[0], u1 = pr[1];
        const __half2* h0 = (const __half2*)&u0;
        const __half2* h1 = (const __half2*)&u1;
        #pragma unroll
        for (int q=0;q<4;q++){
            float2 f0 = __half22float2(h0[q]); vr[2*q]=f0.x; vr[2*q+1]=f0.y;
            float2 f1 = __half22float2(h1[q]); vr[8+2*q]=f1.x; vr[8+2*q+1]=f1.y;
        }
        uint4 w0 = pi[0], w1 = pi[1];
        const __half2* g0 = (const __half2*)&w0;
        const __half2* g1_ = (const __half2*)&w1;
        #pragma unroll
        for (int q=0;q<4;q++){
            float2 f0 = __half22float2(g0[q]); vi[2*q]=f0.x; vi[2*q+1]=f0.y;
            float2 f1 = __half22float2(g1_[q]); vi[8+2*q]=f1.x; vi[8+2*q+1]=f1.y;
        }
    }
    float sr=0.f, si=0.f;
    #pragma unroll
    for (int i=0;i<16;i++){
        float tr = lr*sr - li*si + vr[i];
        float ti = lr*si + li*sr + vi[i];
        sr=tr; si=ti;
    }
    float cdr[6], cdi[6];
    {
        float pr_=lr, pi_=li;
        #pragma unroll
        for (int q=0;q<4;q++){ float tr = pr_*pr_ - pi_*pi_; pi_ = 2.f*pr_*pi_; pr_ = tr; }
        cdr[0]=pr_; cdi[0]=pi_;
        #pragma unroll
        for (int q=1;q<6;q++){ float tr = cdr[q-1]*cdr[q-1]-cdi[q-1]*cdi[q-1];
                               cdi[q]=2.f*cdr[q-1]*cdi[q-1]; cdr[q]=tr; }
    }
    float xr=sr, xi=si;
    #pragma unroll
    for (int st=0; st<5; st++){
        int d = 1<<st;
        float or_ = __shfl_up_sync(FULL, xr, d);
        float oi_ = __shfl_up_sync(FULL, xi, d);
        if (lane >= d){
            float tr = cdr[st]*or_ - cdi[st]*oi_ + xr;
            xi = cdr[st]*oi_ + cdi[st]*or_ + xi;
            xr = tr;
        }
    }
    if (lane==31){ s_wr[warp]=xr; s_wi[warp]=xi; }
    __syncthreads();
    if (tid==0){
        float er=0.f, ei=0.f;
        #pragma unroll
        for (int w=0;w<8;w++){
            s_er[w]=er; s_ei[w]=ei;
            float tr = cdr[5]*er - cdi[5]*ei + s_wr[w];
            ei = cdr[5]*ei + cdi[5]*er + s_wi[w];
            er = tr;
        }
    }
    __syncthreads();
    float Er = s_er[warp], Ei = s_ei[warp];
    float plr=1.f, pli=0.f;
    #pragma unroll
    for (int bt=0; bt<5; bt++){
        if (lane & (1<<bt)){
            float tr = plr*cdr[bt] - pli*cdi[bt];
            pli = plr*cdi[bt] + pli*cdr[bt];
            plr = tr;
        }
    }
    float car = plr*Er - pli*Ei;
    float cai = plr*Ei + pli*Er;
    float pvr = __shfl_up_sync(FULL, xr, 1);
    float pvi = __shfl_up_sync(FULL, xi, 1);
    if (lane > 0){ car += pvr; cai += pvi; }
    sr = car; si = cai;
    #pragma unroll
    for (int i=0;i<16;i++){
        float tr = lr*sr - li*si + vr[i];
        float ti = lr*si + li*sr + vi[i];
        sr=tr; si=ti;
        vr[i]=sr; vi[i]=si;
    }
    {
        uint4 u0, u1;
        __half2* h0 = (__half2*)&u0;
        __half2* h1 = (__half2*)&u1;
        #pragma unroll
        for (int q=0;q<4;q++){
            h0[q] = __floats2half2_rn(vr[2*q], vr[2*q+1]);
            h1[q] = __floats2half2_rn(vr[8+2*q], vr[8+2*q+1]);
        }
        pr[0] = u0; pr[1] = u1;
        #pragma unroll
        for (int q=0;q<4;q++){
            h0[q] = __floats2half2_rn(vi[2*q], vi[2*q+1]);
            h1[q] = __floats2half2_rn(vi[8+2*q], vi[8+2*q+1]);
        }
        pi[0] = u0; pi[1] = u1;
    }
}

// ===================== C-mix GEMM (fp16) ============================================
#define SM_CMIX (13824*4)
__global__ void __launch_bounds__(256,3) k_cmix(const float* __restrict__ xin,
                        const float* __restrict__ Dsk,
                        const float* __restrict__ g1, const float* __restrict__ b1v, int l)
{
    extern __shared__ uint32_t smem[];
    uint32_t* saT = smem;             // [128 kp][72] half2 (k-pair major)
    uint32_t  sb = (uint32_t)__cvta_generic_to_shared(smem);
    int tid = threadIdx.x, lane = tid&31, warp = tid>>5;
    int gid = lane>>2, tig = lane&3;
    int row0 = blockIdx.x * 64;
    int b = row0 >> 12, t0 = row0 & (T-1);

    {   // prefetch Wc chunk 0 (2048 words)
        const uint32_t* ws = (const uint32_t*)(g_WcH + l*32768);
        #pragma unroll
        for (int j=0;j<2;j++){
            int f = tid + j*256, row = f>>3, g = (f&7)*4;
            cpa16(sb + (9216 + row*36 + g)*4, ws + row*32 + g);
        }
        cpcommit();
    }

    // stage xs (real|imag) as half2 k-pairs: vectorized uint2 loads + prmt + STS.128
    #pragma unroll
    for (int i=0;i<8;i++){
        int idx = tid + i*256;            // 2048 quads
        int kp = idx>>4, r4 = (idx&15)<<2;
        int k2 = 2*kp;
        const __half* sp = (k2<128) ? (g_burH + (b*NS+k2)*T + t0)
                                    : (g_buiH + (b*NS + (k2-128))*T + t0);
        uint2 u = *(const uint2*)&sp[r4];         // row k2, halves r4..r4+3
        uint2 v = *(const uint2*)&sp[T + r4];     // row k2+1
        uint4 w;
        w.x = __byte_perm(u.x, v.x, 0x5410);
        w.y = __byte_perm(u.x, v.x, 0x7632);
        w.z = __byte_perm(u.y, v.y, 0x5410);
        w.w = __byte_perm(u.y, v.y, 0x7632);
        *(uint4*)&saT[kp*72 + r4] = w;
    }

    int wm = (warp>>1)*16, wn = (warp&1)*64, wnb = (warp&1)*8;
    float acc[8][4];
    #pragma unroll
    for (int nt=0;nt<8;nt++){ acc[nt][0]=acc[nt][1]=acc[nt][2]=acc[nt][3]=0.f; }

    for (int kc=0; kc<8; kc++){
        cpwait0();
        __syncthreads();
        if (kc < 7){
            const uint32_t* ws = (const uint32_t*)(g_WcH + l*32768) + (kc+1)*2048;
            uint32_t dst = sb + (9216 + ((kc+1)&1)*2304)*4;
            #pragma unroll
            for (int j=0;j<2;j++){
                int f = tid + j*256, row = f>>3, g = (f&7)*4;
                cpa16(dst + (row*36 + g)*4, ws + row*32 + g);
            }
            cpcommit();
        }
        uint32_t* sw = smem + 9216 + (kc&1)*2304;
        #pragma unroll
        for (int ks=0; ks<2; ks++){
            int kp0 = kc*16 + ks*8;
            uint32_t a0 = saT[(kp0+tig)*72   + wm+gid];
            uint32_t a1 = saT[(kp0+tig)*72   + wm+gid+8];
            uint32_t a2 = saT[(kp0+tig+4)*72 + wm+gid];
            uint32_t a3 = saT[(kp0+tig+4)*72 + wm+gid+8];
            const uint32_t* bw = sw + (ks*32 + gid*4 + tig)*36 + wnb*2;
            #pragma unroll
            for (int nt0=0; nt0<8; nt0+=2){
                uint4 bv = *(const uint4*)(bw + nt0*2);
                mma16(acc[nt0],   a0,a1,a2,a3, bv.x, bv.y);
                mma16(acc[nt0+1], a0,a1,a2,a3, bv.z, bv.w);
            }
        }
    }
    __syncthreads();
    float* so = (float*)smem;   // [64][132]
    #pragma unroll
    for (int nt=0; nt<8; nt++){
        int n = wn + nt*8 + 2*tig;
        so[(wm+gid)*132 + n]     = acc[nt][0];
        so[(wm+gid)*132 + n+1]   = acc[nt][1];
        so[(wm+gid+8)*132 + n]   = acc[nt][2];
        so[(wm+gid+8)*132 + n+1] = acc[nt][3];
    }
    __syncthreads();
    const float* res = xin ? xin : g_x;
    for (int e=tid; e<8192; e+=256){
        int h = e&127, r = e>>7;
        int gi = (row0+r)*H + h;
        float xv = res[gi];
        float xn = (xv - g_mu[row0+r])*g_rs[row0+r]*g1[l*H+h] + b1v[l*H+h];
        g_x[gi] = xv + so[r*132+h] + xn*Dsk[l*H+h];
    }
}

// ===================== LN2 + MLP (fp16), M=64, 512 threads ==========================
#define SM_MLP (21504*4)
__global__ void __launch_bounds__(512,2) k_mlp(const float* __restrict__ g2,
                      const float* __restrict__ b2v,
                      const float* __restrict__ b1v, const float* __restrict__ b2o, int l)
{
    extern __shared__ uint32_t smem[];
    uint32_t* sa = smem;                     // [64][68] half2
    uint32_t* sh = smem + 4352;              // [64][132] half2 (128 kp + pad)
    uint32_t  sb = (uint32_t)__cvta_generic_to_shared(smem);
    uint32_t  wb = sb + 12800*4;
    int tid = threadIdx.x, lane = tid&31, warp = tid>>5;
    int gid = lane>>2, tig = lane&3;
    int row0 = blockIdx.x * 64;

    {   // prefetch W1 chunk 0 (4096 words)
        const uint32_t* ws = (const uint32_t*)(g_W1H + l*32768);
        #pragma unroll
        for (int j=0;j<2;j++){
            int f = tid + j*512, row = f>>4, g = (f&15)*4;
            cpa16(wb + (row*68 + g)*4, ws + row*64 + g);
        }
        cpcommit();
    }

    // LN2: 16 warps x 4 rows
    for (int rr=0; rr<4; rr++){
        int r = warp*4 + rr;
        int base = (row0+r)*H;
        float2 p0 = *(const float2*)&g_x[base + 2*lane];
        float2 p1 = *(const float2*)&g_x[base + 64 + 2*lane];
        float s  = p0.x+p0.y+p1.x+p1.y;
        float sq = p0.x*p0.x+p0.y*p0.y+p1.x*p1.x+p1.y*p1.y;
        #pragma unroll
        for (int o=16;o>0;o>>=1){ s += __shfl_xor_sync(FULL,s,o); sq += __shfl_xor_sync(FULL,sq,o); }
        float mu = s * (1.0f/128.0f);
        float var = sq * (1.0f/128.0f) - mu*mu;
        float rstd = rsqrtf(var + 1e-5f);
        float2 ga = *(const float2*)&g2[l*H + 2*lane];
        float2 ba = *(const float2*)&b2v[l*H + 2*lane];
        float2 gb = *(const float2*)&g2[l*H + 64 + 2*lane];
        float2 bb = *(const float2*)&b2v[l*H + 64 + 2*lane];
        sa[r*68 + lane]      = f2h2((p0.x-mu)*rstd*ga.x + ba.x, (p0.y-mu)*rstd*ga.y + ba.y);
        sa[r*68 + 32 + lane] = f2h2((p1.x-mu)*rstd*gb.x + bb.x, (p1.y-mu)*rstd*gb.y + bb.y);
    }

    // ---- GEMM1: [64x128] @ [128x256] ----
    int wm = (warp>>2)*16, wn = (warp&3)*64, wnb = (warp&3)*8;
    float acc[8][4];
    #pragma unroll
    for (int nt=0;nt<8;nt++){ acc[nt][0]=acc[nt][1]=acc[nt][2]=acc[nt][3]=0.f; }
    for (int kc=0; kc<4; kc++){
        cpwait0();
        __syncthreads();
        if (kc < 3){
            const uint32_t* ws = (const uint32_t*)(g_W1H + l*32768) + (kc+1)*4096;
            uint32_t dst = wb + (((kc+1)&1)*4352)*4;
            #pragma unroll
            for (int j=0;j<2;j++){
                int f = tid + j*512, row = f>>4, g = (f&15)*4;
                cpa16(dst + (row*68 + g)*4, ws + row*64 + g);
            }
            cpcommit();
        }
        uint32_t* sw = smem + 12800 + (kc&1)*4352;
        #pragma unroll
        for (int ks=0; ks<2; ks++){
            int kp0 = kc*16 + ks*8;
            uint32_t a0 = sa[(wm+gid)*68   + kp0 + tig];
            uint32_t a1 = sa[(wm+gid+8)*68 + kp0 + tig];
            uint32_t a2 = sa[(wm+gid)*68   + kp0 + tig+4];
            uint32_t a3 = sa[(wm+gid+8)*68 + kp0 + tig+4];
            const uint32_t* bw = sw + (ks*32 + gid*4 + tig)*68 + wnb*2;
            #pragma unroll
            for (int nt0=0; nt0<8; nt0+=2){
                uint4 bv = *(const uint4*)(bw + nt0*2);
                mma16(acc[nt0],   a0,a1,a2,a3, bv.x, bv.y);
                mma16(acc[nt0+1], a0,a1,a2,a3, bv.z, bv.w);
            }
        }
    }
    // prefetch W2 chunk 0 into buf0 (safe: buf0 dead since kc=3 sync)
    {
        const uint32_t* ws = (const uint32_t*)(g_W2H + l*32768);
        {
            int f = tid, row = f>>3, g = (f&7)*4;   // 2048 words, 512 ops
            cpa16(wb + (row*36 + g)*4, ws + row*32 + g);
        }
        cpcommit();
    }
    // bias + gelu -> sh (half2)
    #pragma unroll
    for (int nt=0; nt<8; nt++){
        int n = wn + nt*8 + 2*tig;
        float bb0 = b1v[l*256 + n], bb1 = b1v[l*256 + n + 1];
        float x0 = acc[nt][0]+bb0, x1 = acc[nt][1]+bb1;
        float x2 = acc[nt][2]+bb0, x3 = acc[nt][3]+bb1;
        int c = n>>1;
        sh[(wm+gid)*132 + c]   = f2h2(0.5f*x0*(1.0f+erff(x0*0.70710678118f)),
                                      0.5f*x1*(1.0f+erff(x1*0.70710678118f)));
        sh[(wm+gid+8)*132 + c] = f2h2(0.5f*x2*(1.0f+erff(x2*0.70710678118f)),
                                      0.5f*x3*(1.0f+erff(x3*0.70710678118f)));
    }

    // ---- GEMM2: [64x256] @ [256x128] ----
    int wn2 = (warp&3)*32, wnb2 = (warp&3)*4;
    float acc2[4][4];
    #pragma unroll
    for (int nt=0;nt<4;nt++){ acc2[nt][0]=acc2[nt][1]=acc2[nt][2]=acc2[nt][3]=0.f; }
    for (int kc=0; kc<8; kc++){
        cpwait0();
        __syncthreads();
        if (kc < 7){
            const uint32_t* ws = (const uint32_t*)(g_W2H + l*32768) + (kc+1)*2048;
            uint32_t dst = wb + (((kc+1)&1)*4352)*4;
            {
                int f = tid, row = f>>3, g = (f&7)*4;
                cpa16(dst + (row*36 + g)*4, ws + row*32 + g);
            }
            cpcommit();
        }
        uint32_t* sw = smem + 12800 + (kc&1)*4352;
        #pragma unroll
        for (int ks=0; ks<2; ks++){
            int kp0 = kc*16 + ks*8;
            uint32_t a0 = sh[(wm+gid)*132   + kp0 + tig];
            uint32_t a1 = sh[(wm+gid+8)*132 + kp0 + tig];
            uint32_t a2 = sh[(wm+gid)*132   + kp0 + tig+4];
            uint32_t a3 = sh[(wm+gid+8)*132 + kp0 + tig+4];
            const uint32_t* bw = sw + (ks*32 + gid*4 + tig)*36 + wnb2*2;
            #pragma unroll
            for (int nt0=0; nt0<4; nt0+=2){
                uint4 bv = *(const uint4*)(bw + nt0*2);
                mma16(acc2[nt0],   a0,a1,a2,a3, bv.x, bv.y);
                mma16(acc2[nt0+1], a0,a1,a2,a3, bv.z, bv.w);
            }
        }
    }
    __syncthreads();
    float* so = (float*)smem;    // [64][132] floats (overlays sa+sh, both dead)
    #pragma unroll
    for (int nt=0; nt<4; nt++){
        int n = wn2 + nt*8 + 2*tig;
        so[(wm+gid)*132 + n]     = acc2[nt][0];
        so[(wm+gid)*132 + n+1]   = acc2[nt][1];
        so[(wm+gid+8)*132 + n]   = acc2[nt][2];
        so[(wm+gid+8)*132 + n+1] = acc2[nt][3];
    }
    __syncthreads();
    for (int e=tid; e<8192; e+=512){
        int h = e&127, r = e>>7;
        int gi = (row0+r)*H + h;
        g_x[gi] = g_x[gi] + so[r*132+h] + b2o[l*H+h];
    }
}

// ===================== conv1 as fp16 GEMM (K=640), output half ======================
#define SM_CONV (13780*4)
__global__ void __launch_bounds__(256,3) k_conv1(const float* __restrict__ bc1)
{
    extern __shared__ uint32_t smem[];
    uint32_t* sx = smem;
    uint32_t  sb = (uint32_t)__cvta_generic_to_shared(smem);
    int tid = threadIdx.x, lane = tid&31, warp = tid>>5;
    int gid = lane>>2, tig = lane&3;
    int b = blockIdx.x >> 5;
    int ip0 = (blockIdx.x & 31) * 64;
    int t0 = 2*ip0 - 2;

    {
        const uint32_t* ws = (const uint32_t*)g_Wc1H;
        #pragma unroll
        for (int j=0;j<2;j++){
            int f = tid + j*256, row = f>>3, g = (f&7)*4;
            cpa16(sb + (9172 + row*36 + g)*4, ws + row*32 + g);
        }
        cpcommit();
    }
    for (int e=tid; e<131*32; e+=256){
        int t = e>>5, icq = e&31;             // icq: quad of channels
        int tg = t0 + t;
        uint2 w = make_uint2(0u, 0u);
        if (tg>=0 && tg<T){
            float4 p = *(const float4*)&g_x[(b*T+tg)*H + 4*icq];
            w.x = f2h2(p.x, p.y);
            w.y = f2h2(p.z, p.w);
        }
        *(uint2*)&sx[t*70 + 2*icq] = w;
    }

    int wm = (warp>>1)*16, wn = (warp&1)*64, wnb = (warp&1)*8;
    float acc[8][4];
    #pragma unroll
    for (int nt=0;nt<8;nt++){ acc[nt][0]=acc[nt][1]=acc[nt][2]=acc[nt][3]=0.f; }

    for (int c=0; c<20; c++){
        cpwait0();
        __syncthreads();
        if (c < 19){
            const uint32_t* ws = (const uint32_t*)g_Wc1H + (c+1)*2048;
            uint32_t dst = sb + (9172 + ((c+1)&1)*2304)*4;
            #pragma unroll
            for (int j=0;j<2;j++){
                int f = tid + j*256, row = f>>3, g = (f&7)*4;
                cpa16(dst + (row*36 + g)*4, ws + row*32 + g);
            }
            cpcommit();
        }
        uint32_t* sw = smem + 9172 + (c&1)*2304;
        int kv = c>>2, icpb = (c&3)*16;
        #pragma unroll
        for (int ks=0; ks<2; ks++){
            int icp0 = icpb + ks*8;
            uint32_t a0 = sx[(2*(wm+gid)+kv)*70   + icp0 + tig];
            uint32_t a1 = sx[(2*(wm+gid+8)+kv)*70 + icp0 + tig];
            uint32_t a2 = sx[(2*(wm+gid)+kv)*70   + icp0 + tig+4];
            uint32_t a3 = sx[(2*(wm+gid+8)+kv)*70 + icp0 + tig+4];
            const uint32_t* bw = sw + (ks*32 + gid*4 + tig)*36 + wnb*2;
            #pragma unroll
            for (int nt0=0; nt0<8; nt0+=2){
                uint4 bv = *(const uint4*)(bw + nt0*2);
                mma16(acc[nt0],   a0,a1,a2,a3, bv.x, bv.y);
                mma16(acc[nt0+1], a0,a1,a2,a3, bv.z, bv.w);
            }
        }
    }
    __syncthreads();
    float* so = (float*)smem;   // [64][132]
    #pragma unroll
    for (int nt=0; nt<8; nt++){
        int n = wn + nt*8 + 2*tig;
        so[(wm+gid)*132 + n]     = acc[nt][0];
        so[(wm+gid)*132 + n+1]   = acc[nt][1];
        so[(wm+gid+8)*132 + n]   = acc[nt][2];
        so[(wm+gid+8)*132 + n+1] = acc[nt][3];
    }
    __syncthreads();
    // vectorized half2 stores (co-pairs)
    for (int e=tid; e<4096; e+=256){
        int r = e>>6, cop = e&63;
        float v0 = fmaxf(so[r*132 + 2*cop]     + bc1[2*cop],     0.0f);
        float v1 = fmaxf(so[r*132 + 2*cop + 1] + bc1[2*cop + 1], 0.0f);
        *(uint32_t*)&g_y1H[(b*T2 + ip0 + r)*H + 2*cop] = f2h2(v0, v1);
    }
}

// ===================== conv2 + fused pool ===========================================
__global__ void __launch_bounds__(256,3) k_conv2pool(const float* __restrict__ bc2,
                                                     float* __restrict__ out)
{
    extern __shared__ uint32_t smem[];
    uint32_t* sx = smem;
    uint32_t  sb = (uint32_t)__cvta_generic_to_shared(smem);
    int tid = threadIdx.x, lane = tid&31, warp = tid>>5;
    int gid = lane>>2, tig = lane&3;
    int b = blockIdx.x >> 4;
    int tile = blockIdx.x & 15;
    int jp0 = tile * 64;
    int t0 = 2*jp0 - 2;

    {
        const uint32_t* ws = (const uint32_t*)g_Wc2H;
        #pragma unroll
        for (int j=0;j<2;j++){
            int f = tid + j*256, row = f>>3, g = (f&7)*4;
            cpa16(sb + (9172 + row*36 + g)*4, ws + row*32 + g);
        }
        cpcommit();
    }
    for (int e=tid; e<131*32; e+=256){
        int t = e>>5, icq = e&31;
        int tg = t0 + t;
        uint2 w = make_uint2(0u, 0u);
        if (tg>=0 && tg<T2) w = *(const uint2*)&g_y1H[(b*T2+tg)*H + 4*icq];
        *(uint2*)&sx[t*70 + 2*icq] = w;
    }

    int wm = (warp>>1)*16, wn = (warp&1)*64, wnb = (warp&1)*8;
    float acc[8][4];
    #pragma unroll
    for (int nt=0;nt<8;nt++){ acc[nt][0]=acc[nt][1]=acc[nt][2]=acc[nt][3]=0.f; }

    for (int c=0; c<20; c++){
        cpwait0();
        __syncthreads();
        if (c < 19){
            const uint32_t* ws = (const uint32_t*)g_Wc2H + (c+1)*2048;
            uint32_t dst = sb + (9172 + ((c+1)&1)*2304)*4;
            #pragma unroll
            for (int j=0;j<2;j++){
                int f = tid + j*256, row = f>>3, g = (f&7)*4;
                cpa16(dst + (row*36 + g)*4, ws + row*32 + g);
            }
            cpcommit();
        }
        uint32_t* sw = smem + 9172 + (c&1)*2304;
        int kv = c>>2, icpb = (c&3)*16;
        #pragma unroll
        for (int ks=0; ks<2; ks++){
            int icp0 = icpb + ks*8;
            uint32_t a0 = sx[(2*(wm+gid)+kv)*70   + icp0 + tig];
            uint32_t a1 = sx[(2*(wm+gid+8)+kv)*70 + icp0 + tig];
            uint32_t a2 = sx[(2*(wm+gid)+kv)*70   + icp0 + tig+4];
            uint32_t a3 = sx[(2*(wm+gid+8)+kv)*70 + icp0 + tig+4];
            const uint32_t* bw = sw + (ks*32 + gid*4 + tig)*36 + wnb*2;
            #pragma unroll
            for (int nt0=0; nt0<8; nt0+=2){
                uint4 bv = *(const uint4*)(bw + nt0*2);
                mma16(acc[nt0],   a0,a1,a2,a3, bv.x, bv.y);
                mma16(acc[nt0+1], a0,a1,a2,a3, bv.z, bv.w);
            }
        }
    }
    __syncthreads();
    float* so = (float*)smem;   // [64][132]
    #pragma unroll
    for (int nt=0; nt<8; nt++){
        int n = wn + nt*8 + 2*tig;
        so[(wm+gid)*132 + n]     = acc[nt][0];
        so[(wm+gid)*132 + n+1]   = acc[nt][1];
        so[(wm+gid+8)*132 + n]   = acc[nt][2];
        so[(wm+gid+8)*132 + n+1] = acc[nt][3];
    }
    __syncthreads();
    {
        int co = tid & 127, half = tid >> 7;
        float bias = bc2[co];
        float s0 = 0.f, s1 = 0.f;
        #pragma unroll
        for (int i=0;i<16;i++) s0 += fmaxf(so[(half*32+i)*132+co] + bias, 0.0f);
        #pragma unroll
        for (int i=16;i<32;i++) s1 += fmaxf(so[(half*32+i)*132+co] + bias, 0.0f);
        int d = tile*4 + half*2;
        out[(b*H+co)*DOUT + d]     = s0 * (1.0f/16.0f);
        out[(b*H+co)*DOUT + d + 1] = s1 * (1.0f/16.0f);
    }
}

// ---------------- launch ----------------
extern "C" void kernel_launch(void* const* d_in, const int* in_sizes, int n_in,
                              void* d_out, int out_size)
{
    (void)in_sizes; (void)n_in; (void)out_size;
    const float* x    = (const float*)d_in[0];
    const float* ln1g = (const float*)d_in[1];
    const float* ln1b = (const float*)d_in[2];
    const float* ln2g = (const float*)d_in[3];
    const float* ln2b = (const float*)d_in[4];
    const float* lre  = (const float*)d_in[5];
    const float* lim  = (const float*)d_in[6];
    const float* Bre  = (const float*)d_in[7];
    const float* Bim  = (const float*)d_in[8];
    const float* Cre  = (const float*)d_in[9];
    const float* Cim  = (const float*)d_in[10];
    const float* Dsk  = (const float*)d_in[11];
    const float* lstep= (const float*)d_in[12];
    const float* W1   = (const float*)d_in[13];
    const float* b1   = (const float*)d_in[14];
    const float* W2   = (const float*)d_in[15];
    const float* b2   = (const float*)d_in[16];
    const float* c1w  = (const float*)d_in[17];
    const float* c1b  = (const float*)d_in[18];
    const float* c2w  = (const float*)d_in[19];
    const float* c2b  = (const float*)d_in[20];
    float* out = (float*)d_out;

    cudaFuncSetAttribute(k_ln_bu,     cudaFuncAttributeMaxDynamicSharedMemorySize, SM_LNBU);
    cudaFuncSetAttribute(k_cmix,      cudaFuncAttributeMaxDynamicSharedMemorySize, SM_CMIX);
    cudaFuncSetAttribute(k_mlp,       cudaFuncAttributeMaxDynamicSharedMemorySize, SM_MLP);
    cudaFuncSetAttribute(k_conv1,     cudaFuncAttributeMaxDynamicSharedMemorySize, SM_CONV);
    cudaFuncSetAttribute(k_conv2pool, cudaFuncAttributeMaxDynamicSharedMemorySize, SM_CONV);

    k_prep<<<DEPTH*NS, H>>>(lre, lim, Bre, Bim, lstep);
    k_prepW<<<256, 256>>>(Cre, Cim, W1, W2);
    k_prepConv<<<320, 256>>>(c1w, c2w);
    for (int l=0;l<DEPTH;l++){
        const float* xin = (l==0) ? x : nullptr;
        k_ln_bu<<<TT/64, 512, SM_LNBU>>>(xin, ln1g, ln1b, l);
        k_scan<<<BATCH*NS, 256>>>(l);
        k_cmix<<<TT/64, 256, SM_CMIX>>>(xin, Dsk, ln1g, ln1b, l);
        k_mlp<<<TT/64, 512, SM_MLP>>>(ln2g, ln2b, b1, b2, l);
    }
    k_conv1<<<BATCH*32, 256, SM_CONV>>>(c1b);
    k_conv2pool<<<BATCH*16, 256, SM_CONV>>>(c2b, out);
}

// round 16
// speedup vs baseline: 7.2045x; 1.0598x over previous
#include <cuda_runtime.h>
#include <cuda_fp16.h>
#include <math.h>
#include <stdint.h>

#define BATCH 32
#define T 4096
#define H 128
#define NS 128
#define DEPTH 2
#define TT (BATCH*T)
#define T2 2048
#define DOUT 64
#define FULL 0xFFFFFFFFu

// ---------------- scratch ----------------
__device__ float g_x  [TT*H];
__device__ float g_mu [TT];
__device__ float g_rs [TT];
__device__ __half g_burH[BATCH*NS*T];
__device__ __half g_buiH[BATCH*NS*T];
__device__ __half g_y1H [BATCH*T2*H];
__device__ float g_lbr[DEPTH*NS], g_lbi[DEPTH*NS];
// packed (m16n8k16 fragment order) fp16 weights
__device__ __half g_WbuH[DEPTH*32768];  // K=128,N=256
__device__ __half g_WcH [DEPTH*32768];  // K=256,N=128
__device__ __half g_W1H [DEPTH*32768];  // K=128,N=256
__device__ __half g_W2H [DEPTH*32768];  // K=256,N=128
__device__ __half g_Wc1H[81920];        // K=640,N=128
__device__ __half g_Wc2H[81920];

// ---------------- helpers ----------------
__device__ __forceinline__ uint32_t f2h2(float lo, float hi){
    __half2 h = __floats2half2_rn(lo, hi);
    return *(uint32_t*)&h;
}
__device__ __forceinline__ void mma16(float* c, uint32_t a0,uint32_t a1,uint32_t a2,uint32_t a3,
                                      uint32_t b0,uint32_t b1){
    asm volatile("mma.sync.aligned.m16n8k16.row.col.f32.f16.f16.f32 "
        "{%0,%1,%2,%3},{%4,%5,%6,%7},{%8,%9},{%0,%1,%2,%3};"
        : "+f"(c[0]),"+f"(c[1]),"+f"(c[2]),"+f"(c[3])
        : "r"(a0),"r"(a1),"r"(a2),"r"(a3),"r"(b0),"r"(b1));
}
__device__ __forceinline__ void cpa16(uint32_t s, const void* g){
    asm volatile("cp.async.cg.shared.global [%0], [%1], 16;" :: "r"(s), "l"(g));
}
__device__ __forceinline__ void cpcommit(){ asm volatile("cp.async.commit_group;" ::: "memory"); }
__device__ __forceinline__ void cpwait0(){ asm volatile("cp.async.wait_group 0;" ::: "memory"); }

// fp16 fragment-order packed half index, k chunks of 16, NT = N/8
__device__ __forceinline__ int packIdxH(int k, int n, int NT){
    int k16 = k>>4, r = k&15;
    int tig = (r>>1)&3, hi = (r>>3)&1, lo = r&1;
    int row = k16*32 + (n&7)*4 + tig;
    return ((row*(2*NT) + (n>>3)*2 + hi)<<1) | lo;
}

// ---------------- param prep ----------------
__global__ void k_prep(const float* __restrict__ lre, const float* __restrict__ lim,
                       const float* __restrict__ Bre, const float* __restrict__ Bim,
                       const float* __restrict__ lstep)
{
    int idx = blockIdx.x;               // l*NS + n
    int l = idx >> 7, n = idx & 127;
    float lr = lre[idx], li = lim[idx];
    float dt = expf(lstep[idx]);
    float er = expf(lr*dt);
    float lbr = er * cosf(li*dt);
    float lbi = er * sinf(li*dt);
    if (threadIdx.x == 0){ g_lbr[idx]=lbr; g_lbi[idx]=lbi; }
    float den = lr*lr + li*li;
    float nr = lbr - 1.0f, ni = lbi;
    float fr = (nr*lr + ni*li)/den;
    float fi = (ni*lr - nr*li)/den;
    int h = threadIdx.x;
    float br = Bre[idx*H + h], bi = Bim[idx*H + h];
    float wr = fr*br - fi*bi;
    float wi = fr*bi + fi*br;
    g_WbuH[l*32768 + packIdxH(h, n,     32)] = __float2half(wr);
    g_WbuH[l*32768 + packIdxH(h, n+128, 32)] = __float2half(wi);
}

__global__ void k_prepW(const float* __restrict__ Cre, const float* __restrict__ Cim,
                        const float* __restrict__ W1, const float* __restrict__ W2)
{
    int i = blockIdx.x*256 + threadIdx.x;        // 65536
    int l = i>>15, rem = i&32767;
    {   // Wc: [k(256)][h(128)]
        int k = rem>>7, h = rem&127;
        float v = (k<128) ? 2.0f*Cre[(l*H+h)*NS + k]
                          : -2.0f*Cim[(l*H+h)*NS + (k-128)];
        g_WcH[l*32768 + packIdxH(k, h, 16)] = __float2half(v);
    }
    {   // W1: [k(128)][n(256)]
        int k = rem>>8, n = rem&255;
        g_W1H[l*32768 + packIdxH(k, n, 32)] = __float2half(W1[i]);
    }
    {   // W2: [k(256)][n(128)]
        int k = rem>>7, n = rem&127;
        g_W2H[l*32768 + packIdxH(k, n, 16)] = __float2half(W2[i]);
    }
}

__global__ void k_prepConv(const float* __restrict__ w1, const float* __restrict__ w2)
{
    int i = blockIdx.x*256 + threadIdx.x;        // 81920
    int co = i & 127, r = i >> 7;                // r = kv*128+ic
    int kv = r >> 7, ic = r & 127;
    int k = kv*128 + ic;
    int d = packIdxH(k, co, 16);
    g_Wc1H[d] = __float2half(w1[(co*H + ic)*5 + kv]);
    g_Wc2H[d] = __float2half(w2[(co*H + ic)*5 + kv]);
}

// ===================== LN1 + Bu GEMM (fp16), Bu -> [B][N][T] half ===================
#define SM_LNBU (16448*4)
__global__ void __launch_bounds__(512,2) k_ln_bu(const float* __restrict__ xin,
                        const float* __restrict__ g1, const float* __restrict__ b1v, int l)
{
    extern __shared__ uint32_t smem[];
    uint32_t* sa = smem;            // [64][68] half2
    uint32_t  sb = (uint32_t)__cvta_generic_to_shared(smem);
    const float* src = xin ? xin : g_x;
    int tid = threadIdx.x, lane = tid&31, warp = tid>>5;
    int gid = lane>>2, tig = lane&3;
    int row0 = blockIdx.x * 64;
    int b = row0 >> 12, t0 = row0 & (T-1);

    {   // prefetch chunk 0 (4096 words)
        const uint32_t* ws = (const uint32_t*)(g_WbuH + l*32768);
        #pragma unroll
        for (int j=0;j<2;j++){
            int f = tid + j*512, row = f>>4, g = (f&15)*4;
            cpa16(sb + (4352 + row*68 + g)*4, ws + row*64 + g);
        }
        cpcommit();
    }

    // ---- LayerNorm: 16 warps x 4 rows, write half2 pairs ----
    for (int rr = 0; rr < 4; rr++){
        int r = warp*4 + rr;
        int base = (row0 + r) * H;
        float2 p0 = *(const float2*)&src[base + 2*lane];
        float2 p1 = *(const float2*)&src[base + 64 + 2*lane];
        float s  = p0.x+p0.y+p1.x+p1.y;
        float sq = p0.x*p0.x+p0.y*p0.y+p1.x*p1.x+p1.y*p1.y;
        #pragma unroll
        for (int o=16;o>0;o>>=1){ s += __shfl_xor_sync(FULL,s,o); sq += __shfl_xor_sync(FULL,sq,o); }
        float mu = s * (1.0f/128.0f);
        float var = sq * (1.0f/128.0f) - mu*mu;
        float rstd = rsqrtf(var + 1e-5f);
        if (lane == 0){ g_mu[row0+r] = mu; g_rs[row0+r] = rstd; }
        float2 ga = *(const float2*)&g1[l*H + 2*lane];
        float2 ba = *(const float2*)&b1v[l*H + 2*lane];
        float2 gb = *(const float2*)&g1[l*H + 64 + 2*lane];
        float2 bb = *(const float2*)&b1v[l*H + 64 + 2*lane];
        sa[r*68 + lane]      = f2h2((p0.x-mu)*rstd*ga.x + ba.x, (p0.y-mu)*rstd*ga.y + ba.y);
        sa[r*68 + 32 + lane] = f2h2((p1.x-mu)*rstd*gb.x + bb.x, (p1.y-mu)*rstd*gb.y + bb.y);
    }

    int wm = (warp>>2)*16, wn = (warp&3)*64, wnb = (warp&3)*8;
    float acc[8][4];
    #pragma unroll
    for (int nt=0;nt<8;nt++){ acc[nt][0]=acc[nt][1]=acc[nt][2]=acc[nt][3]=0.f; }

    for (int kc=0; kc<4; kc++){
        cpwait0();
        __syncthreads();
        if (kc < 3){
            const uint32_t* ws = (const uint32_t*)(g_WbuH + l*32768) + (kc+1)*4096;
            uint32_t dst = sb + (4352 + ((kc+1)&1)*4352)*4;
            #pragma unroll
            for (int j=0;j<2;j++){
                int f = tid + j*512, row = f>>4, g = (f&15)*4;
                cpa16(dst + (row*68 + g)*4, ws + row*64 + g);
            }
            cpcommit();
        }
        uint32_t* sw = smem + 4352 + (kc&1)*4352;
        #pragma unroll
        for (int ks=0; ks<2; ks++){
            int kp0 = kc*16 + ks*8;
            uint32_t a0 = sa[(wm+gid)*68   + kp0 + tig];
            uint32_t a1 = sa[(wm+gid+8)*68 + kp0 + tig];
            uint32_t a2 = sa[(wm+gid)*68   + kp0 + tig+4];
            uint32_t a3 = sa[(wm+gid+8)*68 + kp0 + tig+4];
            const uint32_t* bw = sw + (ks*32 + gid*4 + tig)*68 + wnb*2;
            #pragma unroll
            for (int nt0=0; nt0<8; nt0+=2){
                uint4 bv = *(const uint4*)(bw + nt0*2);
                mma16(acc[nt0],   a0,a1,a2,a3, bv.x, bv.y);
                mma16(acc[nt0+1], a0,a1,a2,a3, bv.z, bv.w);
            }
        }
    }
    __syncthreads();
    float* so = (float*)smem;    // [64][257]
    #pragma unroll
    for (int nt=0; nt<8; nt++){
        int n = wn + nt*8 + 2*tig;
        so[(wm+gid)*257 + n]     = acc[nt][0];
        so[(wm+gid)*257 + n+1]   = acc[nt][1];
        so[(wm+gid+8)*257 + n]   = acc[nt][2];
        so[(wm+gid+8)*257 + n+1] = acc[nt][3];
    }
    __syncthreads();
    for (int i=0; i<16; i++){
        int n = warp*16 + i;
        int np = n & 127;
        __half* dst = ((n<128) ? g_burH : g_buiH) + (b*NS + np)*T + t0;
        float v0 = so[(2*lane)*257 + n];
        float v1 = so[(2*lane+1)*257 + n];
        *(uint32_t*)&dst[2*lane] = f2h2(v0, v1);
    }
}

// ---------------- in-place scan over T (half I/O, fp32 compute) ----------------
__global__ void k_scan(int l)
{
    __shared__ float s_wr[8], s_wi[8], s_er[8], s_ei[8];
    int bid = blockIdx.x;
    int n = bid & (NS-1);
    int tid = threadIdx.x, lane = tid & 31, warp = tid >> 5;
    int base = bid * T + tid * 16;
    float lr = g_lbr[l*NS+n], li = g_lbi[l*NS+n];

    float vr[16], vi[16];
    uint4* pr = (uint4*)(g_burH + base);
    uint4* pi = (uint4*)(g_buiH + base);
    {
        uint4 u0 = pr[0], u1 = pr[1];
        const __half2* h0 = (const __half2*)&u0;
        const __half2* h1 = (const __half2*)&u1;
        #pragma unroll
        for (int q=0;q<4;q++){
            float2 f0 = __half22float2(h0[q]); vr[2*q]=f0.x; vr[2*q+1]=f0.y;
            float2 f1 = __half22float2(h1[q]); vr[8+2*q]=f1.x; vr[8+2*q+1]=f1.y;
        }
        uint4 w0 = pi[0], w1 = pi[1];
        const __half2* g0 = (const __half2*)&w0;
        const __half2* g1_ = (const __half2*)&w1;
        #pragma unroll
        for (int q=0;q<4;q++){
            float2 f0 = __half22float2(g0[q]); vi[2*q]=f0.x; vi[2*q+1]=f0.y;
            float2 f1 = __half22float2(g1_[q]); vi[8+2*q]=f1.x; vi[8+2*q+1]=f1.y;
        }
    }
    float sr=0.f, si=0.f;
    #pragma unroll
    for (int i=0;i<16;i++){
        float tr = lr*sr - li*si + vr[i];
        float ti = lr*si + li*sr + vi[i];
        sr=tr; si=ti;
    }
    float cdr[6], cdi[6];
    {
        float pr_=lr, pi_=li;
        #pragma unroll
        for (int q=0;q<4;q++){ float tr = pr_*pr_ - pi_*pi_; pi_ = 2.f*pr_*pi_; pr_ = tr; }
        cdr[0]=pr_; cdi[0]=pi_;
        #pragma unroll
        for (int q=1;q<6;q++){ float tr = cdr[q-1]*cdr[q-1]-cdi[q-1]*cdi[q-1];
                               cdi[q]=2.f*cdr[q-1]*cdi[q-1]; cdr[q]=tr; }
    }
    float xr=sr, xi=si;
    #pragma unroll
    for (int st=0; st<5; st++){
        int d = 1<<st;
        float or_ = __shfl_up_sync(FULL, xr, d);
        float oi_ = __shfl_up_sync(FULL, xi, d);
        if (lane >= d){
            float tr = cdr[st]*or_ - cdi[st]*oi_ + xr;
            xi = cdr[st]*oi_ + cdi[st]*or_ + xi;
            xr = tr;
        }
    }
    if (lane==31){ s_wr[warp]=xr; s_wi[warp]=xi; }
    __syncthreads();
    if (tid==0){
        float er=0.f, ei=0.f;
        #pragma unroll
        for (int w=0;w<8;w++){
            s_er[w]=er; s_ei[w]=ei;
            float tr = cdr[5]*er - cdi[5]*ei + s_wr[w];
            ei = cdr[5]*ei + cdi[5]*er + s_wi[w];
            er = tr;
        }
    }
    __syncthreads();
    float Er = s_er[warp], Ei = s_ei[warp];
    float plr=1.f, pli=0.f;
    #pragma unroll
    for (int bt=0; bt<5; bt++){
        if (lane & (1<<bt)){
            float tr = plr*cdr[bt] - pli*cdi[bt];
            pli = plr*cdi[bt] + pli*cdr[bt];
            plr = tr;
        }
    }
    float car = plr*Er - pli*Ei;
    float cai = plr*Ei + pli*Er;
    float pvr = __shfl_up_sync(FULL, xr, 1);
    float pvi = __shfl_up_sync(FULL, xi, 1);
    if (lane > 0){ car += pvr; cai += pvi; }
    sr = car; si = cai;
    #pragma unroll
    for (int i=0;i<16;i++){
        float tr = lr*sr - li*si + vr[i];
        float ti = lr*si + li*sr + vi[i];
        sr=tr; si=ti;
        vr[i]=sr; vi[i]=si;
    }
    {
        uint4 u0, u1;
        __half2* h0 = (__half2*)&u0;
        __half2* h1 = (__half2*)&u1;
        #pragma unroll
        for (int q=0;q<4;q++){
            h0[q] = __floats2half2_rn(vr[2*q], vr[2*q+1]);
            h1[q] = __floats2half2_rn(vr[8+2*q], vr[8+2*q+1]);
        }
        pr[0] = u0; pr[1] = u1;
        #pragma unroll
        for (int q=0;q<4;q++){
            h0[q] = __floats2half2_rn(vi[2*q], vi[2*q+1]);
            h1[q] = __floats2half2_rn(vi[8+2*q], vi[8+2*q+1]);
        }
        pi[0] = u0; pi[1] = u1;
    }
}

// ===================== FUSED: C-mix + LN2 + MLP, 64 rows, 512 threads ===============
// smem (words): sxv[0,8448) fp32 [64][132]
//               act[8448,21248): phase A saT[128][72]=9216 ; phase B sa 4352 + sh 8448
//               wbuf[21248,25856): dbuf (Wc/W2: 2x2304, W1: 2x2176)
#define SM_CMLP (25856*4)
__global__ void __launch_bounds__(512,2) k_cmlp(const float* __restrict__ xin,
                      const float* __restrict__ Dsk,
                      const float* __restrict__ g1, const float* __restrict__ b1c,
                      const float* __restrict__ g2, const float* __restrict__ b2v,
                      const float* __restrict__ b1m, const float* __restrict__ b2o, int l)
{
    extern __shared__ uint32_t smem[];
    float*    sxv = (float*)smem;            // [64][132] fp32
    uint32_t* saT = smem + 8448;             // phase A: [128 kp][72]
    uint32_t* sa  = smem + 8448;             // phase B: [64][68] half2
    uint32_t* sh  = smem + 8448 + 4352;      // phase B: [64][132] half2
    uint32_t  sb  = (uint32_t)__cvta_generic_to_shared(smem);
    uint32_t  wb  = sb + 21248*4;
    int tid = threadIdx.x, lane = tid&31, warp = tid>>5;
    int gid = lane>>2, tig = lane&3;
    int row0 = blockIdx.x * 64;
    int b = row0 >> 12, t0 = row0 & (T-1);

    // ---------------- phase A: C-mix ----------------
    {   // prefetch Wc chunk 0 (2048 words)
        const uint32_t* ws = (const uint32_t*)(g_WcH + l*32768);
        int row = tid>>3, g = (tid&7)*4;
        cpa16(wb + (row*36 + g)*4, ws + row*32 + g);
        cpcommit();
    }

    // stage xs (real|imag) as half2 k-pairs: uint2 loads + prmt + STS.128
    #pragma unroll
    for (int i=0;i<4;i++){
        int idx = tid + i*512;            // 2048 quads
        int kp = idx>>4, r4 = (idx&15)<<2;
        int k2 = 2*kp;
        const __half* sp = (k2<128) ? (g_burH + (b*NS+k2)*T + t0)
                                    : (g_buiH + (b*NS + (k2-128))*T + t0);
        uint2 u = *(const uint2*)&sp[r4];
        uint2 v = *(const uint2*)&sp[T + r4];
        uint4 w;
        w.x = __byte_perm(u.x, v.x, 0x5410);
        w.y = __byte_perm(u.x, v.x, 0x7632);
        w.z = __byte_perm(u.y, v.y, 0x5410);
        w.w = __byte_perm(u.y, v.y, 0x7632);
        *(uint4*)&saT[kp*72 + r4] = w;
    }

    int wm = (warp>>2)*16;
    {
        int wn = (warp&3)*32, wnb = (warp&3)*4;
        float acc[4][4];
        #pragma unroll
        for (int nt=0;nt<4;nt++){ acc[nt][0]=acc[nt][1]=acc[nt][2]=acc[nt][3]=0.f; }

        for (int kc=0; kc<8; kc++){
            cpwait0();
            __syncthreads();
            if (kc < 7){
                const uint32_t* ws = (const uint32_t*)(g_WcH + l*32768) + (kc+1)*2048;
                uint32_t dst = wb + (((kc+1)&1)*2304)*4;
                int row = tid>>3, g = (tid&7)*4;
                cpa16(dst + (row*36 + g)*4, ws + row*32 + g);
                cpcommit();
            }
            uint32_t* sw = smem + 21248 + (kc&1)*2304;
            #pragma unroll
            for (int ks=0; ks<2; ks++){
                int kp0 = kc*16 + ks*8;
                uint32_t a0 = saT[(kp0+tig)*72   + wm+gid];
                uint32_t a1 = saT[(kp0+tig)*72   + wm+gid+8];
                uint32_t a2 = saT[(kp0+tig+4)*72 + wm+gid];
                uint32_t a3 = saT[(kp0+tig+4)*72 + wm+gid+8];
                const uint32_t* bw = sw + (ks*32 + gid*4 + tig)*36 + wnb*2;
                #pragma unroll
                for (int nt0=0; nt0<4; nt0+=2){
                    uint4 bv = *(const uint4*)(bw + nt0*2);
                    mma16(acc[nt0],   a0,a1,a2,a3, bv.x, bv.y);
                    mma16(acc[nt0+1], a0,a1,a2,a3, bv.z, bv.w);
                }
            }
        }
        // prefetch W1 chunk0 into wbuf buf0 (buf0 dead since kc=7's barrier)
        {
            const uint32_t* ws = (const uint32_t*)(g_W1H + l*32768);
            int row = tid>>4, g = (tid&15)*4;       // 2048 words
            cpa16(wb + (row*68 + g)*4, ws + row*64 + g);
            cpcommit();
        }
        __syncthreads();
        // stage cmix acc into sxv
        #pragma unroll
        for (int nt=0; nt<4; nt++){
            int n = wn + nt*8 + 2*tig;
            sxv[(wm+gid)*132 + n]     = acc[nt][0];
            sxv[(wm+gid)*132 + n+1]   = acc[nt][1];
            sxv[(wm+gid+8)*132 + n]   = acc[nt][2];
            sxv[(wm+gid+8)*132 + n+1] = acc[nt][3];
        }
    }
    __syncthreads();
    // per-element: sxv = res + cmix + xn*Dsk   (g_x never written here)
    const float* res = xin ? xin : g_x;
    #pragma unroll
    for (int i=0;i<16;i++){
        int e = tid + i*512;
        int h = e&127, r = e>>7;
        float xv = res[(row0+r)*H + h];
        float xn = (xv - g_mu[row0+r])*g_rs[row0+r]*g1[l*H+h] + b1c[l*H+h];
        sxv[r*132+h] = xv + sxv[r*132+h] + xn*Dsk[l*H+h];
    }
    __syncthreads();

    // ---------------- phase B: LN2 + MLP ----------------
    for (int rr=0; rr<4; rr++){
        int r = warp*4 + rr;
        float2 p0 = *(const float2*)&sxv[r*132 + 2*lane];
        float2 p1 = *(const float2*)&sxv[r*132 + 64 + 2*lane];
        float s  = p0.x+p0.y+p1.x+p1.y;
        float sq = p0.x*p0.x+p0.y*p0.y+p1.x*p1.x+p1.y*p1.y;
        #pragma unroll
        for (int o=16;o>0;o>>=1){ s += __shfl_xor_sync(FULL,s,o); sq += __shfl_xor_sync(FULL,sq,o); }
        float mu = s * (1.0f/128.0f);
        float var = sq * (1.0f/128.0f) - mu*mu;
        float rstd = rsqrtf(var + 1e-5f);
        float2 ga = *(const float2*)&g2[l*H + 2*lane];
        float2 ba = *(const float2*)&b2v[l*H + 2*lane];
        float2 gb = *(const float2*)&g2[l*H + 64 + 2*lane];
        float2 bb = *(const float2*)&b2v[l*H + 64 + 2*lane];
        sa[r*68 + lane]      = f2h2((p0.x-mu)*rstd*ga.x + ba.x, (p0.y-mu)*rstd*ga.y + ba.y);
        sa[r*68 + 32 + lane] = f2h2((p1.x-mu)*rstd*gb.x + bb.x, (p1.y-mu)*rstd*gb.y + bb.y);
    }

    // ---- GEMM1: [64x128] @ [128x256], 8 chunks of k16 ----
    int wn = (warp&3)*64, wnb = (warp&3)*8;
    float acc[8][4];
    #pragma unroll
    for (int nt=0;nt<8;nt++){ acc[nt][0]=acc[nt][1]=acc[nt][2]=acc[nt][3]=0.f; }
    for (int kc=0; kc<8; kc++){
        cpwait0();
        __syncthreads();
        if (kc < 7){
            const uint32_t* ws = (const uint32_t*)(g_W1H + l*32768) + (kc+1)*2048;
            uint32_t dst = wb + (((kc+1)&1)*2176)*4;
            int row = tid>>4, g = (tid&15)*4;
            cpa16(dst + (row*68 + g)*4, ws + row*64 + g);
            cpcommit();
        }
        uint32_t* sw = smem + 21248 + (kc&1)*2176;
        int kp0 = kc*8;
        uint32_t a0 = sa[(wm+gid)*68   + kp0 + tig];
        uint32_t a1 = sa[(wm+gid+8)*68 + kp0 + tig];
        uint32_t a2 = sa[(wm+gid)*68   + kp0 + tig+4];
        uint32_t a3 = sa[(wm+gid+8)*68 + kp0 + tig+4];
        const uint32_t* bw = sw + (gid*4 + tig)*68 + wnb*2;
        #pragma unroll
        for (int nt0=0; nt0<8; nt0+=2){
            uint4 bv = *(const uint4*)(bw + nt0*2);
            mma16(acc[nt0],   a0,a1,a2,a3, bv.x, bv.y);
            mma16(acc[nt0+1], a0,a1,a2,a3, bv.z, bv.w);
        }
    }
    // prefetch W2 chunk 0 into buf0 (buf0 dead since kc=7's barrier)
    {
        const uint32_t* ws = (const uint32_t*)(g_W2H + l*32768);
        int row = tid>>3, g = (tid&7)*4;
        cpa16(wb + (row*36 + g)*4, ws + row*32 + g);
        cpcommit();
    }
    // bias + gelu -> sh (half2)
    #pragma unroll
    for (int nt=0; nt<8; nt++){
        int n = wn + nt*8 + 2*tig;
        float bb0 = b1m[l*256 + n], bb1 = b1m[l*256 + n + 1];
        float x0 = acc[nt][0]+bb0, x1 = acc[nt][1]+bb1;
        float x2 = acc[nt][2]+bb0, x3 = acc[nt][3]+bb1;
        int c = n>>1;
        sh[(wm+gid)*132 + c]   = f2h2(0.5f*x0*(1.0f+erff(x0*0.70710678118f)),
                                      0.5f*x1*(1.0f+erff(x1*0.70710678118f)));
        sh[(wm+gid+8)*132 + c] = f2h2(0.5f*x2*(1.0f+erff(x2*0.70710678118f)),
                                      0.5f*x3*(1.0f+erff(x3*0.70710678118f)));
    }

    // ---- GEMM2: [64x256] @ [256x128], 8 chunks of k32 ----
    int wn2 = (warp&3)*32, wnb2 = (warp&3)*4;
    float acc2[4][4];
    #pragma unroll
    for (int nt=0;nt<4;nt++){ acc2[nt][0]=acc2[nt][1]=acc2[nt][2]=acc2[nt][3]=0.f; }
    for (int kc=0; kc<8; kc++){
        cpwait0();
        __syncthreads();
        if (kc < 7){
            const uint32_t* ws = (const uint32_t*)(g_W2H + l*32768) + (kc+1)*2048;
            uint32_t dst = wb + (((kc+1)&1)*2304)*4;
            int row = tid>>3, g = (tid&7)*4;
            cpa16(dst + (row*36 + g)*4, ws + row*32 + g);
            cpcommit();
        }
        uint32_t* sw = smem + 21248 + (kc&1)*2304;
        #pragma unroll
        for (int ks=0; ks<2; ks++){
            int kp0 = kc*16 + ks*8;
            uint32_t a0 = sh[(wm+gid)*132   + kp0 + tig];
            uint32_t a1 = sh[(wm+gid+8)*132 + kp0 + tig];
            uint32_t a2 = sh[(wm+gid)*132   + kp0 + tig+4];
            uint32_t a3 = sh[(wm+gid+8)*132 + kp0 + tig+4];
            const uint32_t* bw = sw + (ks*32 + gid*4 + tig)*36 + wnb2*2;
            #pragma unroll
            for (int nt0=0; nt0<4; nt0+=2){
                uint4 bv = *(const uint4*)(bw + nt0*2);
                mma16(acc2[nt0],   a0,a1,a2,a3, bv.x, bv.y);
                mma16(acc2[nt0+1], a0,a1,a2,a3, bv.z, bv.w);
            }
        }
    }
    __syncthreads();
    float* so2 = (float*)(smem + 8448);   // [64][132] fp32, overlays sa+sh (dead)
    #pragma unroll
    for (int nt=0; nt<4; nt++){
        int n = wn2 + nt*8 + 2*tig;
        so2[(wm+gid)*132 + n]     = acc2[nt][0];
        so2[(wm+gid)*132 + n+1]   = acc2[nt][1];
        so2[(wm+gid+8)*132 + n]   = acc2[nt][2];
        so2[(wm+gid+8)*132 + n+1] = acc2[nt][3];
    }
    __syncthreads();
    #pragma unroll
    for (int i=0;i<16;i++){
        int e = tid + i*512;
        int h = e&127, r = e>>7;
        g_x[(row0+r)*H + h] = sxv[r*132+h] + so2[r*132+h] + b2o[l*H+h];
    }
}

// ===================== conv1 as fp16 GEMM (K=640), output half ======================
#define SM_CONV (13780*4)
__global__ void __launch_bounds__(256,3) k_conv1(const float* __restrict__ bc1)
{
    extern __shared__ uint32_t smem[];
    uint32_t* sx = smem;
    uint32_t  sb = (uint32_t)__cvta_generic_to_shared(smem);
    int tid = threadIdx.x, lane = tid&31, warp = tid>>5;
    int gid = lane>>2, tig = lane&3;
    int b = blockIdx.x >> 5;
    int ip0 = (blockIdx.x & 31) * 64;
    int t0 = 2*ip0 - 2;

    {
        const uint32_t* ws = (const uint32_t*)g_Wc1H;
        #pragma unroll
        for (int j=0;j<2;j++){
            int f = tid + j*256, row = f>>3, g = (f&7)*4;
            cpa16(sb + (9172 + row*36 + g)*4, ws + row*32 + g);
        }
        cpcommit();
    }
    for (int e=tid; e<131*32; e+=256){
        int t = e>>5, icq = e&31;
        int tg = t0 + t;
        uint2 w = make_uint2(0u, 0u);
        if (tg>=0 && tg<T){
            float4 p = *(const float4*)&g_x[(b*T+tg)*H + 4*icq];
            w.x = f2h2(p.x, p.y);
            w.y = f2h2(p.z, p.w);
        }
        *(uint2*)&sx[t*70 + 2*icq] = w;
    }

    int wm = (warp>>1)*16, wn = (warp&1)*64, wnb = (warp&1)*8;
    float acc[8][4];
    #pragma unroll
    for (int nt=0;nt<8;nt++){ acc[nt][0]=acc[nt][1]=acc[nt][2]=acc[nt][3]=0.f; }

    for (int c=0; c<20; c++){
        cpwait0();
        __syncthreads();
        if (c < 19){
            const uint32_t* ws = (const uint32_t*)g_Wc1H + (c+1)*2048;
            uint32_t dst = sb + (9172 + ((c+1)&1)*2304)*4;
            #pragma unroll
            for (int j=0;j<2;j++){
                int f = tid + j*256, row = f>>3, g = (f&7)*4;
                cpa16(dst + (row*36 + g)*4, ws + row*32 + g);
            }
            cpcommit();
        }
        uint32_t* sw = smem + 9172 + (c&1)*2304;
        int kv = c>>2, icpb = (c&3)*16;
        #pragma unroll
        for (int ks=0; ks<2; ks++){
            int icp0 = icpb + ks*8;
            uint32_t a0 = sx[(2*(wm+gid)+kv)*70   + icp0 + tig];
            uint32_t a1 = sx[(2*(wm+gid+8)+kv)*70 + icp0 + tig];
            uint32_t a2 = sx[(2*(wm+gid)+kv)*70   + icp0 + tig+4];
            uint32_t a3 = sx[(2*(wm+gid+8)+kv)*70 + icp0 + tig+4];
            const uint32_t* bw = sw + (ks*32 + gid*4 + tig)*36 + wnb*2;
            #pragma unroll
            for (int nt0=0; nt0<8; nt0+=2){
                uint4 bv = *(const uint4*)(bw + nt0*2);
                mma16(acc[nt0],   a0,a1,a2,a3, bv.x, bv.y);
                mma16(acc[nt0+1], a0,a1,a2,a3, bv.z, bv.w);
            }
        }
    }
    __syncthreads();
    float* so = (float*)smem;   // [64][132]
    #pragma unroll
    for (int nt=0; nt<8; nt++){
        int n = wn + nt*8 + 2*tig;
        so[(wm+gid)*132 + n]     = acc[nt][0];
        so[(wm+gid)*132 + n+1]   = acc[nt][1];
        so[(wm+gid+8)*132 + n]   = acc[nt][2];
        so[(wm+gid+8)*132 + n+1] = acc[nt][3];
    }
    __syncthreads();
    for (int e=tid; e<4096; e+=256){
        int r = e>>6, cop = e&63;
        float v0 = fmaxf(so[r*132 + 2*cop]     + bc1[2*cop],     0.0f);
        float v1 = fmaxf(so[r*132 + 2*cop + 1] + bc1[2*cop + 1], 0.0f);
        *(uint32_t*)&g_y1H[(b*T2 + ip0 + r)*H + 2*cop] = f2h2(v0, v1);
    }
}

// ===================== conv2 + fused pool ===========================================
__global__ void __launch_bounds__(256,3) k_conv2pool(const float* __restrict__ bc2,
                                                     float* __restrict__ out)
{
    extern __shared__ uint32_t smem[];
    uint32_t* sx = smem;
    uint32_t  sb = (uint32_t)__cvta_generic_to_shared(smem);
    int tid = threadIdx.x, lane = tid&31, warp = tid>>5;
    int gid = lane>>2, tig = lane&3;
    int b = blockIdx.x >> 4;
    int tile = blockIdx.x & 15;
    int jp0 = tile * 64;
    int t0 = 2*jp0 - 2;

    {
        const uint32_t* ws = (const uint32_t*)g_Wc2H;
        #pragma unroll
        for (int j=0;j<2;j++){
            int f = tid + j*256, row = f>>3, g = (f&7)*4;
            cpa16(sb + (9172 + row*36 + g)*4, ws + row*32 + g);
        }
        cpcommit();
    }
    for (int e=tid; e<131*32; e+=256){
        int t = e>>5, icq = e&31;
        int tg = t0 + t;
        uint2 w = make_uint2(0u, 0u);
        if (tg>=0 && tg<T2) w = *(const uint2*)&g_y1H[(b*T2+tg)*H + 4*icq];
        *(uint2*)&sx[t*70 + 2*icq] = w;
    }

    int wm = (warp>>1)*16, wn = (warp&1)*64, wnb = (warp&1)*8;
    float acc[8][4];
    #pragma unroll
    for (int nt=0;nt<8;nt++){ acc[nt][0]=acc[nt][1]=acc[nt][2]=acc[nt][3]=0.f; }

    for (int c=0; c<20; c++){
        cpwait0();
        __syncthreads();
        if (c < 19){
            const uint32_t* ws = (const uint32_t*)g_Wc2H + (c+1)*2048;
            uint32_t dst = sb + (9172 + ((c+1)&1)*2304)*4;
            #pragma unroll
            for (int j=0;j<2;j++){
                int f = tid + j*256, row = f>>3, g = (f&7)*4;
                cpa16(dst + (row*36 + g)*4, ws + row*32 + g);
            }
            cpcommit();
        }
        uint32_t* sw = smem + 9172 + (c&1)*2304;
        int kv = c>>2, icpb = (c&3)*16;
        #pragma unroll
        for (int ks=0; ks<2; ks++){
            int icp0 = icpb + ks*8;
            uint32_t a0 = sx[(2*(wm+gid)+kv)*70   + icp0 + tig];
            uint32_t a1 = sx[(2*(wm+gid+8)+kv)*70 + icp0 + tig];
            uint32_t a2 = sx[(2*(wm+gid)+kv)*70   + icp0 + tig+4];
            uint32_t a3 = sx[(2*(wm+gid+8)+kv)*70 + icp0 + tig+4];
            const uint32_t* bw = sw + (ks*32 + gid*4 + tig)*36 + wnb*2;
            #pragma unroll
            for (int nt0=0; nt0<8; nt0+=2){
                uint4 bv = *(const uint4*)(bw + nt0*2);
                mma16(acc[nt0],   a0,a1,a2,a3, bv.x, bv.y);
                mma16(acc[nt0+1], a0,a1,a2,a3, bv.z, bv.w);
            }
        }
    }
    __syncthreads();
    float* so = (float*)smem;   // [64][132]
    #pragma unroll
    for (int nt=0; nt<8; nt++){
        int n = wn + nt*8 + 2*tig;
        so[(wm+gid)*132 + n]     = acc[nt][0];
        so[(wm+gid)*132 + n+1]   = acc[nt][1];
        so[(wm+gid+8)*132 + n]   = acc[nt][2];
        so[(wm+gid+8)*132 + n+1] = acc[nt][3];
    }
    __syncthreads();
    {
        int co = tid & 127, half = tid >> 7;
        float bias = bc2[co];
        float s0 = 0.f, s1 = 0.f;
        #pragma unroll
        for (int i=0;i<16;i++) s0 += fmaxf(so[(half*32+i)*132+co] + bias, 0.0f);
        #pragma unroll
        for (int i=16;i<32;i++) s1 += fmaxf(so[(half*32+i)*132+co] + bias, 0.0f);
        int d = tile*4 + half*2;
        out[(b*H+co)*DOUT + d]     = s0 * (1.0f/16.0f);
        out[(b*H+co)*DOUT + d + 1] = s1 * (1.0f/16.0f);
    }
}

// ---------------- launch ----------------
extern "C" void kernel_launch(void* const* d_in, const int* in_sizes, int n_in,
                              void* d_out, int out_size)
{
    (void)in_sizes; (void)n_in; (void)out_size;
    const float* x    = (const float*)d_in[0];
    const float* ln1g = (const float*)d_in[1];
    const float* ln1b = (const float*)d_in[2];
    const float* ln2g = (const float*)d_in[3];
    const float* ln2b = (const float*)d_in[4];
    const float* lre  = (const float*)d_in[5];
    const float* lim  = (const float*)d_in[6];
    const float* Bre  = (const float*)d_in[7];
    const float* Bim  = (const float*)d_in[8];
    const float* Cre  = (const float*)d_in[9];
    const float* Cim  = (const float*)d_in[10];
    const float* Dsk  = (const float*)d_in[11];
    const float* lstep= (const float*)d_in[12];
    const float* W1   = (const float*)d_in[13];
    const float* b1   = (const float*)d_in[14];
    const float* W2   = (const float*)d_in[15];
    const float* b2   = (const float*)d_in[16];
    const float* c1w  = (const float*)d_in[17];
    const float* c1b  = (const float*)d_in[18];
    const float* c2w  = (const float*)d_in[19];
    const float* c2b  = (const float*)d_in[20];
    float* out = (float*)d_out;

    cudaFuncSetAttribute(k_ln_bu,     cudaFuncAttributeMaxDynamicSharedMemorySize, SM_LNBU);
    cudaFuncSetAttribute(k_cmlp,      cudaFuncAttributeMaxDynamicSharedMemorySize, SM_CMLP);
    cudaFuncSetAttribute(k_conv1,     cudaFuncAttributeMaxDynamicSharedMemorySize, SM_CONV);
    cudaFuncSetAttribute(k_conv2pool, cudaFuncAttributeMaxDynamicSharedMemorySize, SM_CONV);

    k_prep<<<DEPTH*NS, H>>>(lre, lim, Bre, Bim, lstep);
    k_prepW<<<256, 256>>>(Cre, Cim, W1, W2);
    k_prepConv<<<320, 256>>>(c1w, c2w);
    for (int l=0;l<DEPTH;l++){
        const float* xin = (l==0) ? x : nullptr;
        k_ln_bu<<<TT/64, 512, SM_LNBU>>>(xin, ln1g, ln1b, l);
        k_scan<<<BATCH*NS, 256>>>(l);
        k_cmlp<<<TT/64, 512, SM_CMLP>>>(xin, Dsk, ln1g, ln1b,
                                        ln2g, ln2b, b1, b2, l);
    }
    k_conv1<<<BATCH*32, 256, SM_CONV>>>(c1b);
    k_conv2pool<<<BATCH*16, 256, SM_CONV>>>(c2b, out);
}